// round 4
// baseline (speedup 1.0000x reference)
#include <cuda_runtime.h>
#include <cuda_fp16.h>
#include <stdint.h>
#include <math.h>

#define B_ 2
#define S_ 2048
#define E_ 1024
#define H_ 16
#define D_ 64
#define M_ (B_*S_)    // 4096
#define BH_ (B_*H_)   // 32

// ---------------- scratch (device globals; no allocation allowed) -------------
__device__ __half g_xh[(size_t)M_*E_];
__device__ __half g_xl[(size_t)M_*E_];
__device__ __half g_wh[(size_t)4*E_*E_];
__device__ __half g_wl[(size_t)4*E_*E_];
__device__ __half g_qh[(size_t)BH_*S_*D_];
__device__ __half g_ql[(size_t)BH_*S_*D_];
__device__ __half g_kh[(size_t)BH_*S_*D_];
__device__ __half g_kl[(size_t)BH_*S_*D_];
__device__ __half g_vth[(size_t)BH_*D_*S_];   // transposed [bh][d][s]
__device__ __half g_vtl[(size_t)BH_*D_*S_];
__device__ __half g_ohh[(size_t)M_*E_];
__device__ __half g_ohl[(size_t)M_*E_];

// ---------------- helpers ----------------------------------------------------
__device__ __forceinline__ uint32_t smem_u32(const void* p) {
    uint32_t a;
    asm("{ .reg .u64 t; cvta.to.shared.u64 t, %1; cvt.u32.u64 %0, t; }" : "=r"(a) : "l"(p));
    return a;
}
__device__ __forceinline__ void cp16(uint32_t s, const void* g) {
    asm volatile("cp.async.cg.shared.global [%0], [%1], 16;" :: "r"(s), "l"(g));
}
#define CP_COMMIT() asm volatile("cp.async.commit_group;" ::: "memory")
#define CP_WAIT2()  asm volatile("cp.async.wait_group 2;" ::: "memory")

__device__ __forceinline__ void ldsm4(uint32_t addr, uint32_t r[4]) {
    asm volatile("ldmatrix.sync.aligned.m8n8.x4.shared.b16 {%0,%1,%2,%3}, [%4];"
        : "=r"(r[0]), "=r"(r[1]), "=r"(r[2]), "=r"(r[3]) : "r"(addr));
}
__device__ __forceinline__ void mma_fp16(float* c, const uint32_t* a, uint32_t b0, uint32_t b1) {
    asm volatile(
        "mma.sync.aligned.m16n8k16.row.col.f32.f16.f16.f32 "
        "{%0,%1,%2,%3}, {%4,%5,%6,%7}, {%8,%9}, {%0,%1,%2,%3};"
        : "+f"(c[0]), "+f"(c[1]), "+f"(c[2]), "+f"(c[3])
        : "r"(a[0]), "r"(a[1]), "r"(a[2]), "r"(a[3]), "r"(b0), "r"(b1));
}
__device__ __forceinline__ uint32_t pack2(float x, float y) {
    __half2 h = __floats2half2_rn(x, y);
    return *(uint32_t*)&h;
}
__device__ __forceinline__ void split16(float v, __half& h, __half& l) {
    h = __float2half_rn(v);
    l = __float2half_rn(v - __half2float(h));
}

// ---------------- fp32 -> fp16 hi/lo conversion ------------------------------
__global__ __launch_bounds__(256) void convert_kernel(
    const float* __restrict__ x,  const float* __restrict__ Wq,
    const float* __restrict__ Wk, const float* __restrict__ Wv,
    const float* __restrict__ Wc)
{
    const int seg = blockIdx.y;
    const float* src; __half* hi; __half* lo; int n4;
    if (seg == 0) { src = x;  hi = g_xh; lo = g_xl; n4 = M_*E_/4; }
    else {
        src = (seg==1)?Wq:(seg==2)?Wk:(seg==3)?Wv:Wc;
        hi = g_wh + (size_t)(seg-1)*E_*E_;
        lo = g_wl + (size_t)(seg-1)*E_*E_;
        n4 = E_*E_/4;
    }
    int i = blockIdx.x * 256 + threadIdx.x;
    if (i >= n4) return;
    float4 v = ((const float4*)src)[i];
    __half h0,h1,h2,h3,l0,l1,l2,l3;
    split16(v.x,h0,l0); split16(v.y,h1,l1); split16(v.z,h2,l2); split16(v.w,h3,l3);
    ((__half2*)hi)[2*i]   = __halves2half2(h0, h1);
    ((__half2*)hi)[2*i+1] = __halves2half2(h2, h3);
    ((__half2*)lo)[2*i]   = __halves2half2(l0, l1);
    ((__half2*)lo)[2*i+1] = __halves2half2(l2, l3);
}

// ---------------- HMMA split-fp16 GEMM ---------------------------------------
// C[m,n] = sum_k A[m,k]*B[n,k]; 128x128 tile, 8 warps, k-chunk 32, 3 stages.
// MMA issue is product-major (hh pass, hl pass, lh pass) so consecutive mma ops
// never share an accumulator (reuse distance 8) -> C->C latency hidden.
#define GROWB 80
#define GT_BYTES (128*GROWB)      // 10240
#define GSTAGE  (4*GT_BYTES)      // 40960: Ah, Al, Bh, Bl
#define GNST 3
#define GSMEM   (GNST*GSTAGE)     // 122880

template<int MODE>
__global__ __launch_bounds__(256) void gemm_kernel(float* __restrict__ out,
                                                   const float* __restrict__ bc)
{
    extern __shared__ char sm[];
    const uint32_t s0 = smem_u32(sm);
    const int tid = threadIdx.x;
    const int lane = tid & 31, warp = tid >> 5;
    const int wm = warp >> 2, wn = warp & 3;
    const int m0 = blockIdx.y * 128, n0 = blockIdx.x * 128;

    const __half *Ah, *Al, *Bh2, *Bl2;
    if (MODE == 0) {
        Ah = g_xh; Al = g_xl;
        Bh2 = g_wh + (size_t)blockIdx.z * E_ * E_;
        Bl2 = g_wl + (size_t)blockIdx.z * E_ * E_;
    } else {
        Ah = g_ohh; Al = g_ohl;
        Bh2 = g_wh + (size_t)3 * E_ * E_;
        Bl2 = g_wl + (size_t)3 * E_ * E_;
    }

    float acc[4][4][4];
#pragma unroll
    for (int a = 0; a < 4; a++)
#pragma unroll
        for (int b = 0; b < 4; b++)
#pragma unroll
            for (int c = 0; c < 4; c++) acc[a][b][c] = 0.f;

    auto load = [&](int c) {
        const uint32_t base = s0 + (c % GNST) * GSTAGE;
        const int k0 = c * 32;
#pragma unroll
        for (int i = 0; i < 8; i++) {
            int g = i * 256 + tid;           // 0..2047
            int t = g >> 9;                  // 0..3 : Ah,Al,Bh,Bl
            int r = (g >> 2) & 127;
            int ch = g & 3;
            const __half* src = (t == 0) ? Ah : (t == 1) ? Al : (t == 2) ? Bh2 : Bl2;
            int row = ((t < 2) ? m0 : n0) + r;
            cp16(base + t * GT_BYTES + r * GROWB + ch * 16,
                 src + (size_t)row * E_ + k0 + ch * 8);
        }
    };

    load(0); CP_COMMIT();
    load(1); CP_COMMIT();
    load(2); CP_COMMIT();

    const int rowoff = (lane & 7) + ((lane >> 3) & 1) * 8;
    for (int c = 0; c < 32; c++) {
        CP_WAIT2();
        __syncthreads();
        const uint32_t base = s0 + (c % GNST) * GSTAGE;
#pragma unroll
        for (int ks = 0; ks < 2; ks++) {
            const int chunk = ks * 2 + (lane >> 4);
            uint32_t ah[4][4], al[4][4];
#pragma unroll
            for (int mi = 0; mi < 4; mi++) {
                uint32_t ra = base + (wm*64 + mi*16 + rowoff) * GROWB + chunk * 16;
                ldsm4(ra, ah[mi]);
                ldsm4(ra + GT_BYTES, al[mi]);
            }
#pragma unroll
            for (int p = 0; p < 2; p++) {
                uint32_t bh[4], bl[4];
                uint32_t rb = base + 2*GT_BYTES + (wn*32 + p*16 + rowoff) * GROWB + chunk * 16;
                ldsm4(rb, bh);
                ldsm4(rb + GT_BYTES, bl);
                // hh pass
#pragma unroll
                for (int mi = 0; mi < 4; mi++) mma_fp16(acc[mi][2*p],   ah[mi], bh[0], bh[2]);
#pragma unroll
                for (int mi = 0; mi < 4; mi++) mma_fp16(acc[mi][2*p+1], ah[mi], bh[1], bh[3]);
                // hl pass
#pragma unroll
                for (int mi = 0; mi < 4; mi++) mma_fp16(acc[mi][2*p],   ah[mi], bl[0], bl[2]);
#pragma unroll
                for (int mi = 0; mi < 4; mi++) mma_fp16(acc[mi][2*p+1], ah[mi], bl[1], bl[3]);
                // lh pass
#pragma unroll
                for (int mi = 0; mi < 4; mi++) mma_fp16(acc[mi][2*p],   al[mi], bh[0], bh[2]);
#pragma unroll
                for (int mi = 0; mi < 4; mi++) mma_fp16(acc[mi][2*p+1], al[mi], bh[1], bh[3]);
            }
        }
        __syncthreads();
        if (c + GNST < 32) load(c + GNST);
        CP_COMMIT();
    }

    const int g = lane >> 2, tg2 = (lane & 3) * 2;
    if (MODE == 1) {
#pragma unroll
        for (int mi = 0; mi < 4; mi++) {
            int m = m0 + wm*64 + mi*16 + g;
#pragma unroll
            for (int ni = 0; ni < 4; ni++) {
                int n = n0 + wn*32 + ni*8 + tg2;
                float b0 = bc[n], b1 = bc[n+1];
                *(float2*)(out + (size_t)m * E_ + n) =
                    make_float2(acc[mi][ni][0] + b0, acc[mi][ni][1] + b1);
                *(float2*)(out + (size_t)(m+8) * E_ + n) =
                    make_float2(acc[mi][ni][2] + b0, acc[mi][ni][3] + b1);
            }
        }
        return;
    }

    // ---- MODE 0: transpose via smem, then per-row cumprod(cos) ----
    float* st = (float*)sm;   // [128][132] fp32
#pragma unroll
    for (int mi = 0; mi < 4; mi++) {
        int r = wm*64 + mi*16 + g;
#pragma unroll
        for (int ni = 0; ni < 4; ni++) {
            int n = wn*32 + ni*8 + tg2;
            st[(size_t)r * 132 + n]     = acc[mi][ni][0];
            st[(size_t)r * 132 + n + 1] = acc[mi][ni][1];
            st[(size_t)(r+8) * 132 + n]     = acc[mi][ni][2];
            st[(size_t)(r+8) * 132 + n + 1] = acc[mi][ni][3];
        }
    }
    __syncthreads();

    {
        const int head = tid >> 7;          // 0..1 (two heads per 128-col tile)
        const int r = tid & 127;
        const int m = m0 + r;
        const int b = m >> 11, sI = m & (S_ - 1);
        const int hglob = blockIdx.x * 2 + head;
        const int bh = b * H_ + hglob;
        const int z = blockIdx.z;
        const float* src = st + (size_t)r * 132 + head * 64;

        float run = 1.f;
        float val[64];
#pragma unroll
        for (int d = 0; d < 64; d++) { run *= __cosf(src[d]); val[d] = run; }

        if (z < 2) {
            const float sc = (z == 0) ? 0.125f : 1.0f;
            __half hb[64], lb[64];
#pragma unroll
            for (int d = 0; d < 64; d++) split16(val[d] * sc, hb[d], lb[d]);
            __half* dh = (z == 0 ? g_qh : g_kh) + ((size_t)bh * S_ + sI) * 64;
            __half* dl = (z == 0 ? g_ql : g_kl) + ((size_t)bh * S_ + sI) * 64;
#pragma unroll
            for (int j = 0; j < 8; j++) {
                ((uint4*)dh)[j] = ((uint4*)hb)[j];
                ((uint4*)dl)[j] = ((uint4*)lb)[j];
            }
        } else {
#pragma unroll
            for (int d = 0; d < 64; d++) {
                __half h, l; split16(val[d], h, l);
                g_vth[((size_t)bh * 64 + d) * S_ + sI] = h;
                g_vtl[((size_t)bh * 64 + d) * S_ + sI] = l;
            }
        }
    }
}

// ---------------- HMMA flash attention ---------------------------------------
// grid (S/128, BH), 256 threads. Q tile 128 rows, KV tiles 64, 3 stages.
// MMA issue interleaved over panel pairs -> same-acc reuse distance 4.
#define FROWB 144
#define FQT  (128*FROWB)     // 18432
#define FKT  (64*FROWB)      // 9216
#define FSTAGE (4*FKT)       // 36864 : Kh, Kl, Vh, Vl
#define FNST 3
#define FSMEM (2*FQT + FNST*FSTAGE)   // 147456

__global__ __launch_bounds__(256) void flash_kernel()
{
    extern __shared__ char sm[];
    const uint32_t s0 = smem_u32(sm);
    const uint32_t sQ = s0, sKV = s0 + 2 * FQT;
    const int tid = threadIdx.x, lane = tid & 31, warp = tid >> 5;
    const int bh = blockIdx.y;
    const int q0 = blockIdx.x * 128;

    const __half* Qh = g_qh + (size_t)bh * S_ * 64;
    const __half* Ql = g_ql + (size_t)bh * S_ * 64;
    const __half* Kh = g_kh + (size_t)bh * S_ * 64;
    const __half* Kl = g_kl + (size_t)bh * S_ * 64;
    const __half* Vh = g_vth + (size_t)bh * 64 * S_;
    const __half* Vl = g_vtl + (size_t)bh * 64 * S_;

    auto loadKV = [&](int t) {
        const uint32_t base = sKV + (t % FNST) * FSTAGE;
        const int kv0 = t * 64;
#pragma unroll
        for (int i = 0; i < 8; i++) {
            int gi = i * 256 + tid;         // 0..2047
            int tl = gi >> 9;               // 0..3 : Kh,Kl,Vh,Vl
            int r = (gi >> 3) & 63;
            int ch = gi & 7;
            const __half* src;
            if (tl == 0)      src = Kh + (size_t)(kv0 + r) * 64 + ch * 8;
            else if (tl == 1) src = Kl + (size_t)(kv0 + r) * 64 + ch * 8;
            else if (tl == 2) src = Vh + (size_t)r * S_ + kv0 + ch * 8;
            else              src = Vl + (size_t)r * S_ + kv0 + ch * 8;
            cp16(base + tl * FKT + r * FROWB + ch * 16, src);
        }
    };

    {
#pragma unroll
        for (int i = 0; i < 8; i++) {
            int gi = i * 256 + tid;
            int tl = gi >> 10;              // 0,1 : Qh, Ql
            int r = (gi >> 3) & 127;
            int ch = gi & 7;
            const __half* src = (tl ? Ql : Qh) + (size_t)(q0 + r) * 64 + ch * 8;
            cp16(sQ + tl * FQT + r * FROWB + ch * 16, src);
        }
        loadKV(0); CP_COMMIT();
        loadKV(1); CP_COMMIT();
        loadKV(2); CP_COMMIT();
    }

    float o[8][4];
#pragma unroll
    for (int i = 0; i < 8; i++)
#pragma unroll
        for (int j = 0; j < 4; j++) o[i][j] = 0.f;
    float m0r = -1e30f, m1r = -1e30f, l0r = 0.f, l1r = 0.f;

    uint32_t qhf[4][4], qlf[4][4];
    const int rowoff = (lane & 7) + ((lane >> 3) & 1) * 8;

    for (int t = 0; t < 32; t++) {
        CP_WAIT2();
        __syncthreads();
        if (t == 0) {
#pragma unroll
            for (int ks = 0; ks < 4; ks++) {
                uint32_t ra = sQ + (warp*16 + rowoff) * FROWB + (ks*2 + (lane>>4)) * 16;
                ldsm4(ra, qhf[ks]);
                ldsm4(ra + FQT, qlf[ks]);
            }
        }
        const uint32_t kb = sKV + (t % FNST) * FSTAGE;

        float s[8][4];
#pragma unroll
        for (int i = 0; i < 8; i++)
#pragma unroll
            for (int j = 0; j < 4; j++) s[i][j] = 0.f;

        // S = Q K^T, interleaved over panel pairs (acc reuse distance 4)
#pragma unroll
        for (int ks = 0; ks < 4; ks++) {
            const int chunk = ks * 2 + (lane >> 4);
#pragma unroll
            for (int pp = 0; pp < 2; pp++) {
                uint32_t kh[2][4], kl[2][4];
#pragma unroll
                for (int q = 0; q < 2; q++) {
                    uint32_t rb = kb + ((pp*2+q)*16 + rowoff) * FROWB + chunk * 16;
                    ldsm4(rb, kh[q]);
                    ldsm4(rb + FKT, kl[q]);
                }
#pragma unroll
                for (int q = 0; q < 2; q++) mma_fp16(s[2*(pp*2+q)],   qhf[ks], kh[q][0], kh[q][2]);
#pragma unroll
                for (int q = 0; q < 2; q++) mma_fp16(s[2*(pp*2+q)+1], qhf[ks], kh[q][1], kh[q][3]);
#pragma unroll
                for (int q = 0; q < 2; q++) mma_fp16(s[2*(pp*2+q)],   qhf[ks], kl[q][0], kl[q][2]);
#pragma unroll
                for (int q = 0; q < 2; q++) mma_fp16(s[2*(pp*2+q)+1], qhf[ks], kl[q][1], kl[q][3]);
#pragma unroll
                for (int q = 0; q < 2; q++) mma_fp16(s[2*(pp*2+q)],   qlf[ks], kh[q][0], kh[q][2]);
#pragma unroll
                for (int q = 0; q < 2; q++) mma_fp16(s[2*(pp*2+q)+1], qlf[ks], kh[q][1], kh[q][3]);
            }
        }

        // online softmax (rows: g = lane>>2 and g+8; quad-shuffles xor 1,2)
        float rm0 = -1e30f, rm1 = -1e30f;
#pragma unroll
        for (int ni = 0; ni < 8; ni++) {
            rm0 = fmaxf(rm0, fmaxf(s[ni][0], s[ni][1]));
            rm1 = fmaxf(rm1, fmaxf(s[ni][2], s[ni][3]));
        }
        rm0 = fmaxf(rm0, __shfl_xor_sync(0xffffffffu, rm0, 1));
        rm0 = fmaxf(rm0, __shfl_xor_sync(0xffffffffu, rm0, 2));
        rm1 = fmaxf(rm1, __shfl_xor_sync(0xffffffffu, rm1, 1));
        rm1 = fmaxf(rm1, __shfl_xor_sync(0xffffffffu, rm1, 2));
        float mn0 = fmaxf(m0r, rm0), mn1 = fmaxf(m1r, rm1);
        float sc0 = __expf(m0r - mn0), sc1 = __expf(m1r - mn1);

        uint32_t pf[8][2];
        float rs0 = 0.f, rs1 = 0.f;
#pragma unroll
        for (int ni = 0; ni < 8; ni++) {
            float p0 = __expf(s[ni][0] - mn0);
            float p1 = __expf(s[ni][1] - mn0);
            float p2 = __expf(s[ni][2] - mn1);
            float p3 = __expf(s[ni][3] - mn1);
            rs0 += p0 + p1; rs1 += p2 + p3;
            pf[ni][0] = pack2(p0, p1);
            pf[ni][1] = pack2(p2, p3);
        }
        rs0 += __shfl_xor_sync(0xffffffffu, rs0, 1);
        rs0 += __shfl_xor_sync(0xffffffffu, rs0, 2);
        rs1 += __shfl_xor_sync(0xffffffffu, rs1, 1);
        rs1 += __shfl_xor_sync(0xffffffffu, rs1, 2);
        l0r = l0r * sc0 + rs0;  m0r = mn0;
        l1r = l1r * sc1 + rs1;  m1r = mn1;
#pragma unroll
        for (int ni = 0; ni < 8; ni++) {
            o[ni][0] *= sc0; o[ni][1] *= sc0;
            o[ni][2] *= sc1; o[ni][3] *= sc1;
        }

        // O += P V, interleaved over panel pairs (acc reuse distance 4)
        const uint32_t vb = kb + 2 * FKT;
#pragma unroll
        for (int ks = 0; ks < 4; ks++) {
            uint32_t a[4] = { pf[2*ks][0], pf[2*ks][1], pf[2*ks+1][0], pf[2*ks+1][1] };
            const int chunk = ks * 2 + (lane >> 4);
#pragma unroll
            for (int pp = 0; pp < 2; pp++) {
                uint32_t vh[2][4], vl[2][4];
#pragma unroll
                for (int q = 0; q < 2; q++) {
                    uint32_t rb = vb + ((pp*2+q)*16 + rowoff) * FROWB + chunk * 16;
                    ldsm4(rb, vh[q]);
                    ldsm4(rb + FKT, vl[q]);
                }
#pragma unroll
                for (int q = 0; q < 2; q++) mma_fp16(o[2*(pp*2+q)],   a, vh[q][0], vh[q][2]);
#pragma unroll
                for (int q = 0; q < 2; q++) mma_fp16(o[2*(pp*2+q)+1], a, vh[q][1], vh[q][3]);
#pragma unroll
                for (int q = 0; q < 2; q++) mma_fp16(o[2*(pp*2+q)],   a, vl[q][0], vl[q][2]);
#pragma unroll
                for (int q = 0; q < 2; q++) mma_fp16(o[2*(pp*2+q)+1], a, vl[q][1], vl[q][3]);
            }
        }

        __syncthreads();
        if (t + FNST < 32) loadKV(t + FNST);
        CP_COMMIT();
    }

    // epilogue: normalize, split hi/lo fp16, write [B,S,H,D] (= [M,E])
    const float inv0 = 1.f / l0r, inv1 = 1.f / l1r;
    const int g = lane >> 2, tg2 = (lane & 3) * 2;
    const int b = bh >> 4, h = bh & 15;
    const int sA = q0 + warp * 16 + g;
#pragma unroll
    for (int ni = 0; ni < 8; ni++) {
        int d = ni * 8 + tg2;
        size_t i0 = (((size_t)(b * S_ + sA)     * H_ + h) * D_ + d);
        size_t i1 = (((size_t)(b * S_ + sA + 8) * H_ + h) * D_ + d);
        __half h0,h1,h2,h3,l0,l1,l2,l3;
        split16(o[ni][0] * inv0, h0, l0);
        split16(o[ni][1] * inv0, h1, l1);
        split16(o[ni][2] * inv1, h2, l2);
        split16(o[ni][3] * inv1, h3, l3);
        *(__half2*)(g_ohh + i0) = __halves2half2(h0, h1);
        *(__half2*)(g_ohl + i0) = __halves2half2(l0, l1);
        *(__half2*)(g_ohh + i1) = __halves2half2(h2, h3);
        *(__half2*)(g_ohl + i1) = __halves2half2(l2, l3);
    }
}

// ---------------------------------------------------------------------------
extern "C" void kernel_launch(void* const* d_in, const int* in_sizes, int n_in,
                              void* d_out, int out_size)
{
    const float* x  = (const float*)d_in[0];
    const float* Wq = (const float*)d_in[1];
    const float* Wk = (const float*)d_in[2];
    const float* Wv = (const float*)d_in[3];
    const float* Wc = (const float*)d_in[4];
    const float* bc = (const float*)d_in[5];
    float* out = (float*)d_out;

    cudaFuncSetAttribute(gemm_kernel<0>, cudaFuncAttributeMaxDynamicSharedMemorySize, GSMEM);
    cudaFuncSetAttribute(gemm_kernel<1>, cudaFuncAttributeMaxDynamicSharedMemorySize, GSMEM);
    cudaFuncSetAttribute(flash_kernel,   cudaFuncAttributeMaxDynamicSharedMemorySize, FSMEM);

    // 1) fp32 -> fp16 hi/lo for x and all weights
    convert_kernel<<<dim3(4096, 5), 256>>>(x, Wq, Wk, Wv, Wc);

    // 2) QKV projections (HMMA split) + fused quantum cumprod(cos) epilogue
    gemm_kernel<0><<<dim3(E_/128, M_/128, 3), 256, GSMEM>>>(nullptr, nullptr);

    // 3) flash attention (HMMA split QK, fp16 P, split V)
    flash_kernel<<<dim3(S_/128, BH_), 256, FSMEM>>>();

    // 4) output projection (HMMA split) + bias
    gemm_kernel<1><<<dim3(E_/128, M_/128, 1), 256, GSMEM>>>(out, bc);
}

// round 5
// speedup vs baseline: 1.1194x; 1.1194x over previous
#include <cuda_runtime.h>
#include <cuda_fp16.h>
#include <stdint.h>
#include <math.h>

#define B_ 2
#define S_ 2048
#define E_ 1024
#define H_ 16
#define D_ 64
#define M_ (B_*S_)    // 4096
#define BH_ (B_*H_)   // 32

// ---------------- scratch (device globals; no allocation allowed) -------------
__device__ __half g_xh[(size_t)M_*E_];
__device__ __half g_xl[(size_t)M_*E_];
__device__ __half g_wh[(size_t)4*E_*E_];
__device__ __half g_wl[(size_t)4*E_*E_];
__device__ __half g_qh[(size_t)BH_*S_*D_];
__device__ __half g_ql[(size_t)BH_*S_*D_];
__device__ __half g_kh[(size_t)BH_*S_*D_];
__device__ __half g_kl[(size_t)BH_*S_*D_];
__device__ __half g_vth[(size_t)BH_*D_*S_];   // transposed [bh][d][s]
__device__ __half g_vtl[(size_t)BH_*D_*S_];
__device__ __half g_ohh[(size_t)M_*E_];
__device__ __half g_ohl[(size_t)M_*E_];

// ---------------- helpers ----------------------------------------------------
__device__ __forceinline__ uint32_t smem_u32(const void* p) {
    uint32_t a;
    asm("{ .reg .u64 t; cvta.to.shared.u64 t, %1; cvt.u32.u64 %0, t; }" : "=r"(a) : "l"(p));
    return a;
}
__device__ __forceinline__ void cp16(uint32_t s, const void* g) {
    asm volatile("cp.async.cg.shared.global [%0], [%1], 16;" :: "r"(s), "l"(g));
}
#define CP_COMMIT() asm volatile("cp.async.commit_group;" ::: "memory")
#define CP_WAIT1()  asm volatile("cp.async.wait_group 1;" ::: "memory")

__device__ __forceinline__ void ldsm4(uint32_t addr, uint32_t r[4]) {
    asm volatile("ldmatrix.sync.aligned.m8n8.x4.shared.b16 {%0,%1,%2,%3}, [%4];"
        : "=r"(r[0]), "=r"(r[1]), "=r"(r[2]), "=r"(r[3]) : "r"(addr));
}
__device__ __forceinline__ void mma_fp16(float* c, const uint32_t* a, uint32_t b0, uint32_t b1) {
    asm volatile(
        "mma.sync.aligned.m16n8k16.row.col.f32.f16.f16.f32 "
        "{%0,%1,%2,%3}, {%4,%5,%6,%7}, {%8,%9}, {%0,%1,%2,%3};"
        : "+f"(c[0]), "+f"(c[1]), "+f"(c[2]), "+f"(c[3])
        : "r"(a[0]), "r"(a[1]), "r"(a[2]), "r"(a[3]), "r"(b0), "r"(b1));
}
__device__ __forceinline__ uint32_t pack2(float x, float y) {
    __half2 h = __floats2half2_rn(x, y);
    return *(uint32_t*)&h;
}
__device__ __forceinline__ void split16(float v, __half& h, __half& l) {
    h = __float2half_rn(v);
    l = __float2half_rn(v - __half2float(h));
}

// ---------------- fp32 -> fp16 hi/lo conversion ------------------------------
__global__ __launch_bounds__(256) void convert_kernel(
    const float* __restrict__ x,  const float* __restrict__ Wq,
    const float* __restrict__ Wk, const float* __restrict__ Wv,
    const float* __restrict__ Wc)
{
    const int seg = blockIdx.y;
    const float* src; __half* hi; __half* lo; int n4;
    if (seg == 0) { src = x;  hi = g_xh; lo = g_xl; n4 = M_*E_/4; }
    else {
        src = (seg==1)?Wq:(seg==2)?Wk:(seg==3)?Wv:Wc;
        hi = g_wh + (size_t)(seg-1)*E_*E_;
        lo = g_wl + (size_t)(seg-1)*E_*E_;
        n4 = E_*E_/4;
    }
    int i = blockIdx.x * 256 + threadIdx.x;
    if (i >= n4) return;
    float4 v = ((const float4*)src)[i];
    __half h0,h1,h2,h3,l0,l1,l2,l3;
    split16(v.x,h0,l0); split16(v.y,h1,l1); split16(v.z,h2,l2); split16(v.w,h3,l3);
    ((__half2*)hi)[2*i]   = __halves2half2(h0, h1);
    ((__half2*)hi)[2*i+1] = __halves2half2(h2, h3);
    ((__half2*)lo)[2*i]   = __halves2half2(l0, l1);
    ((__half2*)lo)[2*i+1] = __halves2half2(l2, l3);
}

// ---------------- HMMA split-fp16 GEMM ---------------------------------------
// C[m,n] = sum_k A[m,k]*B[n,k]; 128x128 tile, 8 warps, k-chunk 32, 2 stages
// (2 CTAs/SM). MMA issue product-major: same-acc reuse distance 8.
#define GROWB 80
#define GT_BYTES (128*GROWB)      // 10240
#define GSTAGE  (4*GT_BYTES)      // 40960: Ah, Al, Bh, Bl
#define GSMEM   (2*GSTAGE)        // 81920 -> 2 CTAs/SM

template<int MODE>
__global__ __launch_bounds__(256, 2) void gemm_kernel(float* __restrict__ out,
                                                      const float* __restrict__ bc)
{
    extern __shared__ char sm[];
    const uint32_t s0 = smem_u32(sm);
    const int tid = threadIdx.x;
    const int lane = tid & 31, warp = tid >> 5;
    const int wm = warp >> 2, wn = warp & 3;
    const int m0 = blockIdx.y * 128, n0 = blockIdx.x * 128;

    const __half *Ah, *Al, *Bh2, *Bl2;
    if (MODE == 0) {
        Ah = g_xh; Al = g_xl;
        Bh2 = g_wh + (size_t)blockIdx.z * E_ * E_;
        Bl2 = g_wl + (size_t)blockIdx.z * E_ * E_;
    } else {
        Ah = g_ohh; Al = g_ohl;
        Bh2 = g_wh + (size_t)3 * E_ * E_;
        Bl2 = g_wl + (size_t)3 * E_ * E_;
    }

    float acc[4][4][4];
#pragma unroll
    for (int a = 0; a < 4; a++)
#pragma unroll
        for (int b = 0; b < 4; b++)
#pragma unroll
            for (int c = 0; c < 4; c++) acc[a][b][c] = 0.f;

    auto load = [&](int c) {
        const uint32_t base = s0 + (c & 1) * GSTAGE;
        const int k0 = c * 32;
#pragma unroll
        for (int i = 0; i < 8; i++) {
            int g = i * 256 + tid;           // 0..2047
            int t = g >> 9;                  // 0..3 : Ah,Al,Bh,Bl
            int r = (g >> 2) & 127;
            int ch = g & 3;
            const __half* src = (t == 0) ? Ah : (t == 1) ? Al : (t == 2) ? Bh2 : Bl2;
            int row = ((t < 2) ? m0 : n0) + r;
            cp16(base + t * GT_BYTES + r * GROWB + ch * 16,
                 src + (size_t)row * E_ + k0 + ch * 8);
        }
    };

    load(0); CP_COMMIT();
    load(1); CP_COMMIT();

    const int rowoff = (lane & 7) + ((lane >> 3) & 1) * 8;
    for (int c = 0; c < 32; c++) {
        CP_WAIT1();
        __syncthreads();
        const uint32_t base = s0 + (c & 1) * GSTAGE;
#pragma unroll
        for (int ks = 0; ks < 2; ks++) {
            const int chunk = ks * 2 + (lane >> 4);
            uint32_t ah[4][4], al[4][4];
#pragma unroll
            for (int mi = 0; mi < 4; mi++) {
                uint32_t ra = base + (wm*64 + mi*16 + rowoff) * GROWB + chunk * 16;
                ldsm4(ra, ah[mi]);
                ldsm4(ra + GT_BYTES, al[mi]);
            }
#pragma unroll
            for (int p = 0; p < 2; p++) {
                uint32_t bh[4], bl[4];
                uint32_t rb = base + 2*GT_BYTES + (wn*32 + p*16 + rowoff) * GROWB + chunk * 16;
                ldsm4(rb, bh);
                ldsm4(rb + GT_BYTES, bl);
                // hh pass
#pragma unroll
                for (int mi = 0; mi < 4; mi++) mma_fp16(acc[mi][2*p],   ah[mi], bh[0], bh[2]);
#pragma unroll
                for (int mi = 0; mi < 4; mi++) mma_fp16(acc[mi][2*p+1], ah[mi], bh[1], bh[3]);
                // hl pass
#pragma unroll
                for (int mi = 0; mi < 4; mi++) mma_fp16(acc[mi][2*p],   ah[mi], bl[0], bl[2]);
#pragma unroll
                for (int mi = 0; mi < 4; mi++) mma_fp16(acc[mi][2*p+1], ah[mi], bl[1], bl[3]);
                // lh pass
#pragma unroll
                for (int mi = 0; mi < 4; mi++) mma_fp16(acc[mi][2*p],   al[mi], bh[0], bh[2]);
#pragma unroll
                for (int mi = 0; mi < 4; mi++) mma_fp16(acc[mi][2*p+1], al[mi], bh[1], bh[3]);
            }
        }
        __syncthreads();
        if (c + 2 < 32) load(c + 2);
        CP_COMMIT();
    }

    const int g = lane >> 2, tg2 = (lane & 3) * 2;
    if (MODE == 1) {
#pragma unroll
        for (int mi = 0; mi < 4; mi++) {
            int m = m0 + wm*64 + mi*16 + g;
#pragma unroll
            for (int ni = 0; ni < 4; ni++) {
                int n = n0 + wn*32 + ni*8 + tg2;
                float b0 = bc[n], b1 = bc[n+1];
                *(float2*)(out + (size_t)m * E_ + n) =
                    make_float2(acc[mi][ni][0] + b0, acc[mi][ni][1] + b1);
                *(float2*)(out + (size_t)(m+8) * E_ + n) =
                    make_float2(acc[mi][ni][2] + b0, acc[mi][ni][3] + b1);
            }
        }
        return;
    }

    // ---- MODE 0: transpose via smem, then per-row cumprod(cos) ----
    float* st = (float*)sm;   // [128][132] fp32
#pragma unroll
    for (int mi = 0; mi < 4; mi++) {
        int r = wm*64 + mi*16 + g;
#pragma unroll
        for (int ni = 0; ni < 4; ni++) {
            int n = wn*32 + ni*8 + tg2;
            st[(size_t)r * 132 + n]     = acc[mi][ni][0];
            st[(size_t)r * 132 + n + 1] = acc[mi][ni][1];
            st[(size_t)(r+8) * 132 + n]     = acc[mi][ni][2];
            st[(size_t)(r+8) * 132 + n + 1] = acc[mi][ni][3];
        }
    }
    __syncthreads();

    {
        const int head = tid >> 7;          // 0..1 (two heads per 128-col tile)
        const int r = tid & 127;
        const int m = m0 + r;
        const int b = m >> 11, sI = m & (S_ - 1);
        const int hglob = blockIdx.x * 2 + head;
        const int bh = b * H_ + hglob;
        const int z = blockIdx.z;
        const float* src = st + (size_t)r * 132 + head * 64;

        float run = 1.f;
        float val[64];
#pragma unroll
        for (int d = 0; d < 64; d++) { run *= __cosf(src[d]); val[d] = run; }

        if (z < 2) {
            const float sc = (z == 0) ? 0.125f : 1.0f;
            __half hb[64], lb[64];
#pragma unroll
            for (int d = 0; d < 64; d++) split16(val[d] * sc, hb[d], lb[d]);
            __half* dh = (z == 0 ? g_qh : g_kh) + ((size_t)bh * S_ + sI) * 64;
            __half* dl = (z == 0 ? g_ql : g_kl) + ((size_t)bh * S_ + sI) * 64;
#pragma unroll
            for (int j = 0; j < 8; j++) {
                ((uint4*)dh)[j] = ((uint4*)hb)[j];
                ((uint4*)dl)[j] = ((uint4*)lb)[j];
            }
        } else {
#pragma unroll
            for (int d = 0; d < 64; d++) {
                __half h, l; split16(val[d], h, l);
                g_vth[((size_t)bh * 64 + d) * S_ + sI] = h;
                g_vtl[((size_t)bh * 64 + d) * S_ + sI] = l;
            }
        }
    }
}

// ---------------- HMMA flash attention ---------------------------------------
// grid (S/128, BH), 256 threads. Q tile 128 rows, KV tiles 64, 2 stages
// (2 CTAs/SM). MMA issue interleaved over panel pairs (acc reuse distance 4).
#define FROWB 144
#define FQT  (128*FROWB)     // 18432
#define FKT  (64*FROWB)      // 9216
#define FSTAGE (4*FKT)       // 36864 : Kh, Kl, Vh, Vl
#define FSMEM (2*FQT + 2*FSTAGE)   // 110592 -> 2 CTAs/SM

__global__ __launch_bounds__(256, 2) void flash_kernel()
{
    extern __shared__ char sm[];
    const uint32_t s0 = smem_u32(sm);
    const uint32_t sQ = s0, sKV = s0 + 2 * FQT;
    const int tid = threadIdx.x, lane = tid & 31, warp = tid >> 5;
    const int bh = blockIdx.y;
    const int q0 = blockIdx.x * 128;

    const __half* Qh = g_qh + (size_t)bh * S_ * 64;
    const __half* Ql = g_ql + (size_t)bh * S_ * 64;
    const __half* Kh = g_kh + (size_t)bh * S_ * 64;
    const __half* Kl = g_kl + (size_t)bh * S_ * 64;
    const __half* Vh = g_vth + (size_t)bh * 64 * S_;
    const __half* Vl = g_vtl + (size_t)bh * 64 * S_;

    auto loadKV = [&](int t) {
        const uint32_t base = sKV + (t & 1) * FSTAGE;
        const int kv0 = t * 64;
#pragma unroll
        for (int i = 0; i < 8; i++) {
            int gi = i * 256 + tid;         // 0..2047
            int tl = gi >> 9;               // 0..3 : Kh,Kl,Vh,Vl
            int r = (gi >> 3) & 63;
            int ch = gi & 7;
            const __half* src;
            if (tl == 0)      src = Kh + (size_t)(kv0 + r) * 64 + ch * 8;
            else if (tl == 1) src = Kl + (size_t)(kv0 + r) * 64 + ch * 8;
            else if (tl == 2) src = Vh + (size_t)r * S_ + kv0 + ch * 8;
            else              src = Vl + (size_t)r * S_ + kv0 + ch * 8;
            cp16(base + tl * FKT + r * FROWB + ch * 16, src);
        }
    };

    {
#pragma unroll
        for (int i = 0; i < 8; i++) {
            int gi = i * 256 + tid;
            int tl = gi >> 10;              // 0,1 : Qh, Ql
            int r = (gi >> 3) & 127;
            int ch = gi & 7;
            const __half* src = (tl ? Ql : Qh) + (size_t)(q0 + r) * 64 + ch * 8;
            cp16(sQ + tl * FQT + r * FROWB + ch * 16, src);
        }
        loadKV(0); CP_COMMIT();
        loadKV(1); CP_COMMIT();
    }

    float o[8][4];
#pragma unroll
    for (int i = 0; i < 8; i++)
#pragma unroll
        for (int j = 0; j < 4; j++) o[i][j] = 0.f;
    float m0r = -1e30f, m1r = -1e30f, l0r = 0.f, l1r = 0.f;

    uint32_t qhf[4][4], qlf[4][4];
    const int rowoff = (lane & 7) + ((lane >> 3) & 1) * 8;

    for (int t = 0; t < 32; t++) {
        CP_WAIT1();
        __syncthreads();
        if (t == 0) {
#pragma unroll
            for (int ks = 0; ks < 4; ks++) {
                uint32_t ra = sQ + (warp*16 + rowoff) * FROWB + (ks*2 + (lane>>4)) * 16;
                ldsm4(ra, qhf[ks]);
                ldsm4(ra + FQT, qlf[ks]);
            }
        }
        const uint32_t kb = sKV + (t & 1) * FSTAGE;

        float s[8][4];
#pragma unroll
        for (int i = 0; i < 8; i++)
#pragma unroll
            for (int j = 0; j < 4; j++) s[i][j] = 0.f;

        // S = Q K^T, interleaved over panel pairs (acc reuse distance 4)
#pragma unroll
        for (int ks = 0; ks < 4; ks++) {
            const int chunk = ks * 2 + (lane >> 4);
#pragma unroll
            for (int pp = 0; pp < 2; pp++) {
                uint32_t kh[2][4], kl[2][4];
#pragma unroll
                for (int q = 0; q < 2; q++) {
                    uint32_t rb = kb + ((pp*2+q)*16 + rowoff) * FROWB + chunk * 16;
                    ldsm4(rb, kh[q]);
                    ldsm4(rb + FKT, kl[q]);
                }
#pragma unroll
                for (int q = 0; q < 2; q++) mma_fp16(s[2*(pp*2+q)],   qhf[ks], kh[q][0], kh[q][2]);
#pragma unroll
                for (int q = 0; q < 2; q++) mma_fp16(s[2*(pp*2+q)+1], qhf[ks], kh[q][1], kh[q][3]);
#pragma unroll
                for (int q = 0; q < 2; q++) mma_fp16(s[2*(pp*2+q)],   qhf[ks], kl[q][0], kl[q][2]);
#pragma unroll
                for (int q = 0; q < 2; q++) mma_fp16(s[2*(pp*2+q)+1], qhf[ks], kl[q][1], kl[q][3]);
#pragma unroll
                for (int q = 0; q < 2; q++) mma_fp16(s[2*(pp*2+q)],   qlf[ks], kh[q][0], kh[q][2]);
#pragma unroll
                for (int q = 0; q < 2; q++) mma_fp16(s[2*(pp*2+q)+1], qlf[ks], kh[q][1], kh[q][3]);
            }
        }

        // online softmax (rows: g = lane>>2 and g+8; quad-shuffles xor 1,2)
        float rm0 = -1e30f, rm1 = -1e30f;
#pragma unroll
        for (int ni = 0; ni < 8; ni++) {
            rm0 = fmaxf(rm0, fmaxf(s[ni][0], s[ni][1]));
            rm1 = fmaxf(rm1, fmaxf(s[ni][2], s[ni][3]));
        }
        rm0 = fmaxf(rm0, __shfl_xor_sync(0xffffffffu, rm0, 1));
        rm0 = fmaxf(rm0, __shfl_xor_sync(0xffffffffu, rm0, 2));
        rm1 = fmaxf(rm1, __shfl_xor_sync(0xffffffffu, rm1, 1));
        rm1 = fmaxf(rm1, __shfl_xor_sync(0xffffffffu, rm1, 2));
        float mn0 = fmaxf(m0r, rm0), mn1 = fmaxf(m1r, rm1);
        float sc0 = __expf(m0r - mn0), sc1 = __expf(m1r - mn1);

        uint32_t pf[8][2];
        float rs0 = 0.f, rs1 = 0.f;
#pragma unroll
        for (int ni = 0; ni < 8; ni++) {
            float p0 = __expf(s[ni][0] - mn0);
            float p1 = __expf(s[ni][1] - mn0);
            float p2 = __expf(s[ni][2] - mn1);
            float p3 = __expf(s[ni][3] - mn1);
            rs0 += p0 + p1; rs1 += p2 + p3;
            pf[ni][0] = pack2(p0, p1);
            pf[ni][1] = pack2(p2, p3);
        }
        rs0 += __shfl_xor_sync(0xffffffffu, rs0, 1);
        rs0 += __shfl_xor_sync(0xffffffffu, rs0, 2);
        rs1 += __shfl_xor_sync(0xffffffffu, rs1, 1);
        rs1 += __shfl_xor_sync(0xffffffffu, rs1, 2);
        l0r = l0r * sc0 + rs0;  m0r = mn0;
        l1r = l1r * sc1 + rs1;  m1r = mn1;
#pragma unroll
        for (int ni = 0; ni < 8; ni++) {
            o[ni][0] *= sc0; o[ni][1] *= sc0;
            o[ni][2] *= sc1; o[ni][3] *= sc1;
        }

        // O += P V, interleaved over panel pairs (acc reuse distance 4)
        const uint32_t vb = kb + 2 * FKT;
#pragma unroll
        for (int ks = 0; ks < 4; ks++) {
            uint32_t a[4] = { pf[2*ks][0], pf[2*ks][1], pf[2*ks+1][0], pf[2*ks+1][1] };
            const int chunk = ks * 2 + (lane >> 4);
#pragma unroll
            for (int pp = 0; pp < 2; pp++) {
                uint32_t vh[2][4], vl[2][4];
#pragma unroll
                for (int q = 0; q < 2; q++) {
                    uint32_t rb = vb + ((pp*2+q)*16 + rowoff) * FROWB + chunk * 16;
                    ldsm4(rb, vh[q]);
                    ldsm4(rb + FKT, vl[q]);
                }
#pragma unroll
                for (int q = 0; q < 2; q++) mma_fp16(o[2*(pp*2+q)],   a, vh[q][0], vh[q][2]);
#pragma unroll
                for (int q = 0; q < 2; q++) mma_fp16(o[2*(pp*2+q)+1], a, vh[q][1], vh[q][3]);
#pragma unroll
                for (int q = 0; q < 2; q++) mma_fp16(o[2*(pp*2+q)],   a, vl[q][0], vl[q][2]);
#pragma unroll
                for (int q = 0; q < 2; q++) mma_fp16(o[2*(pp*2+q)+1], a, vl[q][1], vl[q][3]);
            }
        }

        __syncthreads();
        if (t + 2 < 32) loadKV(t + 2);
        CP_COMMIT();
    }

    // epilogue: normalize, split hi/lo fp16, write [B,S,H,D] (= [M,E])
    const float inv0 = 1.f / l0r, inv1 = 1.f / l1r;
    const int g = lane >> 2, tg2 = (lane & 3) * 2;
    const int b = bh >> 4, h = bh & 15;
    const int sA = q0 + warp * 16 + g;
#pragma unroll
    for (int ni = 0; ni < 8; ni++) {
        int d = ni * 8 + tg2;
        size_t i0 = (((size_t)(b * S_ + sA)     * H_ + h) * D_ + d);
        size_t i1 = (((size_t)(b * S_ + sA + 8) * H_ + h) * D_ + d);
        __half h0,h1,h2,h3,l0,l1,l2,l3;
        split16(o[ni][0] * inv0, h0, l0);
        split16(o[ni][1] * inv0, h1, l1);
        split16(o[ni][2] * inv1, h2, l2);
        split16(o[ni][3] * inv1, h3, l3);
        *(__half2*)(g_ohh + i0) = __halves2half2(h0, h1);
        *(__half2*)(g_ohl + i0) = __halves2half2(l0, l1);
        *(__half2*)(g_ohh + i1) = __halves2half2(h2, h3);
        *(__half2*)(g_ohl + i1) = __halves2half2(l2, l3);
    }
}

// ---------------------------------------------------------------------------
extern "C" void kernel_launch(void* const* d_in, const int* in_sizes, int n_in,
                              void* d_out, int out_size)
{
    const float* x  = (const float*)d_in[0];
    const float* Wq = (const float*)d_in[1];
    const float* Wk = (const float*)d_in[2];
    const float* Wv = (const float*)d_in[3];
    const float* Wc = (const float*)d_in[4];
    const float* bc = (const float*)d_in[5];
    float* out = (float*)d_out;

    cudaFuncSetAttribute(gemm_kernel<0>, cudaFuncAttributeMaxDynamicSharedMemorySize, GSMEM);
    cudaFuncSetAttribute(gemm_kernel<1>, cudaFuncAttributeMaxDynamicSharedMemorySize, GSMEM);
    cudaFuncSetAttribute(flash_kernel,   cudaFuncAttributeMaxDynamicSharedMemorySize, FSMEM);

    // 1) fp32 -> fp16 hi/lo for x and all weights
    convert_kernel<<<dim3(4096, 5), 256>>>(x, Wq, Wk, Wv, Wc);

    // 2) QKV projections (HMMA split) + fused quantum cumprod(cos) epilogue
    gemm_kernel<0><<<dim3(E_/128, M_/128, 3), 256, GSMEM>>>(nullptr, nullptr);

    // 3) flash attention (HMMA split QK, fp16 P, split V)
    flash_kernel<<<dim3(S_/128, BH_), 256, FSMEM>>>();

    // 4) output projection (HMMA split) + bias
    gemm_kernel<1><<<dim3(E_/128, M_/128, 1), 256, GSMEM>>>(out, bc);
}

// round 6
// speedup vs baseline: 1.2050x; 1.0765x over previous
#include <cuda_runtime.h>
#include <cuda_fp16.h>
#include <stdint.h>
#include <math.h>

#define B_ 2
#define S_ 2048
#define E_ 1024
#define H_ 16
#define D_ 64
#define M_ (B_*S_)    // 4096
#define BH_ (B_*H_)   // 32

// ---------------- scratch (device globals; no allocation allowed) -------------
__device__ __half g_xh[(size_t)M_*E_];
__device__ __half g_xl[(size_t)M_*E_];
__device__ __half g_wh[(size_t)4*E_*E_];
__device__ __half g_wl[(size_t)4*E_*E_];
__device__ __half g_qh[(size_t)BH_*S_*D_];
__device__ __half g_ql[(size_t)BH_*S_*D_];
__device__ __half g_kh[(size_t)BH_*S_*D_];
__device__ __half g_kl[(size_t)BH_*S_*D_];
__device__ __half g_vth[(size_t)BH_*D_*S_];   // transposed [bh][d][s]
__device__ __half g_vtl[(size_t)BH_*D_*S_];
__device__ __half g_ohh[(size_t)M_*E_];
__device__ __half g_ohl[(size_t)M_*E_];

// ---------------- helpers ----------------------------------------------------
__device__ __forceinline__ uint32_t smem_u32(const void* p) {
    uint32_t a;
    asm("{ .reg .u64 t; cvta.to.shared.u64 t, %1; cvt.u32.u64 %0, t; }" : "=r"(a) : "l"(p));
    return a;
}
__device__ __forceinline__ void cp16(uint32_t s, const void* g) {
    asm volatile("cp.async.cg.shared.global [%0], [%1], 16;" :: "r"(s), "l"(g));
}
#define CP_COMMIT() asm volatile("cp.async.commit_group;" ::: "memory")
#define CP_WAIT1()  asm volatile("cp.async.wait_group 1;" ::: "memory")

__device__ __forceinline__ void ldsm4(uint32_t addr, uint32_t r[4]) {
    asm volatile("ldmatrix.sync.aligned.m8n8.x4.shared.b16 {%0,%1,%2,%3}, [%4];"
        : "=r"(r[0]), "=r"(r[1]), "=r"(r[2]), "=r"(r[3]) : "r"(addr));
}
__device__ __forceinline__ void mma_fp16(float* c, const uint32_t* a, uint32_t b0, uint32_t b1) {
    asm volatile(
        "mma.sync.aligned.m16n8k16.row.col.f32.f16.f16.f32 "
        "{%0,%1,%2,%3}, {%4,%5,%6,%7}, {%8,%9}, {%0,%1,%2,%3};"
        : "+f"(c[0]), "+f"(c[1]), "+f"(c[2]), "+f"(c[3])
        : "r"(a[0]), "r"(a[1]), "r"(a[2]), "r"(a[3]), "r"(b0), "r"(b1));
}
__device__ __forceinline__ uint32_t pack2(float x, float y) {
    __half2 h = __floats2half2_rn(x, y);
    return *(uint32_t*)&h;
}
__device__ __forceinline__ void split16(float v, __half& h, __half& l) {
    h = __float2half_rn(v);
    l = __float2half_rn(v - __half2float(h));
}

// ---------------- fp32 -> fp16 hi/lo conversion ------------------------------
__global__ __launch_bounds__(256) void convert_kernel(
    const float* __restrict__ x,  const float* __restrict__ Wq,
    const float* __restrict__ Wk, const float* __restrict__ Wv,
    const float* __restrict__ Wc)
{
    const int seg = blockIdx.y;
    const float* src; __half* hi; __half* lo; int n4;
    if (seg == 0) { src = x;  hi = g_xh; lo = g_xl; n4 = M_*E_/4; }
    else {
        src = (seg==1)?Wq:(seg==2)?Wk:(seg==3)?Wv:Wc;
        hi = g_wh + (size_t)(seg-1)*E_*E_;
        lo = g_wl + (size_t)(seg-1)*E_*E_;
        n4 = E_*E_/4;
    }
    int i = blockIdx.x * 256 + threadIdx.x;
    if (i >= n4) return;
    float4 v = ((const float4*)src)[i];
    __half h0,h1,h2,h3,l0,l1,l2,l3;
    split16(v.x,h0,l0); split16(v.y,h1,l1); split16(v.z,h2,l2); split16(v.w,h3,l3);
    ((__half2*)hi)[2*i]   = __halves2half2(h0, h1);
    ((__half2*)hi)[2*i+1] = __halves2half2(h2, h3);
    ((__half2*)lo)[2*i]   = __halves2half2(l0, l1);
    ((__half2*)lo)[2*i+1] = __halves2half2(l2, l3);
}

// ---------------- HMMA split-fp16 GEMM ---------------------------------------
// 128x128 tile, 8 warps (2x4), k-chunk 32, 3 stages + SINGLE barrier per chunk.
// 64B rows with XOR swizzle (chunk ^ (row>>1)&3): conflict-free ldmatrix.
#define GT_BYTES (128*64)         // 8192
#define GSTAGE  (4*GT_BYTES)      // 32768: Ah, Al, Bh, Bl
#define GNST 3
#define GSMEM   (GNST*GSTAGE)     // 98304 -> 2 CTAs/SM

__device__ __forceinline__ uint32_t goff(int r, int ch) {
    return (uint32_t)(r * 64 + ((ch ^ ((r >> 1) & 3)) << 4));
}

template<int MODE>
__global__ __launch_bounds__(256, 2) void gemm_kernel(float* __restrict__ out,
                                                      const float* __restrict__ bc)
{
    extern __shared__ char sm[];
    const uint32_t s0 = smem_u32(sm);
    const int tid = threadIdx.x;
    const int lane = tid & 31, warp = tid >> 5;
    const int wm = warp >> 2, wn = warp & 3;
    const int m0 = blockIdx.y * 128, n0 = blockIdx.x * 128;

    const __half *Ah, *Al, *Bh2, *Bl2;
    if (MODE == 0) {
        Ah = g_xh; Al = g_xl;
        Bh2 = g_wh + (size_t)blockIdx.z * E_ * E_;
        Bl2 = g_wl + (size_t)blockIdx.z * E_ * E_;
    } else {
        Ah = g_ohh; Al = g_ohl;
        Bh2 = g_wh + (size_t)3 * E_ * E_;
        Bl2 = g_wl + (size_t)3 * E_ * E_;
    }

    float acc[4][4][4];
#pragma unroll
    for (int a = 0; a < 4; a++)
#pragma unroll
        for (int b = 0; b < 4; b++)
#pragma unroll
            for (int c = 0; c < 4; c++) acc[a][b][c] = 0.f;

    auto load = [&](int c) {
        const uint32_t base = s0 + (c % GNST) * GSTAGE;
        const int k0 = c * 32;
#pragma unroll
        for (int i = 0; i < 8; i++) {
            int g = i * 256 + tid;           // 0..2047
            int t = g >> 9;                  // 0..3 : Ah,Al,Bh,Bl
            int r = (g >> 2) & 127;
            int ch = g & 3;
            const __half* src = (t == 0) ? Ah : (t == 1) ? Al : (t == 2) ? Bh2 : Bl2;
            int row = ((t < 2) ? m0 : n0) + r;
            cp16(base + t * GT_BYTES + goff(r, ch),
                 src + (size_t)row * E_ + k0 + ch * 8);
        }
    };

    load(0); CP_COMMIT();
    load(1); CP_COMMIT();

    const int rowoff = (lane & 7) + ((lane >> 3) & 1) * 8;
    for (int c = 0; c < 32; c++) {
        CP_WAIT1();              // group c complete (c+1 may pend)
        __syncthreads();         // copies visible to all + everyone done with buf (c-1)%3
        if (c + 2 < 32) load(c + 2);   // -> buf (c+2)%3 == (c-1)%3 : safe, overlaps compute
        CP_COMMIT();
        const uint32_t base = s0 + (c % GNST) * GSTAGE;
#pragma unroll
        for (int ks = 0; ks < 2; ks++) {
            const int chunk = ks * 2 + (lane >> 4);
            uint32_t ah[4][4], al[4][4];
#pragma unroll
            for (int mi = 0; mi < 4; mi++) {
                uint32_t ra = base + goff(wm*64 + mi*16 + rowoff, chunk);
                ldsm4(ra, ah[mi]);
                ldsm4(ra + GT_BYTES, al[mi]);
            }
#pragma unroll
            for (int p = 0; p < 2; p++) {
                uint32_t bh[4], bl[4];
                uint32_t rb = base + 2*GT_BYTES + goff(wn*32 + p*16 + rowoff, chunk);
                ldsm4(rb, bh);
                ldsm4(rb + GT_BYTES, bl);
                // hh pass
#pragma unroll
                for (int mi = 0; mi < 4; mi++) mma_fp16(acc[mi][2*p],   ah[mi], bh[0], bh[2]);
#pragma unroll
                for (int mi = 0; mi < 4; mi++) mma_fp16(acc[mi][2*p+1], ah[mi], bh[1], bh[3]);
                // hl pass
#pragma unroll
                for (int mi = 0; mi < 4; mi++) mma_fp16(acc[mi][2*p],   ah[mi], bl[0], bl[2]);
#pragma unroll
                for (int mi = 0; mi < 4; mi++) mma_fp16(acc[mi][2*p+1], ah[mi], bl[1], bl[3]);
                // lh pass
#pragma unroll
                for (int mi = 0; mi < 4; mi++) mma_fp16(acc[mi][2*p],   al[mi], bh[0], bh[2]);
#pragma unroll
                for (int mi = 0; mi < 4; mi++) mma_fp16(acc[mi][2*p+1], al[mi], bh[1], bh[3]);
            }
        }
    }

    const int g = lane >> 2, tg2 = (lane & 3) * 2;
    if (MODE == 1) {
#pragma unroll
        for (int mi = 0; mi < 4; mi++) {
            int m = m0 + wm*64 + mi*16 + g;
#pragma unroll
            for (int ni = 0; ni < 4; ni++) {
                int n = n0 + wn*32 + ni*8 + tg2;
                float b0 = bc[n], b1 = bc[n+1];
                *(float2*)(out + (size_t)m * E_ + n) =
                    make_float2(acc[mi][ni][0] + b0, acc[mi][ni][1] + b1);
                *(float2*)(out + (size_t)(m+8) * E_ + n) =
                    make_float2(acc[mi][ni][2] + b0, acc[mi][ni][3] + b1);
            }
        }
        return;
    }

    // ---- MODE 0: transpose via smem, then per-row cumprod(cos) ----
    __syncthreads();             // everyone done reading smem stages
    float* st = (float*)sm;      // [128][132] fp32 = 67.6KB <= 96KB
#pragma unroll
    for (int mi = 0; mi < 4; mi++) {
        int r = wm*64 + mi*16 + g;
#pragma unroll
        for (int ni = 0; ni < 4; ni++) {
            int n = wn*32 + ni*8 + tg2;
            st[(size_t)r * 132 + n]     = acc[mi][ni][0];
            st[(size_t)r * 132 + n + 1] = acc[mi][ni][1];
            st[(size_t)(r+8) * 132 + n]     = acc[mi][ni][2];
            st[(size_t)(r+8) * 132 + n + 1] = acc[mi][ni][3];
        }
    }
    __syncthreads();

    {
        const int head = tid >> 7;          // 0..1 (two heads per 128-col tile)
        const int r = tid & 127;
        const int m = m0 + r;
        const int b = m >> 11, sI = m & (S_ - 1);
        const int hglob = blockIdx.x * 2 + head;
        const int bh = b * H_ + hglob;
        const int z = blockIdx.z;
        const float* src = st + (size_t)r * 132 + head * 64;

        float run = 1.f;
        float val[64];
#pragma unroll
        for (int d = 0; d < 64; d++) { run *= __cosf(src[d]); val[d] = run; }

        if (z < 2) {
            const float sc = (z == 0) ? 0.125f : 1.0f;
            __half hb[64], lb[64];
#pragma unroll
            for (int d = 0; d < 64; d++) split16(val[d] * sc, hb[d], lb[d]);
            __half* dh = (z == 0 ? g_qh : g_kh) + ((size_t)bh * S_ + sI) * 64;
            __half* dl = (z == 0 ? g_ql : g_kl) + ((size_t)bh * S_ + sI) * 64;
#pragma unroll
            for (int j = 0; j < 8; j++) {
                ((uint4*)dh)[j] = ((uint4*)hb)[j];
                ((uint4*)dl)[j] = ((uint4*)lb)[j];
            }
        } else {
#pragma unroll
            for (int d = 0; d < 64; d++) {
                __half h, l; split16(val[d], h, l);
                g_vth[((size_t)bh * 64 + d) * S_ + sI] = h;
                g_vtl[((size_t)bh * 64 + d) * S_ + sI] = l;
            }
        }
    }
}

// ---------------- HMMA flash attention ---------------------------------------
// grid (S/128, BH), 256 threads, 2 CTAs/SM. 3 KV stages + single barrier per
// tile. Q is staged through KV stage 2 (dead after one-time ldsm at t==0).
#define FROWB 144
#define FQT  (128*FROWB)     // 18432
#define FKT  (64*FROWB)      // 9216
#define FSTAGE (4*FKT)       // 36864 : Kh, Kl, Vh, Vl
#define FNST 3
#define FSMEM (FNST*FSTAGE)  // 110592 -> 2 CTAs/SM

__global__ __launch_bounds__(256, 2) void flash_kernel()
{
    extern __shared__ char sm[];
    const uint32_t s0 = smem_u32(sm);
    const uint32_t sQ = s0 + 2 * FSTAGE;   // Q lives in stage 2 until t==0 ldsm
    const int tid = threadIdx.x, lane = tid & 31, warp = tid >> 5;
    const int bh = blockIdx.y;
    const int q0 = blockIdx.x * 128;

    const __half* Qh = g_qh + (size_t)bh * S_ * 64;
    const __half* Ql = g_ql + (size_t)bh * S_ * 64;
    const __half* Kh = g_kh + (size_t)bh * S_ * 64;
    const __half* Kl = g_kl + (size_t)bh * S_ * 64;
    const __half* Vh = g_vth + (size_t)bh * 64 * S_;
    const __half* Vl = g_vtl + (size_t)bh * 64 * S_;

    auto loadKV = [&](int t) {
        const uint32_t base = s0 + (t % FNST) * FSTAGE;
        const int kv0 = t * 64;
#pragma unroll
        for (int i = 0; i < 8; i++) {
            int gi = i * 256 + tid;         // 0..2047
            int tl = gi >> 9;               // 0..3 : Kh,Kl,Vh,Vl
            int r = (gi >> 3) & 63;
            int ch = gi & 7;
            const __half* src;
            if (tl == 0)      src = Kh + (size_t)(kv0 + r) * 64 + ch * 8;
            else if (tl == 1) src = Kl + (size_t)(kv0 + r) * 64 + ch * 8;
            else if (tl == 2) src = Vh + (size_t)r * S_ + kv0 + ch * 8;
            else              src = Vl + (size_t)r * S_ + kv0 + ch * 8;
            cp16(base + tl * FKT + r * FROWB + ch * 16, src);
        }
    };

    {
        // group 0: Q (into stage 2) + KV0; group 1: KV1
#pragma unroll
        for (int i = 0; i < 8; i++) {
            int gi = i * 256 + tid;
            int tl = gi >> 10;              // 0,1 : Qh, Ql
            int r = (gi >> 3) & 127;
            int ch = gi & 7;
            const __half* src = (tl ? Ql : Qh) + (size_t)(q0 + r) * 64 + ch * 8;
            cp16(sQ + tl * FQT + r * FROWB + ch * 16, src);
        }
        loadKV(0); CP_COMMIT();
        loadKV(1); CP_COMMIT();
    }

    float o[8][4];
#pragma unroll
    for (int i = 0; i < 8; i++)
#pragma unroll
        for (int j = 0; j < 4; j++) o[i][j] = 0.f;
    float m0r = -1e30f, m1r = -1e30f, l0r = 0.f, l1r = 0.f;

    uint32_t qhf[4][4], qlf[4][4];
    const int rowoff = (lane & 7) + ((lane >> 3) & 1) * 8;

    for (int t = 0; t < 32; t++) {
        CP_WAIT1();              // group t done (t+1 may pend)
        __syncthreads();
        if (t == 0) {
            // one-time Q fragment load from stage 2; must finish CTA-wide
            // before loadKV(2) overwrites stage 2
#pragma unroll
            for (int ks = 0; ks < 4; ks++) {
                uint32_t ra = sQ + (warp*16 + rowoff) * FROWB + (ks*2 + (lane>>4)) * 16;
                ldsm4(ra, qhf[ks]);
                ldsm4(ra + FQT, qlf[ks]);
            }
            __syncthreads();
        }
        if (t + 2 < 32) loadKV(t + 2);   // -> stage (t+2)%3 == (t-1)%3 : safe
        CP_COMMIT();

        const uint32_t kb = s0 + (t % FNST) * FSTAGE;

        float s[8][4];
#pragma unroll
        for (int i = 0; i < 8; i++)
#pragma unroll
            for (int j = 0; j < 4; j++) s[i][j] = 0.f;

        // S = Q K^T, interleaved over panel pairs (acc reuse distance 4)
#pragma unroll
        for (int ks = 0; ks < 4; ks++) {
            const int chunk = ks * 2 + (lane >> 4);
#pragma unroll
            for (int pp = 0; pp < 2; pp++) {
                uint32_t kh[2][4], kl[2][4];
#pragma unroll
                for (int q = 0; q < 2; q++) {
                    uint32_t rb = kb + ((pp*2+q)*16 + rowoff) * FROWB + chunk * 16;
                    ldsm4(rb, kh[q]);
                    ldsm4(rb + FKT, kl[q]);
                }
#pragma unroll
                for (int q = 0; q < 2; q++) mma_fp16(s[2*(pp*2+q)],   qhf[ks], kh[q][0], kh[q][2]);
#pragma unroll
                for (int q = 0; q < 2; q++) mma_fp16(s[2*(pp*2+q)+1], qhf[ks], kh[q][1], kh[q][3]);
#pragma unroll
                for (int q = 0; q < 2; q++) mma_fp16(s[2*(pp*2+q)],   qhf[ks], kl[q][0], kl[q][2]);
#pragma unroll
                for (int q = 0; q < 2; q++) mma_fp16(s[2*(pp*2+q)+1], qhf[ks], kl[q][1], kl[q][3]);
#pragma unroll
                for (int q = 0; q < 2; q++) mma_fp16(s[2*(pp*2+q)],   qlf[ks], kh[q][0], kh[q][2]);
#pragma unroll
                for (int q = 0; q < 2; q++) mma_fp16(s[2*(pp*2+q)+1], qlf[ks], kh[q][1], kh[q][3]);
            }
        }

        // online softmax (rows: g = lane>>2 and g+8; quad-shuffles xor 1,2)
        float rm0 = -1e30f, rm1 = -1e30f;
#pragma unroll
        for (int ni = 0; ni < 8; ni++) {
            rm0 = fmaxf(rm0, fmaxf(s[ni][0], s[ni][1]));
            rm1 = fmaxf(rm1, fmaxf(s[ni][2], s[ni][3]));
        }
        rm0 = fmaxf(rm0, __shfl_xor_sync(0xffffffffu, rm0, 1));
        rm0 = fmaxf(rm0, __shfl_xor_sync(0xffffffffu, rm0, 2));
        rm1 = fmaxf(rm1, __shfl_xor_sync(0xffffffffu, rm1, 1));
        rm1 = fmaxf(rm1, __shfl_xor_sync(0xffffffffu, rm1, 2));
        float mn0 = fmaxf(m0r, rm0), mn1 = fmaxf(m1r, rm1);
        float sc0 = __expf(m0r - mn0), sc1 = __expf(m1r - mn1);

        uint32_t pf[8][2];
        float rs0 = 0.f, rs1 = 0.f;
#pragma unroll
        for (int ni = 0; ni < 8; ni++) {
            float p0 = __expf(s[ni][0] - mn0);
            float p1 = __expf(s[ni][1] - mn0);
            float p2 = __expf(s[ni][2] - mn1);
            float p3 = __expf(s[ni][3] - mn1);
            rs0 += p0 + p1; rs1 += p2 + p3;
            pf[ni][0] = pack2(p0, p1);
            pf[ni][1] = pack2(p2, p3);
        }
        rs0 += __shfl_xor_sync(0xffffffffu, rs0, 1);
        rs0 += __shfl_xor_sync(0xffffffffu, rs0, 2);
        rs1 += __shfl_xor_sync(0xffffffffu, rs1, 1);
        rs1 += __shfl_xor_sync(0xffffffffu, rs1, 2);
        l0r = l0r * sc0 + rs0;  m0r = mn0;
        l1r = l1r * sc1 + rs1;  m1r = mn1;
#pragma unroll
        for (int ni = 0; ni < 8; ni++) {
            o[ni][0] *= sc0; o[ni][1] *= sc0;
            o[ni][2] *= sc1; o[ni][3] *= sc1;
        }

        // O += P V, interleaved over panel pairs (acc reuse distance 4)
        const uint32_t vb = kb + 2 * FKT;
#pragma unroll
        for (int ks = 0; ks < 4; ks++) {
            uint32_t a[4] = { pf[2*ks][0], pf[2*ks][1], pf[2*ks+1][0], pf[2*ks+1][1] };
            const int chunk = ks * 2 + (lane >> 4);
#pragma unroll
            for (int pp = 0; pp < 2; pp++) {
                uint32_t vh[2][4], vl[2][4];
#pragma unroll
                for (int q = 0; q < 2; q++) {
                    uint32_t rb = vb + ((pp*2+q)*16 + rowoff) * FROWB + chunk * 16;
                    ldsm4(rb, vh[q]);
                    ldsm4(rb + FKT, vl[q]);
                }
#pragma unroll
                for (int q = 0; q < 2; q++) mma_fp16(o[2*(pp*2+q)],   a, vh[q][0], vh[q][2]);
#pragma unroll
                for (int q = 0; q < 2; q++) mma_fp16(o[2*(pp*2+q)+1], a, vh[q][1], vh[q][3]);
#pragma unroll
                for (int q = 0; q < 2; q++) mma_fp16(o[2*(pp*2+q)],   a, vl[q][0], vl[q][2]);
#pragma unroll
                for (int q = 0; q < 2; q++) mma_fp16(o[2*(pp*2+q)+1], a, vl[q][1], vl[q][3]);
            }
        }
    }

    // epilogue: normalize, split hi/lo fp16, write [B,S,H,D] (= [M,E])
    const float inv0 = 1.f / l0r, inv1 = 1.f / l1r;
    const int g = lane >> 2, tg2 = (lane & 3) * 2;
    const int b = bh >> 4, h = bh & 15;
    const int sA = q0 + warp * 16 + g;
#pragma unroll
    for (int ni = 0; ni < 8; ni++) {
        int d = ni * 8 + tg2;
        size_t i0 = (((size_t)(b * S_ + sA)     * H_ + h) * D_ + d);
        size_t i1 = (((size_t)(b * S_ + sA + 8) * H_ + h) * D_ + d);
        __half h0,h1,h2,h3,l0,l1,l2,l3;
        split16(o[ni][0] * inv0, h0, l0);
        split16(o[ni][1] * inv0, h1, l1);
        split16(o[ni][2] * inv1, h2, l2);
        split16(o[ni][3] * inv1, h3, l3);
        *(__half2*)(g_ohh + i0) = __halves2half2(h0, h1);
        *(__half2*)(g_ohl + i0) = __halves2half2(l0, l1);
        *(__half2*)(g_ohh + i1) = __halves2half2(h2, h3);
        *(__half2*)(g_ohl + i1) = __halves2half2(l2, l3);
    }
}

// ---------------------------------------------------------------------------
extern "C" void kernel_launch(void* const* d_in, const int* in_sizes, int n_in,
                              void* d_out, int out_size)
{
    const float* x  = (const float*)d_in[0];
    const float* Wq = (const float*)d_in[1];
    const float* Wk = (const float*)d_in[2];
    const float* Wv = (const float*)d_in[3];
    const float* Wc = (const float*)d_in[4];
    const float* bc = (const float*)d_in[5];
    float* out = (float*)d_out;

    cudaFuncSetAttribute(gemm_kernel<0>, cudaFuncAttributeMaxDynamicSharedMemorySize, GSMEM);
    cudaFuncSetAttribute(gemm_kernel<1>, cudaFuncAttributeMaxDynamicSharedMemorySize, GSMEM);
    cudaFuncSetAttribute(flash_kernel,   cudaFuncAttributeMaxDynamicSharedMemorySize, FSMEM);

    // 1) fp32 -> fp16 hi/lo for x and all weights
    convert_kernel<<<dim3(4096, 5), 256>>>(x, Wq, Wk, Wv, Wc);

    // 2) QKV projections (HMMA split) + fused quantum cumprod(cos) epilogue
    gemm_kernel<0><<<dim3(E_/128, M_/128, 3), 256, GSMEM>>>(nullptr, nullptr);

    // 3) flash attention (HMMA split QK, fp16 P, split V)
    flash_kernel<<<dim3(S_/128, BH_), 256, FSMEM>>>();

    // 4) output projection (HMMA split) + bias
    gemm_kernel<1><<<dim3(E_/128, M_/128, 1), 256, GSMEM>>>(out, bc);
}

// round 7
// speedup vs baseline: 1.3716x; 1.1383x over previous
#include <cuda_runtime.h>
#include <cuda_fp16.h>
#include <stdint.h>
#include <math.h>

#define B_ 2
#define S_ 2048
#define E_ 1024
#define H_ 16
#define D_ 64
#define M_ (B_*S_)    // 4096
#define BH_ (B_*H_)   // 32

// ---------------- scratch (device globals; no allocation allowed) -------------
__device__ __half g_xh[(size_t)M_*E_];
__device__ __half g_xl[(size_t)M_*E_];
__device__ __half g_wh[(size_t)4*E_*E_];
__device__ __half g_wl[(size_t)4*E_*E_];
__device__ __half g_qh[(size_t)BH_*S_*D_];    // Q: plain fp16 (pre-scaled /8)
__device__ __half g_kh[(size_t)BH_*S_*D_];
__device__ __half g_kl[(size_t)BH_*S_*D_];
__device__ __half g_vth[(size_t)BH_*D_*S_];   // transposed [bh][d][s]
__device__ __half g_vtl[(size_t)BH_*D_*S_];
__device__ __half g_oh[(size_t)M_*E_];        // attn out: plain fp16

// ---------------- helpers ----------------------------------------------------
__device__ __forceinline__ uint32_t smem_u32(const void* p) {
    uint32_t a;
    asm("{ .reg .u64 t; cvta.to.shared.u64 t, %1; cvt.u32.u64 %0, t; }" : "=r"(a) : "l"(p));
    return a;
}
__device__ __forceinline__ void cp16(uint32_t s, const void* g) {
    asm volatile("cp.async.cg.shared.global [%0], [%1], 16;" :: "r"(s), "l"(g));
}
#define CP_COMMIT() asm volatile("cp.async.commit_group;" ::: "memory")
#define CP_WAIT1()  asm volatile("cp.async.wait_group 1;" ::: "memory")

__device__ __forceinline__ void ldsm4(uint32_t addr, uint32_t r[4]) {
    asm volatile("ldmatrix.sync.aligned.m8n8.x4.shared.b16 {%0,%1,%2,%3}, [%4];"
        : "=r"(r[0]), "=r"(r[1]), "=r"(r[2]), "=r"(r[3]) : "r"(addr));
}
__device__ __forceinline__ void mma_fp16(float* c, const uint32_t* a, uint32_t b0, uint32_t b1) {
    asm volatile(
        "mma.sync.aligned.m16n8k16.row.col.f32.f16.f16.f32 "
        "{%0,%1,%2,%3}, {%4,%5,%6,%7}, {%8,%9}, {%0,%1,%2,%3};"
        : "+f"(c[0]), "+f"(c[1]), "+f"(c[2]), "+f"(c[3])
        : "r"(a[0]), "r"(a[1]), "r"(a[2]), "r"(a[3]), "r"(b0), "r"(b1));
}
__device__ __forceinline__ uint32_t pack2(float x, float y) {
    __half2 h = __floats2half2_rn(x, y);
    return *(uint32_t*)&h;
}
__device__ __forceinline__ void split16(float v, __half& h, __half& l) {
    h = __float2half_rn(v);
    l = __float2half_rn(v - __half2float(h));
}

// ---------------- fp32 -> fp16 hi/lo conversion ------------------------------
__global__ __launch_bounds__(256) void convert_kernel(
    const float* __restrict__ x,  const float* __restrict__ Wq,
    const float* __restrict__ Wk, const float* __restrict__ Wv,
    const float* __restrict__ Wc)
{
    const int seg = blockIdx.y;
    const float* src; __half* hi; __half* lo; int n4;
    if (seg == 0) { src = x;  hi = g_xh; lo = g_xl; n4 = M_*E_/4; }
    else {
        src = (seg==1)?Wq:(seg==2)?Wk:(seg==3)?Wv:Wc;
        hi = g_wh + (size_t)(seg-1)*E_*E_;
        lo = g_wl + (size_t)(seg-1)*E_*E_;
        n4 = E_*E_/4;
    }
    int i = blockIdx.x * 256 + threadIdx.x;
    if (i >= n4) return;
    float4 v = ((const float4*)src)[i];
    __half h0,h1,h2,h3,l0,l1,l2,l3;
    split16(v.x,h0,l0); split16(v.y,h1,l1); split16(v.z,h2,l2); split16(v.w,h3,l3);
    ((__half2*)hi)[2*i]   = __halves2half2(h0, h1);
    ((__half2*)hi)[2*i+1] = __halves2half2(h2, h3);
    ((__half2*)lo)[2*i]   = __halves2half2(l0, l1);
    ((__half2*)lo)[2*i+1] = __halves2half2(l2, l3);
}

// ---------------- HMMA GEMM ---------------------------------------------------
// 128x128 tile, 8 warps (2x4), k-chunk 32, 3 stages, single barrier per chunk.
// MODE 0 (QKV): A=x hi/lo, B=W hi/lo, 3 products (hh+hl+lh). Epilogue: quantum
//               cumprod(cos) -> q (plain fp16, /8), k (hi/lo), v^T (hi/lo).
// MODE 1 (out): A=attn-out plain fp16, B=Wc hi/lo, 2 products (hh+hl) + bias.
#define GT_BYTES (128*64)         // 8192 (64B rows, XOR swizzle)

__device__ __forceinline__ uint32_t goff(int r, int ch) {
    return (uint32_t)(r * 64 + ((ch ^ ((r >> 1) & 3)) << 4));
}

template<int MODE>
__global__ __launch_bounds__(256, 2) void gemm_kernel(float* __restrict__ out,
                                                      const float* __restrict__ bc)
{
    constexpr int NT = (MODE == 0) ? 4 : 3;          // tiles per stage
    constexpr uint32_t STAGE = NT * GT_BYTES;

    extern __shared__ char sm[];
    const uint32_t s0 = smem_u32(sm);
    const int tid = threadIdx.x;
    const int lane = tid & 31, warp = tid >> 5;
    const int wm = warp >> 2, wn = warp & 3;
    const int m0 = blockIdx.y * 128, n0 = blockIdx.x * 128;

    const __half *Ah, *Al, *Bh2, *Bl2;
    if (MODE == 0) {
        Ah = g_xh; Al = g_xl;
        Bh2 = g_wh + (size_t)blockIdx.z * E_ * E_;
        Bl2 = g_wl + (size_t)blockIdx.z * E_ * E_;
    } else {
        Ah = g_oh; Al = nullptr;
        Bh2 = g_wh + (size_t)3 * E_ * E_;
        Bl2 = g_wl + (size_t)3 * E_ * E_;
    }

    float acc[4][4][4];
#pragma unroll
    for (int a = 0; a < 4; a++)
#pragma unroll
        for (int b = 0; b < 4; b++)
#pragma unroll
            for (int c = 0; c < 4; c++) acc[a][b][c] = 0.f;

    auto load = [&](int c) {
        const uint32_t base = s0 + (c % 3) * STAGE;
        const int k0 = c * 32;
#pragma unroll
        for (int i = 0; i < NT * 2; i++) {
            int g = i * 256 + tid;
            int t = g >> 9;                  // tile index
            int r = (g >> 2) & 127;
            int ch = g & 3;
            const __half* src; int row;
            if (MODE == 0) {
                src = (t == 0) ? Ah : (t == 1) ? Al : (t == 2) ? Bh2 : Bl2;
                row = ((t < 2) ? m0 : n0) + r;
            } else {
                src = (t == 0) ? Ah : (t == 1) ? Bh2 : Bl2;
                row = ((t == 0) ? m0 : n0) + r;
            }
            cp16(base + t * GT_BYTES + goff(r, ch),
                 src + (size_t)row * E_ + k0 + ch * 8);
        }
    };

    load(0); CP_COMMIT();
    load(1); CP_COMMIT();

    const int rowoff = (lane & 7) + ((lane >> 3) & 1) * 8;
    constexpr uint32_t BOFF = (MODE == 0) ? 2u * GT_BYTES : 1u * GT_BYTES;

    for (int c = 0; c < 32; c++) {
        CP_WAIT1();
        __syncthreads();
        if (c + 2 < 32) load(c + 2);
        CP_COMMIT();
        const uint32_t base = s0 + (c % 3) * STAGE;
#pragma unroll
        for (int ks = 0; ks < 2; ks++) {
            const int chunk = ks * 2 + (lane >> 4);
            uint32_t ah[4][4], al[4][4];
#pragma unroll
            for (int mi = 0; mi < 4; mi++) {
                uint32_t ra = base + goff(wm*64 + mi*16 + rowoff, chunk);
                ldsm4(ra, ah[mi]);
                if (MODE == 0) ldsm4(ra + GT_BYTES, al[mi]);
            }
#pragma unroll
            for (int p = 0; p < 2; p++) {
                uint32_t bh[4], bl[4];
                uint32_t rb = base + BOFF + goff(wn*32 + p*16 + rowoff, chunk);
                ldsm4(rb, bh);
                ldsm4(rb + GT_BYTES, bl);
                // hh pass
#pragma unroll
                for (int mi = 0; mi < 4; mi++) mma_fp16(acc[mi][2*p],   ah[mi], bh[0], bh[2]);
#pragma unroll
                for (int mi = 0; mi < 4; mi++) mma_fp16(acc[mi][2*p+1], ah[mi], bh[1], bh[3]);
                // hl pass
#pragma unroll
                for (int mi = 0; mi < 4; mi++) mma_fp16(acc[mi][2*p],   ah[mi], bl[0], bl[2]);
#pragma unroll
                for (int mi = 0; mi < 4; mi++) mma_fp16(acc[mi][2*p+1], ah[mi], bl[1], bl[3]);
                // lh pass (MODE 0 only)
                if (MODE == 0) {
#pragma unroll
                    for (int mi = 0; mi < 4; mi++) mma_fp16(acc[mi][2*p],   al[mi], bh[0], bh[2]);
#pragma unroll
                    for (int mi = 0; mi < 4; mi++) mma_fp16(acc[mi][2*p+1], al[mi], bh[1], bh[3]);
                }
            }
        }
    }

    const int g = lane >> 2, tg2 = (lane & 3) * 2;
    if (MODE == 1) {
#pragma unroll
        for (int mi = 0; mi < 4; mi++) {
            int m = m0 + wm*64 + mi*16 + g;
#pragma unroll
            for (int ni = 0; ni < 4; ni++) {
                int n = n0 + wn*32 + ni*8 + tg2;
                float b0 = bc[n], b1 = bc[n+1];
                *(float2*)(out + (size_t)m * E_ + n) =
                    make_float2(acc[mi][ni][0] + b0, acc[mi][ni][1] + b1);
                *(float2*)(out + (size_t)(m+8) * E_ + n) =
                    make_float2(acc[mi][ni][2] + b0, acc[mi][ni][3] + b1);
            }
        }
        return;
    }

    // ---- MODE 0: transpose via smem, then per-row cumprod(cos) ----
    __syncthreads();
    float* st = (float*)sm;      // [128][132] fp32 = 67.6KB <= 96KB
#pragma unroll
    for (int mi = 0; mi < 4; mi++) {
        int r = wm*64 + mi*16 + g;
#pragma unroll
        for (int ni = 0; ni < 4; ni++) {
            int n = wn*32 + ni*8 + tg2;
            st[(size_t)r * 132 + n]     = acc[mi][ni][0];
            st[(size_t)r * 132 + n + 1] = acc[mi][ni][1];
            st[(size_t)(r+8) * 132 + n]     = acc[mi][ni][2];
            st[(size_t)(r+8) * 132 + n + 1] = acc[mi][ni][3];
        }
    }
    __syncthreads();

    {
        const int head = tid >> 7;          // 0..1 (two heads per 128-col tile)
        const int r = tid & 127;
        const int m = m0 + r;
        const int b = m >> 11, sI = m & (S_ - 1);
        const int hglob = blockIdx.x * 2 + head;
        const int bh = b * H_ + hglob;
        const int z = blockIdx.z;
        const float* src = st + (size_t)r * 132 + head * 64;

        float run = 1.f;
        float val[64];
#pragma unroll
        for (int d = 0; d < 64; d++) { run *= __cosf(src[d]); val[d] = run; }

        if (z == 0) {
            // Q: plain fp16, pre-scaled by 1/8
            __half hb[64];
#pragma unroll
            for (int d = 0; d < 64; d++) hb[d] = __float2half_rn(val[d] * 0.125f);
            __half* dh = g_qh + ((size_t)bh * S_ + sI) * 64;
#pragma unroll
            for (int j = 0; j < 8; j++) ((uint4*)dh)[j] = ((uint4*)hb)[j];
        } else if (z == 1) {
            __half hb[64], lb[64];
#pragma unroll
            for (int d = 0; d < 64; d++) split16(val[d], hb[d], lb[d]);
            __half* dh = g_kh + ((size_t)bh * S_ + sI) * 64;
            __half* dl = g_kl + ((size_t)bh * S_ + sI) * 64;
#pragma unroll
            for (int j = 0; j < 8; j++) {
                ((uint4*)dh)[j] = ((uint4*)hb)[j];
                ((uint4*)dl)[j] = ((uint4*)lb)[j];
            }
        } else {
#pragma unroll
            for (int d = 0; d < 64; d++) {
                __half h, l; split16(val[d], h, l);
                g_vth[((size_t)bh * 64 + d) * S_ + sI] = h;
                g_vtl[((size_t)bh * 64 + d) * S_ + sI] = l;
            }
        }
    }
}

#define GSMEM0 (3*4*GT_BYTES)   // 98304
#define GSMEM1 (3*3*GT_BYTES)   // 73728

// ---------------- HMMA flash attention ---------------------------------------
// grid (S/128, BH), 256 threads, 2 CTAs/SM. 3 KV stages + single barrier per
// tile. Q (plain fp16) staged through KV stage 2.
// QK: 2 products (qh*kh + qh*kl). PV: 2 products (p*vh + p*vl).
#define FROWB 144
#define FQT  (128*FROWB)     // 18432 (Q single)
#define FKT  (64*FROWB)      // 9216
#define FSTAGE (4*FKT)       // 36864 : Kh, Kl, Vh, Vl
#define FSMEM (3*FSTAGE)     // 110592 -> 2 CTAs/SM

__global__ __launch_bounds__(256, 2) void flash_kernel()
{
    extern __shared__ char sm[];
    const uint32_t s0 = smem_u32(sm);
    const uint32_t sQ = s0 + 2 * FSTAGE;   // Q lives in stage 2 until t==0 ldsm
    const int tid = threadIdx.x, lane = tid & 31, warp = tid >> 5;
    const int bh = blockIdx.y;
    const int q0 = blockIdx.x * 128;

    const __half* Qh = g_qh + (size_t)bh * S_ * 64;
    const __half* Kh = g_kh + (size_t)bh * S_ * 64;
    const __half* Kl = g_kl + (size_t)bh * S_ * 64;
    const __half* Vh = g_vth + (size_t)bh * 64 * S_;
    const __half* Vl = g_vtl + (size_t)bh * 64 * S_;

    auto loadKV = [&](int t) {
        const uint32_t base = s0 + (t % 3) * FSTAGE;
        const int kv0 = t * 64;
#pragma unroll
        for (int i = 0; i < 8; i++) {
            int gi = i * 256 + tid;         // 0..2047
            int tl = gi >> 9;               // 0..3 : Kh,Kl,Vh,Vl
            int r = (gi >> 3) & 63;
            int ch = gi & 7;
            const __half* src;
            if (tl == 0)      src = Kh + (size_t)(kv0 + r) * 64 + ch * 8;
            else if (tl == 1) src = Kl + (size_t)(kv0 + r) * 64 + ch * 8;
            else if (tl == 2) src = Vh + (size_t)r * S_ + kv0 + ch * 8;
            else              src = Vl + (size_t)r * S_ + kv0 + ch * 8;
            cp16(base + tl * FKT + r * FROWB + ch * 16, src);
        }
    };

    {
        // group 0: Q (into stage 2) + KV0; group 1: KV1
#pragma unroll
        for (int i = 0; i < 4; i++) {
            int gi = i * 256 + tid;         // 0..1023
            int r = gi >> 3;                // 0..127
            int ch = gi & 7;
            cp16(sQ + r * FROWB + ch * 16, Qh + (size_t)(q0 + r) * 64 + ch * 8);
        }
        loadKV(0); CP_COMMIT();
        loadKV(1); CP_COMMIT();
    }

    float o[8][4];
#pragma unroll
    for (int i = 0; i < 8; i++)
#pragma unroll
        for (int j = 0; j < 4; j++) o[i][j] = 0.f;
    float m0r = -1e30f, m1r = -1e30f, l0r = 0.f, l1r = 0.f;

    uint32_t qhf[4][4];
    const int rowoff = (lane & 7) + ((lane >> 3) & 1) * 8;

    for (int t = 0; t < 32; t++) {
        CP_WAIT1();              // group t done (t+1 may pend)
        __syncthreads();
        if (t == 0) {
            // one-time Q fragment load from stage 2; must finish CTA-wide
            // before loadKV(2) overwrites stage 2
#pragma unroll
            for (int ks = 0; ks < 4; ks++) {
                uint32_t ra = sQ + (warp*16 + rowoff) * FROWB + (ks*2 + (lane>>4)) * 16;
                ldsm4(ra, qhf[ks]);
            }
            __syncthreads();
        }
        if (t + 2 < 32) loadKV(t + 2);
        CP_COMMIT();

        const uint32_t kb = s0 + (t % 3) * FSTAGE;

        float s[8][4];
#pragma unroll
        for (int i = 0; i < 8; i++)
#pragma unroll
            for (int j = 0; j < 4; j++) s[i][j] = 0.f;

        // S = Q K^T, 2 products, interleaved over panel pairs
#pragma unroll
        for (int ks = 0; ks < 4; ks++) {
            const int chunk = ks * 2 + (lane >> 4);
#pragma unroll
            for (int pp = 0; pp < 2; pp++) {
                uint32_t kh[2][4], kl[2][4];
#pragma unroll
                for (int q = 0; q < 2; q++) {
                    uint32_t rb = kb + ((pp*2+q)*16 + rowoff) * FROWB + chunk * 16;
                    ldsm4(rb, kh[q]);
                    ldsm4(rb + FKT, kl[q]);
                }
#pragma unroll
                for (int q = 0; q < 2; q++) mma_fp16(s[2*(pp*2+q)],   qhf[ks], kh[q][0], kh[q][2]);
#pragma unroll
                for (int q = 0; q < 2; q++) mma_fp16(s[2*(pp*2+q)+1], qhf[ks], kh[q][1], kh[q][3]);
#pragma unroll
                for (int q = 0; q < 2; q++) mma_fp16(s[2*(pp*2+q)],   qhf[ks], kl[q][0], kl[q][2]);
#pragma unroll
                for (int q = 0; q < 2; q++) mma_fp16(s[2*(pp*2+q)+1], qhf[ks], kl[q][1], kl[q][3]);
            }
        }

        // online softmax (rows: g = lane>>2 and g+8; quad-shuffles xor 1,2)
        float rm0 = -1e30f, rm1 = -1e30f;
#pragma unroll
        for (int ni = 0; ni < 8; ni++) {
            rm0 = fmaxf(rm0, fmaxf(s[ni][0], s[ni][1]));
            rm1 = fmaxf(rm1, fmaxf(s[ni][2], s[ni][3]));
        }
        rm0 = fmaxf(rm0, __shfl_xor_sync(0xffffffffu, rm0, 1));
        rm0 = fmaxf(rm0, __shfl_xor_sync(0xffffffffu, rm0, 2));
        rm1 = fmaxf(rm1, __shfl_xor_sync(0xffffffffu, rm1, 1));
        rm1 = fmaxf(rm1, __shfl_xor_sync(0xffffffffu, rm1, 2));
        float mn0 = fmaxf(m0r, rm0), mn1 = fmaxf(m1r, rm1);
        float sc0 = __expf(m0r - mn0), sc1 = __expf(m1r - mn1);

        uint32_t pf[8][2];
        float rs0 = 0.f, rs1 = 0.f;
#pragma unroll
        for (int ni = 0; ni < 8; ni++) {
            float p0 = __expf(s[ni][0] - mn0);
            float p1 = __expf(s[ni][1] - mn0);
            float p2 = __expf(s[ni][2] - mn1);
            float p3 = __expf(s[ni][3] - mn1);
            rs0 += p0 + p1; rs1 += p2 + p3;
            pf[ni][0] = pack2(p0, p1);
            pf[ni][1] = pack2(p2, p3);
        }
        rs0 += __shfl_xor_sync(0xffffffffu, rs0, 1);
        rs0 += __shfl_xor_sync(0xffffffffu, rs0, 2);
        rs1 += __shfl_xor_sync(0xffffffffu, rs1, 1);
        rs1 += __shfl_xor_sync(0xffffffffu, rs1, 2);
        l0r = l0r * sc0 + rs0;  m0r = mn0;
        l1r = l1r * sc1 + rs1;  m1r = mn1;
#pragma unroll
        for (int ni = 0; ni < 8; ni++) {
            o[ni][0] *= sc0; o[ni][1] *= sc0;
            o[ni][2] *= sc1; o[ni][3] *= sc1;
        }

        // O += P V, 2 products, interleaved over panel pairs
        const uint32_t vb = kb + 2 * FKT;
#pragma unroll
        for (int ks = 0; ks < 4; ks++) {
            uint32_t a[4] = { pf[2*ks][0], pf[2*ks][1], pf[2*ks+1][0], pf[2*ks+1][1] };
            const int chunk = ks * 2 + (lane >> 4);
#pragma unroll
            for (int pp = 0; pp < 2; pp++) {
                uint32_t vh[2][4], vl[2][4];
#pragma unroll
                for (int q = 0; q < 2; q++) {
                    uint32_t rb = vb + ((pp*2+q)*16 + rowoff) * FROWB + chunk * 16;
                    ldsm4(rb, vh[q]);
                    ldsm4(rb + FKT, vl[q]);
                }
#pragma unroll
                for (int q = 0; q < 2; q++) mma_fp16(o[2*(pp*2+q)],   a, vh[q][0], vh[q][2]);
#pragma unroll
                for (int q = 0; q < 2; q++) mma_fp16(o[2*(pp*2+q)+1], a, vh[q][1], vh[q][3]);
#pragma unroll
                for (int q = 0; q < 2; q++) mma_fp16(o[2*(pp*2+q)],   a, vl[q][0], vl[q][2]);
#pragma unroll
                for (int q = 0; q < 2; q++) mma_fp16(o[2*(pp*2+q)+1], a, vl[q][1], vl[q][3]);
            }
        }
    }

    // epilogue: normalize, write plain fp16 attn out in [B,S,H,D] (= [M,E])
    const float inv0 = 1.f / l0r, inv1 = 1.f / l1r;
    const int g = lane >> 2, tg2 = (lane & 3) * 2;
    const int b = bh >> 4, h = bh & 15;
    const int sA = q0 + warp * 16 + g;
#pragma unroll
    for (int ni = 0; ni < 8; ni++) {
        int d = ni * 8 + tg2;
        size_t i0 = (((size_t)(b * S_ + sA)     * H_ + h) * D_ + d);
        size_t i1 = (((size_t)(b * S_ + sA + 8) * H_ + h) * D_ + d);
        *(__half2*)(g_oh + i0) = __floats2half2_rn(o[ni][0] * inv0, o[ni][1] * inv0);
        *(__half2*)(g_oh + i1) = __floats2half2_rn(o[ni][2] * inv1, o[ni][3] * inv1);
    }
}

// ---------------------------------------------------------------------------
extern "C" void kernel_launch(void* const* d_in, const int* in_sizes, int n_in,
                              void* d_out, int out_size)
{
    const float* x  = (const float*)d_in[0];
    const float* Wq = (const float*)d_in[1];
    const float* Wk = (const float*)d_in[2];
    const float* Wv = (const float*)d_in[3];
    const float* Wc = (const float*)d_in[4];
    const float* bc = (const float*)d_in[5];
    float* out = (float*)d_out;

    cudaFuncSetAttribute(gemm_kernel<0>, cudaFuncAttributeMaxDynamicSharedMemorySize, GSMEM0);
    cudaFuncSetAttribute(gemm_kernel<1>, cudaFuncAttributeMaxDynamicSharedMemorySize, GSMEM1);
    cudaFuncSetAttribute(flash_kernel,   cudaFuncAttributeMaxDynamicSharedMemorySize, FSMEM);

    // 1) fp32 -> fp16 hi/lo for x and all weights
    convert_kernel<<<dim3(4096, 5), 256>>>(x, Wq, Wk, Wv, Wc);

    // 2) QKV projections (3-product HMMA) + fused quantum cumprod(cos) epilogue
    gemm_kernel<0><<<dim3(E_/128, M_/128, 3), 256, GSMEM0>>>(nullptr, nullptr);

    // 3) flash attention (2-product QK, fp16 P, 2-product PV)
    flash_kernel<<<dim3(S_/128, BH_), 256, FSMEM>>>();

    // 4) output projection (2-product HMMA) + bias
    gemm_kernel<1><<<dim3(E_/128, M_/128, 1), 256, GSMEM1>>>(out, bc);
}

// round 8
// speedup vs baseline: 1.6841x; 1.2278x over previous
#include <cuda_runtime.h>
#include <cuda_fp16.h>
#include <stdint.h>
#include <math.h>

#define B_ 2
#define S_ 2048
#define E_ 1024
#define H_ 16
#define D_ 64
#define M_ (B_*S_)    // 4096
#define BH_ (B_*H_)   // 32

// ---------------- scratch (device globals; no allocation allowed) -------------
__device__ __half g_xh[(size_t)M_*E_];
__device__ __half g_xl[(size_t)M_*E_];
__device__ __half g_wh[(size_t)4*E_*E_];
__device__ __half g_wl[(size_t)4*E_*E_];
__device__ __half g_qh[(size_t)BH_*S_*D_];    // Q: plain fp16 (pre-scaled /8)
__device__ __half g_kh[(size_t)BH_*S_*D_];    // K: plain fp16
__device__ __half g_vth[(size_t)BH_*D_*S_];   // V^T: plain fp16 [bh][d][s]
__device__ __half g_oh[(size_t)M_*E_];        // attn out: plain fp16

// ---------------- helpers ----------------------------------------------------
__device__ __forceinline__ uint32_t smem_u32(const void* p) {
    uint32_t a;
    asm("{ .reg .u64 t; cvta.to.shared.u64 t, %1; cvt.u32.u64 %0, t; }" : "=r"(a) : "l"(p));
    return a;
}
__device__ __forceinline__ void cp16(uint32_t s, const void* g) {
    asm volatile("cp.async.cg.shared.global [%0], [%1], 16;" :: "r"(s), "l"(g));
}
#define CP_COMMIT() asm volatile("cp.async.commit_group;" ::: "memory")
#define CP_WAIT1()  asm volatile("cp.async.wait_group 1;" ::: "memory")
#define CP_WAIT2()  asm volatile("cp.async.wait_group 2;" ::: "memory")

__device__ __forceinline__ void ldsm4(uint32_t addr, uint32_t r[4]) {
    asm volatile("ldmatrix.sync.aligned.m8n8.x4.shared.b16 {%0,%1,%2,%3}, [%4];"
        : "=r"(r[0]), "=r"(r[1]), "=r"(r[2]), "=r"(r[3]) : "r"(addr));
}
__device__ __forceinline__ void mma_fp16(float* c, const uint32_t* a, uint32_t b0, uint32_t b1) {
    asm volatile(
        "mma.sync.aligned.m16n8k16.row.col.f32.f16.f16.f32 "
        "{%0,%1,%2,%3}, {%4,%5,%6,%7}, {%8,%9}, {%0,%1,%2,%3};"
        : "+f"(c[0]), "+f"(c[1]), "+f"(c[2]), "+f"(c[3])
        : "r"(a[0]), "r"(a[1]), "r"(a[2]), "r"(a[3]), "r"(b0), "r"(b1));
}
__device__ __forceinline__ uint32_t pack2(float x, float y) {
    __half2 h = __floats2half2_rn(x, y);
    return *(uint32_t*)&h;
}
__device__ __forceinline__ void split16(float v, __half& h, __half& l) {
    h = __float2half_rn(v);
    l = __float2half_rn(v - __half2float(h));
}

// ---------------- fp32 -> fp16 hi/lo conversion ------------------------------
__global__ __launch_bounds__(256) void convert_kernel(
    const float* __restrict__ x,  const float* __restrict__ Wq,
    const float* __restrict__ Wk, const float* __restrict__ Wv,
    const float* __restrict__ Wc)
{
    const int seg = blockIdx.y;
    const float* src; __half* hi; __half* lo; int n4;
    if (seg == 0) { src = x;  hi = g_xh; lo = g_xl; n4 = M_*E_/4; }
    else {
        src = (seg==1)?Wq:(seg==2)?Wk:(seg==3)?Wv:Wc;
        hi = g_wh + (size_t)(seg-1)*E_*E_;
        lo = g_wl + (size_t)(seg-1)*E_*E_;
        n4 = E_*E_/4;
    }
    int i = blockIdx.x * 256 + threadIdx.x;
    if (i >= n4) return;
    float4 v = ((const float4*)src)[i];
    __half h0,h1,h2,h3,l0,l1,l2,l3;
    split16(v.x,h0,l0); split16(v.y,h1,l1); split16(v.z,h2,l2); split16(v.w,h3,l3);
    ((__half2*)hi)[2*i]   = __halves2half2(h0, h1);
    ((__half2*)hi)[2*i+1] = __halves2half2(h2, h3);
    ((__half2*)lo)[2*i]   = __halves2half2(l0, l1);
    ((__half2*)lo)[2*i+1] = __halves2half2(l2, l3);
}

// ---------------- HMMA GEMM ---------------------------------------------------
// 128x128 tile, 8 warps (2x4), k-chunk 32, 3 stages, single barrier per chunk.
// MODE 0 (QKV): A=x hi/lo, B=W hi/lo, 3 products. Epilogue: quantum
//               cumprod(cos) -> q (fp16, /8), k (fp16), v^T (fp16).
// MODE 1 (out): A=attn-out fp16, B=Wc hi/lo, 2 products + bias.
#define GT_BYTES (128*64)         // 8192 (64B rows, XOR swizzle)

__device__ __forceinline__ uint32_t goff(int r, int ch) {
    return (uint32_t)(r * 64 + ((ch ^ ((r >> 1) & 3)) << 4));
}

template<int MODE>
__global__ __launch_bounds__(256, 2) void gemm_kernel(float* __restrict__ out,
                                                      const float* __restrict__ bc)
{
    constexpr int NT = (MODE == 0) ? 4 : 3;          // tiles per stage
    constexpr uint32_t STAGE = NT * GT_BYTES;

    extern __shared__ char sm[];
    const uint32_t s0 = smem_u32(sm);
    const int tid = threadIdx.x;
    const int lane = tid & 31, warp = tid >> 5;
    const int wm = warp >> 2, wn = warp & 3;
    const int m0 = blockIdx.y * 128, n0 = blockIdx.x * 128;

    const __half *Ah, *Al, *Bh2, *Bl2;
    if (MODE == 0) {
        Ah = g_xh; Al = g_xl;
        Bh2 = g_wh + (size_t)blockIdx.z * E_ * E_;
        Bl2 = g_wl + (size_t)blockIdx.z * E_ * E_;
    } else {
        Ah = g_oh; Al = nullptr;
        Bh2 = g_wh + (size_t)3 * E_ * E_;
        Bl2 = g_wl + (size_t)3 * E_ * E_;
    }

    float acc[4][4][4];
#pragma unroll
    for (int a = 0; a < 4; a++)
#pragma unroll
        for (int b = 0; b < 4; b++)
#pragma unroll
            for (int c = 0; c < 4; c++) acc[a][b][c] = 0.f;

    auto load = [&](int c) {
        const uint32_t base = s0 + (c % 3) * STAGE;
        const int k0 = c * 32;
#pragma unroll
        for (int i = 0; i < NT * 2; i++) {
            int g = i * 256 + tid;
            int t = g >> 9;                  // tile index
            int r = (g >> 2) & 127;
            int ch = g & 3;
            const __half* src; int row;
            if (MODE == 0) {
                src = (t == 0) ? Ah : (t == 1) ? Al : (t == 2) ? Bh2 : Bl2;
                row = ((t < 2) ? m0 : n0) + r;
            } else {
                src = (t == 0) ? Ah : (t == 1) ? Bh2 : Bl2;
                row = ((t == 0) ? m0 : n0) + r;
            }
            cp16(base + t * GT_BYTES + goff(r, ch),
                 src + (size_t)row * E_ + k0 + ch * 8);
        }
    };

    load(0); CP_COMMIT();
    load(1); CP_COMMIT();

    const int rowoff = (lane & 7) + ((lane >> 3) & 1) * 8;
    constexpr uint32_t BOFF = (MODE == 0) ? 2u * GT_BYTES : 1u * GT_BYTES;

    for (int c = 0; c < 32; c++) {
        CP_WAIT1();
        __syncthreads();
        if (c + 2 < 32) load(c + 2);
        CP_COMMIT();
        const uint32_t base = s0 + (c % 3) * STAGE;
#pragma unroll
        for (int ks = 0; ks < 2; ks++) {
            const int chunk = ks * 2 + (lane >> 4);
            uint32_t ah[4][4], al[4][4];
#pragma unroll
            for (int mi = 0; mi < 4; mi++) {
                uint32_t ra = base + goff(wm*64 + mi*16 + rowoff, chunk);
                ldsm4(ra, ah[mi]);
                if (MODE == 0) ldsm4(ra + GT_BYTES, al[mi]);
            }
#pragma unroll
            for (int p = 0; p < 2; p++) {
                uint32_t bh[4], bl[4];
                uint32_t rb = base + BOFF + goff(wn*32 + p*16 + rowoff, chunk);
                ldsm4(rb, bh);
                ldsm4(rb + GT_BYTES, bl);
                // hh pass
#pragma unroll
                for (int mi = 0; mi < 4; mi++) mma_fp16(acc[mi][2*p],   ah[mi], bh[0], bh[2]);
#pragma unroll
                for (int mi = 0; mi < 4; mi++) mma_fp16(acc[mi][2*p+1], ah[mi], bh[1], bh[3]);
                // hl pass
#pragma unroll
                for (int mi = 0; mi < 4; mi++) mma_fp16(acc[mi][2*p],   ah[mi], bl[0], bl[2]);
#pragma unroll
                for (int mi = 0; mi < 4; mi++) mma_fp16(acc[mi][2*p+1], ah[mi], bl[1], bl[3]);
                // lh pass (MODE 0 only)
                if (MODE == 0) {
#pragma unroll
                    for (int mi = 0; mi < 4; mi++) mma_fp16(acc[mi][2*p],   al[mi], bh[0], bh[2]);
#pragma unroll
                    for (int mi = 0; mi < 4; mi++) mma_fp16(acc[mi][2*p+1], al[mi], bh[1], bh[3]);
                }
            }
        }
    }

    const int g = lane >> 2, tg2 = (lane & 3) * 2;
    if (MODE == 1) {
#pragma unroll
        for (int mi = 0; mi < 4; mi++) {
            int m = m0 + wm*64 + mi*16 + g;
#pragma unroll
            for (int ni = 0; ni < 4; ni++) {
                int n = n0 + wn*32 + ni*8 + tg2;
                float b0 = bc[n], b1 = bc[n+1];
                *(float2*)(out + (size_t)m * E_ + n) =
                    make_float2(acc[mi][ni][0] + b0, acc[mi][ni][1] + b1);
                *(float2*)(out + (size_t)(m+8) * E_ + n) =
                    make_float2(acc[mi][ni][2] + b0, acc[mi][ni][3] + b1);
            }
        }
        return;
    }

    // ---- MODE 0: transpose via smem, then per-row cumprod(cos) ----
    __syncthreads();
    float* st = (float*)sm;      // [128][132] fp32 = 67.6KB <= 96KB
#pragma unroll
    for (int mi = 0; mi < 4; mi++) {
        int r = wm*64 + mi*16 + g;
#pragma unroll
        for (int ni = 0; ni < 4; ni++) {
            int n = wn*32 + ni*8 + tg2;
            st[(size_t)r * 132 + n]     = acc[mi][ni][0];
            st[(size_t)r * 132 + n + 1] = acc[mi][ni][1];
            st[(size_t)(r+8) * 132 + n]     = acc[mi][ni][2];
            st[(size_t)(r+8) * 132 + n + 1] = acc[mi][ni][3];
        }
    }
    __syncthreads();

    {
        const int head = tid >> 7;          // 0..1 (two heads per 128-col tile)
        const int r = tid & 127;
        const int m = m0 + r;
        const int b = m >> 11, sI = m & (S_ - 1);
        const int hglob = blockIdx.x * 2 + head;
        const int bh = b * H_ + hglob;
        const int z = blockIdx.z;
        const float* src = st + (size_t)r * 132 + head * 64;

        float run = 1.f;
        float val[64];
#pragma unroll
        for (int d = 0; d < 64; d++) { run *= __cosf(src[d]); val[d] = run; }

        if (z < 2) {
            const float sc = (z == 0) ? 0.125f : 1.0f;
            __half hb[64];
#pragma unroll
            for (int d = 0; d < 64; d++) hb[d] = __float2half_rn(val[d] * sc);
            __half* dh = (z == 0 ? g_qh : g_kh) + ((size_t)bh * S_ + sI) * 64;
#pragma unroll
            for (int j = 0; j < 8; j++) ((uint4*)dh)[j] = ((uint4*)hb)[j];
        } else {
#pragma unroll
            for (int d = 0; d < 64; d++)
                g_vth[((size_t)bh * 64 + d) * S_ + sI] = __float2half_rn(val[d]);
        }
    }
}

#define GSMEM0 (3*4*GT_BYTES)   // 98304
#define GSMEM1 (3*3*GT_BYTES)   // 73728

// ---------------- HMMA flash attention ---------------------------------------
// grid (S/128, BH), 256 threads, 2 CTAs/SM. Plain fp16 Q/K/V (fp32 accum).
// 4 KV stages, 3 in flight (wait_group 2), single barrier per tile.
// Q staged through stage 3 (dead after one-time ldsm at t==0).
#define FROWB 144
#define FKT  (64*FROWB)      // 9216
#define FSTAGE (2*FKT)       // 18432 : Kh, Vh
#define FSMEM (4*FSTAGE)     // 73728 -> 2 CTAs/SM

__global__ __launch_bounds__(256, 2) void flash_kernel()
{
    extern __shared__ char sm[];
    const uint32_t s0 = smem_u32(sm);
    const uint32_t sQ = s0 + 3 * FSTAGE;   // Q lives in stage 3 until t==0 ldsm
    const int tid = threadIdx.x, lane = tid & 31, warp = tid >> 5;
    const int bh = blockIdx.y;
    const int q0 = blockIdx.x * 128;

    const __half* Qh = g_qh + (size_t)bh * S_ * 64;
    const __half* Kh = g_kh + (size_t)bh * S_ * 64;
    const __half* Vh = g_vth + (size_t)bh * 64 * S_;

    auto loadKV = [&](int t) {
        const uint32_t base = s0 + (t & 3) * FSTAGE;
        const int kv0 = t * 64;
#pragma unroll
        for (int i = 0; i < 4; i++) {
            int gi = i * 256 + tid;         // 0..1023
            int tl = gi >> 9;               // 0..1 : Kh, Vh
            int r = (gi >> 3) & 63;
            int ch = gi & 7;
            const __half* src = (tl == 0)
                ? Kh + (size_t)(kv0 + r) * 64 + ch * 8
                : Vh + (size_t)r * S_ + kv0 + ch * 8;
            cp16(base + tl * FKT + r * FROWB + ch * 16, src);
        }
    };

    {
        // group 0: Q (into stage 3) + KV0; group 1: KV1; group 2: KV2
#pragma unroll
        for (int i = 0; i < 4; i++) {
            int gi = i * 256 + tid;         // 0..1023
            int r = gi >> 3;                // 0..127
            int ch = gi & 7;
            cp16(sQ + r * FROWB + ch * 16, Qh + (size_t)(q0 + r) * 64 + ch * 8);
        }
        loadKV(0); CP_COMMIT();
        loadKV(1); CP_COMMIT();
        loadKV(2); CP_COMMIT();
    }

    float o[8][4];
#pragma unroll
    for (int i = 0; i < 8; i++)
#pragma unroll
        for (int j = 0; j < 4; j++) o[i][j] = 0.f;
    float m0r = -1e30f, m1r = -1e30f, l0r = 0.f, l1r = 0.f;

    uint32_t qhf[4][4];
    const int rowoff = (lane & 7) + ((lane >> 3) & 1) * 8;

    for (int t = 0; t < 32; t++) {
        CP_WAIT2();              // groups <= t done (2 younger may pend)
        __syncthreads();
        if (t == 0) {
            // one-time Q fragment load from stage 3; must finish CTA-wide
            // before loadKV(3) overwrites it
#pragma unroll
            for (int ks = 0; ks < 4; ks++) {
                uint32_t ra = sQ + (warp*16 + rowoff) * FROWB + (ks*2 + (lane>>4)) * 16;
                ldsm4(ra, qhf[ks]);
            }
            __syncthreads();
        }
        if (t + 3 < 32) loadKV(t + 3);   // -> stage (t+3)&3 == (t-1)&3 : safe
        CP_COMMIT();

        const uint32_t kb = s0 + (t & 3) * FSTAGE;

        float s[8][4];
#pragma unroll
        for (int i = 0; i < 8; i++)
#pragma unroll
            for (int j = 0; j < 4; j++) s[i][j] = 0.f;

        // S = Q K^T (plain fp16), interleaved over panel pairs
#pragma unroll
        for (int ks = 0; ks < 4; ks++) {
            const int chunk = ks * 2 + (lane >> 4);
#pragma unroll
            for (int pp = 0; pp < 2; pp++) {
                uint32_t kh[2][4];
#pragma unroll
                for (int q = 0; q < 2; q++)
                    ldsm4(kb + ((pp*2+q)*16 + rowoff) * FROWB + chunk * 16, kh[q]);
#pragma unroll
                for (int q = 0; q < 2; q++) mma_fp16(s[2*(pp*2+q)],   qhf[ks], kh[q][0], kh[q][2]);
#pragma unroll
                for (int q = 0; q < 2; q++) mma_fp16(s[2*(pp*2+q)+1], qhf[ks], kh[q][1], kh[q][3]);
            }
        }

        // online softmax (rows: g = lane>>2 and g+8; quad-shuffles xor 1,2)
        float rm0 = -1e30f, rm1 = -1e30f;
#pragma unroll
        for (int ni = 0; ni < 8; ni++) {
            rm0 = fmaxf(rm0, fmaxf(s[ni][0], s[ni][1]));
            rm1 = fmaxf(rm1, fmaxf(s[ni][2], s[ni][3]));
        }
        rm0 = fmaxf(rm0, __shfl_xor_sync(0xffffffffu, rm0, 1));
        rm0 = fmaxf(rm0, __shfl_xor_sync(0xffffffffu, rm0, 2));
        rm1 = fmaxf(rm1, __shfl_xor_sync(0xffffffffu, rm1, 1));
        rm1 = fmaxf(rm1, __shfl_xor_sync(0xffffffffu, rm1, 2));
        float mn0 = fmaxf(m0r, rm0), mn1 = fmaxf(m1r, rm1);
        float sc0 = __expf(m0r - mn0), sc1 = __expf(m1r - mn1);

        uint32_t pf[8][2];
        float rs0 = 0.f, rs1 = 0.f;
#pragma unroll
        for (int ni = 0; ni < 8; ni++) {
            float p0 = __expf(s[ni][0] - mn0);
            float p1 = __expf(s[ni][1] - mn0);
            float p2 = __expf(s[ni][2] - mn1);
            float p3 = __expf(s[ni][3] - mn1);
            rs0 += p0 + p1; rs1 += p2 + p3;
            pf[ni][0] = pack2(p0, p1);
            pf[ni][1] = pack2(p2, p3);
        }
        rs0 += __shfl_xor_sync(0xffffffffu, rs0, 1);
        rs0 += __shfl_xor_sync(0xffffffffu, rs0, 2);
        rs1 += __shfl_xor_sync(0xffffffffu, rs1, 1);
        rs1 += __shfl_xor_sync(0xffffffffu, rs1, 2);
        l0r = l0r * sc0 + rs0;  m0r = mn0;
        l1r = l1r * sc1 + rs1;  m1r = mn1;
#pragma unroll
        for (int ni = 0; ni < 8; ni++) {
            o[ni][0] *= sc0; o[ni][1] *= sc0;
            o[ni][2] *= sc1; o[ni][3] *= sc1;
        }

        // O += P V (plain fp16 V), interleaved over panel pairs
        const uint32_t vb = kb + FKT;
#pragma unroll
        for (int ks = 0; ks < 4; ks++) {
            uint32_t a[4] = { pf[2*ks][0], pf[2*ks][1], pf[2*ks+1][0], pf[2*ks+1][1] };
            const int chunk = ks * 2 + (lane >> 4);
#pragma unroll
            for (int pp = 0; pp < 2; pp++) {
                uint32_t vh[2][4];
#pragma unroll
                for (int q = 0; q < 2; q++)
                    ldsm4(vb + ((pp*2+q)*16 + rowoff) * FROWB + chunk * 16, vh[q]);
#pragma unroll
                for (int q = 0; q < 2; q++) mma_fp16(o[2*(pp*2+q)],   a, vh[q][0], vh[q][2]);
#pragma unroll
                for (int q = 0; q < 2; q++) mma_fp16(o[2*(pp*2+q)+1], a, vh[q][1], vh[q][3]);
            }
        }
    }

    // epilogue: normalize, write plain fp16 attn out in [B,S,H,D] (= [M,E])
    const float inv0 = 1.f / l0r, inv1 = 1.f / l1r;
    const int g = lane >> 2, tg2 = (lane & 3) * 2;
    const int b = bh >> 4, h = bh & 15;
    const int sA = q0 + warp * 16 + g;
#pragma unroll
    for (int ni = 0; ni < 8; ni++) {
        int d = ni * 8 + tg2;
        size_t i0 = (((size_t)(b * S_ + sA)     * H_ + h) * D_ + d);
        size_t i1 = (((size_t)(b * S_ + sA + 8) * H_ + h) * D_ + d);
        *(__half2*)(g_oh + i0) = __floats2half2_rn(o[ni][0] * inv0, o[ni][1] * inv0);
        *(__half2*)(g_oh + i1) = __floats2half2_rn(o[ni][2] * inv1, o[ni][3] * inv1);
    }
}

// ---------------------------------------------------------------------------
extern "C" void kernel_launch(void* const* d_in, const int* in_sizes, int n_in,
                              void* d_out, int out_size)
{
    const float* x  = (const float*)d_in[0];
    const float* Wq = (const float*)d_in[1];
    const float* Wk = (const float*)d_in[2];
    const float* Wv = (const float*)d_in[3];
    const float* Wc = (const float*)d_in[4];
    const float* bc = (const float*)d_in[5];
    float* out = (float*)d_out;

    cudaFuncSetAttribute(gemm_kernel<0>, cudaFuncAttributeMaxDynamicSharedMemorySize, GSMEM0);
    cudaFuncSetAttribute(gemm_kernel<1>, cudaFuncAttributeMaxDynamicSharedMemorySize, GSMEM1);
    cudaFuncSetAttribute(flash_kernel,   cudaFuncAttributeMaxDynamicSharedMemorySize, FSMEM);

    // 1) fp32 -> fp16 hi/lo for x and all weights
    convert_kernel<<<dim3(4096, 5), 256>>>(x, Wq, Wk, Wv, Wc);

    // 2) QKV projections (3-product HMMA) + fused quantum cumprod(cos) epilogue
    gemm_kernel<0><<<dim3(E_/128, M_/128, 3), 256, GSMEM0>>>(nullptr, nullptr);

    // 3) flash attention (plain fp16 Q/K/V, fp32 accum)
    flash_kernel<<<dim3(S_/128, BH_), 256, FSMEM>>>();

    // 4) output projection (2-product HMMA) + bias
    gemm_kernel<1><<<dim3(E_/128, M_/128, 1), 256, GSMEM1>>>(out, bc);
}

// round 9
// speedup vs baseline: 1.7802x; 1.0571x over previous
#include <cuda_runtime.h>
#include <cuda_fp16.h>
#include <stdint.h>
#include <math.h>

#define B_ 2
#define S_ 2048
#define E_ 1024
#define H_ 16
#define D_ 64
#define M_ (B_*S_)    // 4096
#define BH_ (B_*H_)   // 32

// ---------------- scratch (device globals; no allocation allowed) -------------
__device__ __half g_xh[(size_t)M_*E_];
__device__ __half g_xl[(size_t)M_*E_];
__device__ __half g_wh[(size_t)4*E_*E_];
__device__ __half g_wl[(size_t)4*E_*E_];
__device__ __half g_qh[(size_t)BH_*S_*D_];    // Q: fp16, pre-scaled by log2e/8
__device__ __half g_kh[(size_t)BH_*S_*D_];    // K: plain fp16
__device__ __half g_vth[(size_t)BH_*D_*S_];   // V^T: plain fp16 [bh][d][s]
__device__ __half g_oh[(size_t)M_*E_];        // attn out: plain fp16

// ---------------- helpers ----------------------------------------------------
__device__ __forceinline__ uint32_t smem_u32(const void* p) {
    uint32_t a;
    asm("{ .reg .u64 t; cvta.to.shared.u64 t, %1; cvt.u32.u64 %0, t; }" : "=r"(a) : "l"(p));
    return a;
}
__device__ __forceinline__ void cp16(uint32_t s, const void* g) {
    asm volatile("cp.async.cg.shared.global [%0], [%1], 16;" :: "r"(s), "l"(g));
}
#define CP_COMMIT() asm volatile("cp.async.commit_group;" ::: "memory")
#define CP_WAIT1()  asm volatile("cp.async.wait_group 1;" ::: "memory")
#define CP_WAIT2()  asm volatile("cp.async.wait_group 2;" ::: "memory")

__device__ __forceinline__ void ldsm4(uint32_t addr, uint32_t r[4]) {
    asm volatile("ldmatrix.sync.aligned.m8n8.x4.shared.b16 {%0,%1,%2,%3}, [%4];"
        : "=r"(r[0]), "=r"(r[1]), "=r"(r[2]), "=r"(r[3]) : "r"(addr));
}
__device__ __forceinline__ void mma_fp16(float* c, const uint32_t* a, uint32_t b0, uint32_t b1) {
    asm volatile(
        "mma.sync.aligned.m16n8k16.row.col.f32.f16.f16.f32 "
        "{%0,%1,%2,%3}, {%4,%5,%6,%7}, {%8,%9}, {%0,%1,%2,%3};"
        : "+f"(c[0]), "+f"(c[1]), "+f"(c[2]), "+f"(c[3])
        : "r"(a[0]), "r"(a[1]), "r"(a[2]), "r"(a[3]), "r"(b0), "r"(b1));
}
__device__ __forceinline__ float fexp2(float x) {
    float r;
    asm("ex2.approx.f32 %0, %1;" : "=f"(r) : "f"(x));
    return r;
}
__device__ __forceinline__ uint32_t pack2(float x, float y) {
    __half2 h = __floats2half2_rn(x, y);
    return *(uint32_t*)&h;
}
__device__ __forceinline__ void split16(float v, __half& h, __half& l) {
    h = __float2half_rn(v);
    l = __float2half_rn(v - __half2float(h));
}

// ---------------- fp32 -> fp16 hi/lo conversion ------------------------------
__global__ __launch_bounds__(256) void convert_kernel(
    const float* __restrict__ x,  const float* __restrict__ Wq,
    const float* __restrict__ Wk, const float* __restrict__ Wv,
    const float* __restrict__ Wc)
{
    const int seg = blockIdx.y;
    const float* src; __half* hi; __half* lo; int n4;
    if (seg == 0) { src = x;  hi = g_xh; lo = g_xl; n4 = M_*E_/4; }
    else {
        src = (seg==1)?Wq:(seg==2)?Wk:(seg==3)?Wv:Wc;
        hi = g_wh + (size_t)(seg-1)*E_*E_;
        lo = g_wl + (size_t)(seg-1)*E_*E_;
        n4 = E_*E_/4;
    }
    int i = blockIdx.x * 256 + threadIdx.x;
    if (i >= n4) return;
    float4 v = ((const float4*)src)[i];
    __half h0,h1,h2,h3,l0,l1,l2,l3;
    split16(v.x,h0,l0); split16(v.y,h1,l1); split16(v.z,h2,l2); split16(v.w,h3,l3);
    ((__half2*)hi)[2*i]   = __halves2half2(h0, h1);
    ((__half2*)hi)[2*i+1] = __halves2half2(h2, h3);
    ((__half2*)lo)[2*i]   = __halves2half2(l0, l1);
    ((__half2*)lo)[2*i+1] = __halves2half2(l2, l3);
}

// ---------------- HMMA GEMM ---------------------------------------------------
// 128x128 tile, 8 warps (2x4), k-chunk 32, 3 stages, single barrier per chunk.
// MODE 0 (QKV): A=x hi/lo, B=W hi/lo, 3 products. Epilogue: quantum
//               cumprod(cos) -> q (fp16, *log2e/8), k (fp16), v^T (fp16).
// MODE 1 (out): A=attn-out fp16, B=Wc hi/lo, 2 products + bias.
#define GT_BYTES (128*64)         // 8192 (64B rows, XOR swizzle)

__device__ __forceinline__ uint32_t goff(int r, int ch) {
    return (uint32_t)(r * 64 + ((ch ^ ((r >> 1) & 3)) << 4));
}

template<int MODE>
__global__ __launch_bounds__(256, 2) void gemm_kernel(float* __restrict__ out,
                                                      const float* __restrict__ bc)
{
    constexpr int NT = (MODE == 0) ? 4 : 3;          // tiles per stage
    constexpr uint32_t STAGE = NT * GT_BYTES;

    extern __shared__ char sm[];
    const uint32_t s0 = smem_u32(sm);
    const int tid = threadIdx.x;
    const int lane = tid & 31, warp = tid >> 5;
    const int wm = warp >> 2, wn = warp & 3;
    const int m0 = blockIdx.y * 128, n0 = blockIdx.x * 128;

    const __half *Ah, *Al, *Bh2, *Bl2;
    if (MODE == 0) {
        Ah = g_xh; Al = g_xl;
        Bh2 = g_wh + (size_t)blockIdx.z * E_ * E_;
        Bl2 = g_wl + (size_t)blockIdx.z * E_ * E_;
    } else {
        Ah = g_oh; Al = nullptr;
        Bh2 = g_wh + (size_t)3 * E_ * E_;
        Bl2 = g_wl + (size_t)3 * E_ * E_;
    }

    float acc[4][4][4];
#pragma unroll
    for (int a = 0; a < 4; a++)
#pragma unroll
        for (int b = 0; b < 4; b++)
#pragma unroll
            for (int c = 0; c < 4; c++) acc[a][b][c] = 0.f;

    auto load = [&](int c) {
        const uint32_t base = s0 + (c % 3) * STAGE;
        const int k0 = c * 32;
#pragma unroll
        for (int i = 0; i < NT * 2; i++) {
            int g = i * 256 + tid;
            int t = g >> 9;                  // tile index
            int r = (g >> 2) & 127;
            int ch = g & 3;
            const __half* src; int row;
            if (MODE == 0) {
                src = (t == 0) ? Ah : (t == 1) ? Al : (t == 2) ? Bh2 : Bl2;
                row = ((t < 2) ? m0 : n0) + r;
            } else {
                src = (t == 0) ? Ah : (t == 1) ? Bh2 : Bl2;
                row = ((t == 0) ? m0 : n0) + r;
            }
            cp16(base + t * GT_BYTES + goff(r, ch),
                 src + (size_t)row * E_ + k0 + ch * 8);
        }
    };

    load(0); CP_COMMIT();
    load(1); CP_COMMIT();

    const int rowoff = (lane & 7) + ((lane >> 3) & 1) * 8;
    constexpr uint32_t BOFF = (MODE == 0) ? 2u * GT_BYTES : 1u * GT_BYTES;

    for (int c = 0; c < 32; c++) {
        CP_WAIT1();
        __syncthreads();
        if (c + 2 < 32) load(c + 2);
        CP_COMMIT();
        const uint32_t base = s0 + (c % 3) * STAGE;
#pragma unroll
        for (int ks = 0; ks < 2; ks++) {
            const int chunk = ks * 2 + (lane >> 4);
            uint32_t ah[4][4], al[4][4];
#pragma unroll
            for (int mi = 0; mi < 4; mi++) {
                uint32_t ra = base + goff(wm*64 + mi*16 + rowoff, chunk);
                ldsm4(ra, ah[mi]);
                if (MODE == 0) ldsm4(ra + GT_BYTES, al[mi]);
            }
#pragma unroll
            for (int p = 0; p < 2; p++) {
                uint32_t bh[4], bl[4];
                uint32_t rb = base + BOFF + goff(wn*32 + p*16 + rowoff, chunk);
                ldsm4(rb, bh);
                ldsm4(rb + GT_BYTES, bl);
                // hh pass
#pragma unroll
                for (int mi = 0; mi < 4; mi++) mma_fp16(acc[mi][2*p],   ah[mi], bh[0], bh[2]);
#pragma unroll
                for (int mi = 0; mi < 4; mi++) mma_fp16(acc[mi][2*p+1], ah[mi], bh[1], bh[3]);
                // hl pass
#pragma unroll
                for (int mi = 0; mi < 4; mi++) mma_fp16(acc[mi][2*p],   ah[mi], bl[0], bl[2]);
#pragma unroll
                for (int mi = 0; mi < 4; mi++) mma_fp16(acc[mi][2*p+1], ah[mi], bl[1], bl[3]);
                // lh pass (MODE 0 only)
                if (MODE == 0) {
#pragma unroll
                    for (int mi = 0; mi < 4; mi++) mma_fp16(acc[mi][2*p],   al[mi], bh[0], bh[2]);
#pragma unroll
                    for (int mi = 0; mi < 4; mi++) mma_fp16(acc[mi][2*p+1], al[mi], bh[1], bh[3]);
                }
            }
        }
    }

    const int g = lane >> 2, tg2 = (lane & 3) * 2;
    if (MODE == 1) {
#pragma unroll
        for (int mi = 0; mi < 4; mi++) {
            int m = m0 + wm*64 + mi*16 + g;
#pragma unroll
            for (int ni = 0; ni < 4; ni++) {
                int n = n0 + wn*32 + ni*8 + tg2;
                float b0 = bc[n], b1 = bc[n+1];
                *(float2*)(out + (size_t)m * E_ + n) =
                    make_float2(acc[mi][ni][0] + b0, acc[mi][ni][1] + b1);
                *(float2*)(out + (size_t)(m+8) * E_ + n) =
                    make_float2(acc[mi][ni][2] + b0, acc[mi][ni][3] + b1);
            }
        }
        return;
    }

    // ---- MODE 0: transpose via smem, then per-row cumprod(cos) ----
    __syncthreads();
    float* st = (float*)sm;      // [128][132] fp32 = 67.6KB <= 96KB
#pragma unroll
    for (int mi = 0; mi < 4; mi++) {
        int r = wm*64 + mi*16 + g;
#pragma unroll
        for (int ni = 0; ni < 4; ni++) {
            int n = wn*32 + ni*8 + tg2;
            st[(size_t)r * 132 + n]     = acc[mi][ni][0];
            st[(size_t)r * 132 + n + 1] = acc[mi][ni][1];
            st[(size_t)(r+8) * 132 + n]     = acc[mi][ni][2];
            st[(size_t)(r+8) * 132 + n + 1] = acc[mi][ni][3];
        }
    }
    __syncthreads();

    {
        const int head = tid >> 7;          // 0..1 (two heads per 128-col tile)
        const int r = tid & 127;
        const int m = m0 + r;
        const int b = m >> 11, sI = m & (S_ - 1);
        const int hglob = blockIdx.x * 2 + head;
        const int bh = b * H_ + hglob;
        const int z = blockIdx.z;
        const float* src = st + (size_t)r * 132 + head * 64;

        float run = 1.f;
        float val[64];
#pragma unroll
        for (int d = 0; d < 64; d++) { run *= __cosf(src[d]); val[d] = run; }

        if (z < 2) {
            // Q pre-scale folds softmax 1/sqrt(D) AND log2(e) for ex2-softmax
            const float sc = (z == 0) ? 0.18033688f : 1.0f;   // log2e/8
            __half hb[64];
#pragma unroll
            for (int d = 0; d < 64; d++) hb[d] = __float2half_rn(val[d] * sc);
            __half* dh = (z == 0 ? g_qh : g_kh) + ((size_t)bh * S_ + sI) * 64;
#pragma unroll
            for (int j = 0; j < 8; j++) ((uint4*)dh)[j] = ((uint4*)hb)[j];
        } else {
#pragma unroll
            for (int d = 0; d < 64; d++)
                g_vth[((size_t)bh * 64 + d) * S_ + sI] = __float2half_rn(val[d]);
        }
    }
}

#define GSMEM0 (3*4*GT_BYTES)   // 98304
#define GSMEM1 (3*3*GT_BYTES)   // 73728

// ---------------- HMMA flash attention ---------------------------------------
// grid (S/128, BH), 256 threads, 2 CTAs/SM. Plain fp16 Q/K/V (fp32 accum).
// NO online max: scores are provably bounded (|q.k| <= 64 since q,k are
// cumprod(cos) in [-1,1]) -> ex2 arg <= 11.6, p <= 3020 (fp16-safe),
// l <= 6.2e6 (fp32-safe). l is reduced once in the epilogue.
// 4 KV stages, 3 in flight (wait_group 2), single barrier per tile.
#define FROWB 144
#define FKT  (64*FROWB)      // 9216
#define FSTAGE (2*FKT)       // 18432 : Kh, Vh
#define FSMEM (4*FSTAGE)     // 73728 -> 2 CTAs/SM

__global__ __launch_bounds__(256, 2) void flash_kernel()
{
    extern __shared__ char sm[];
    const uint32_t s0 = smem_u32(sm);
    const uint32_t sQ = s0 + 3 * FSTAGE;   // Q lives in stage 3 until t==0 ldsm
    const int tid = threadIdx.x, lane = tid & 31, warp = tid >> 5;
    const int bh = blockIdx.y;
    const int q0 = blockIdx.x * 128;

    const __half* Qh = g_qh + (size_t)bh * S_ * 64;
    const __half* Kh = g_kh + (size_t)bh * S_ * 64;
    const __half* Vh = g_vth + (size_t)bh * 64 * S_;

    auto loadKV = [&](int t) {
        const uint32_t base = s0 + (t & 3) * FSTAGE;
        const int kv0 = t * 64;
#pragma unroll
        for (int i = 0; i < 4; i++) {
            int gi = i * 256 + tid;         // 0..1023
            int tl = gi >> 9;               // 0..1 : Kh, Vh
            int r = (gi >> 3) & 63;
            int ch = gi & 7;
            const __half* src = (tl == 0)
                ? Kh + (size_t)(kv0 + r) * 64 + ch * 8
                : Vh + (size_t)r * S_ + kv0 + ch * 8;
            cp16(base + tl * FKT + r * FROWB + ch * 16, src);
        }
    };

    {
        // group 0: Q (into stage 3) + KV0; group 1: KV1; group 2: KV2
#pragma unroll
        for (int i = 0; i < 4; i++) {
            int gi = i * 256 + tid;         // 0..1023
            int r = gi >> 3;                // 0..127
            int ch = gi & 7;
            cp16(sQ + r * FROWB + ch * 16, Qh + (size_t)(q0 + r) * 64 + ch * 8);
        }
        loadKV(0); CP_COMMIT();
        loadKV(1); CP_COMMIT();
        loadKV(2); CP_COMMIT();
    }

    float o[8][4];
#pragma unroll
    for (int i = 0; i < 8; i++)
#pragma unroll
        for (int j = 0; j < 4; j++) o[i][j] = 0.f;
    float l0r = 0.f, l1r = 0.f;

    uint32_t qhf[4][4];
    const int rowoff = (lane & 7) + ((lane >> 3) & 1) * 8;

    for (int t = 0; t < 32; t++) {
        CP_WAIT2();              // groups <= t done (2 younger may pend)
        __syncthreads();
        if (t == 0) {
            // one-time Q fragment load from stage 3; must finish CTA-wide
            // before loadKV(3) overwrites it
#pragma unroll
            for (int ks = 0; ks < 4; ks++) {
                uint32_t ra = sQ + (warp*16 + rowoff) * FROWB + (ks*2 + (lane>>4)) * 16;
                ldsm4(ra, qhf[ks]);
            }
            __syncthreads();
        }
        if (t + 3 < 32) loadKV(t + 3);   // -> stage (t+3)&3 == (t-1)&3 : safe
        CP_COMMIT();

        const uint32_t kb = s0 + (t & 3) * FSTAGE;

        float s[8][4];
#pragma unroll
        for (int i = 0; i < 8; i++)
#pragma unroll
            for (int j = 0; j < 4; j++) s[i][j] = 0.f;

        // S = Q K^T (Q pre-scaled by log2e/8), interleaved over panel pairs
#pragma unroll
        for (int ks = 0; ks < 4; ks++) {
            const int chunk = ks * 2 + (lane >> 4);
#pragma unroll
            for (int pp = 0; pp < 2; pp++) {
                uint32_t kh[2][4];
#pragma unroll
                for (int q = 0; q < 2; q++)
                    ldsm4(kb + ((pp*2+q)*16 + rowoff) * FROWB + chunk * 16, kh[q]);
#pragma unroll
                for (int q = 0; q < 2; q++) mma_fp16(s[2*(pp*2+q)],   qhf[ks], kh[q][0], kh[q][2]);
#pragma unroll
                for (int q = 0; q < 2; q++) mma_fp16(s[2*(pp*2+q)+1], qhf[ks], kh[q][1], kh[q][3]);
            }
        }

        // softmax numerator: p = 2^s (no max subtraction; bounded), local l accum
        uint32_t pf[8][2];
#pragma unroll
        for (int ni = 0; ni < 8; ni++) {
            float p0 = fexp2(s[ni][0]);
            float p1 = fexp2(s[ni][1]);
            float p2 = fexp2(s[ni][2]);
            float p3 = fexp2(s[ni][3]);
            l0r += p0 + p1; l1r += p2 + p3;
            pf[ni][0] = pack2(p0, p1);
            pf[ni][1] = pack2(p2, p3);
        }

        // O += P V (plain fp16 V), interleaved over panel pairs
        const uint32_t vb = kb + FKT;
#pragma unroll
        for (int ks = 0; ks < 4; ks++) {
            uint32_t a[4] = { pf[2*ks][0], pf[2*ks][1], pf[2*ks+1][0], pf[2*ks+1][1] };
            const int chunk = ks * 2 + (lane >> 4);
#pragma unroll
            for (int pp = 0; pp < 2; pp++) {
                uint32_t vh[2][4];
#pragma unroll
                for (int q = 0; q < 2; q++)
                    ldsm4(vb + ((pp*2+q)*16 + rowoff) * FROWB + chunk * 16, vh[q]);
#pragma unroll
                for (int q = 0; q < 2; q++) mma_fp16(o[2*(pp*2+q)],   a, vh[q][0], vh[q][2]);
#pragma unroll
                for (int q = 0; q < 2; q++) mma_fp16(o[2*(pp*2+q)+1], a, vh[q][1], vh[q][3]);
            }
        }
    }

    // epilogue: reduce l across the quad (cols of a row live in lanes xor 1,2),
    // normalize, write plain fp16 attn out in [B,S,H,D] (= [M,E])
    l0r += __shfl_xor_sync(0xffffffffu, l0r, 1);
    l0r += __shfl_xor_sync(0xffffffffu, l0r, 2);
    l1r += __shfl_xor_sync(0xffffffffu, l1r, 1);
    l1r += __shfl_xor_sync(0xffffffffu, l1r, 2);
    const float inv0 = 1.f / l0r, inv1 = 1.f / l1r;
    const int g = lane >> 2, tg2 = (lane & 3) * 2;
    const int b = bh >> 4, h = bh & 15;
    const int sA = q0 + warp * 16 + g;
#pragma unroll
    for (int ni = 0; ni < 8; ni++) {
        int d = ni * 8 + tg2;
        size_t i0 = (((size_t)(b * S_ + sA)     * H_ + h) * D_ + d);
        size_t i1 = (((size_t)(b * S_ + sA + 8) * H_ + h) * D_ + d);
        *(__half2*)(g_oh + i0) = __floats2half2_rn(o[ni][0] * inv0, o[ni][1] * inv0);
        *(__half2*)(g_oh + i1) = __floats2half2_rn(o[ni][2] * inv1, o[ni][3] * inv1);
    }
}

// ---------------------------------------------------------------------------
extern "C" void kernel_launch(void* const* d_in, const int* in_sizes, int n_in,
                              void* d_out, int out_size)
{
    const float* x  = (const float*)d_in[0];
    const float* Wq = (const float*)d_in[1];
    const float* Wk = (const float*)d_in[2];
    const float* Wv = (const float*)d_in[3];
    const float* Wc = (const float*)d_in[4];
    const float* bc = (const float*)d_in[5];
    float* out = (float*)d_out;

    cudaFuncSetAttribute(gemm_kernel<0>, cudaFuncAttributeMaxDynamicSharedMemorySize, GSMEM0);
    cudaFuncSetAttribute(gemm_kernel<1>, cudaFuncAttributeMaxDynamicSharedMemorySize, GSMEM1);
    cudaFuncSetAttribute(flash_kernel,   cudaFuncAttributeMaxDynamicSharedMemorySize, FSMEM);

    // 1) fp32 -> fp16 hi/lo for x and all weights
    convert_kernel<<<dim3(4096, 5), 256>>>(x, Wq, Wk, Wv, Wc);

    // 2) QKV projections (3-product HMMA) + fused quantum cumprod(cos) epilogue
    gemm_kernel<0><<<dim3(E_/128, M_/128, 3), 256, GSMEM0>>>(nullptr, nullptr);

    // 3) flash attention (fp16 Q/K/V, ex2 softmax without max-tracking)
    flash_kernel<<<dim3(S_/128, BH_), 256, FSMEM>>>();

    // 4) output projection (2-product HMMA) + bias
    gemm_kernel<1><<<dim3(E_/128, M_/128, 1), 256, GSMEM1>>>(out, bc);
}

// round 10
// speedup vs baseline: 2.1321x; 1.1977x over previous
#include <cuda_runtime.h>
#include <cuda_fp16.h>
#include <stdint.h>
#include <math.h>

#define B_ 2
#define S_ 2048
#define E_ 1024
#define H_ 16
#define D_ 64
#define M_ (B_*S_)    // 4096
#define BH_ (B_*H_)   // 32

// ---------------- scratch (device globals; no allocation allowed) -------------
__device__ __half g_xh[(size_t)M_*E_];
__device__ __half g_xl[(size_t)M_*E_];
__device__ __half g_wh[(size_t)4*E_*E_];
__device__ __half g_wl[(size_t)4*E_*E_];
__device__ __half g_qh[(size_t)BH_*S_*D_];    // Q: fp16, pre-scaled by log2e/8
__device__ __half g_kh[(size_t)BH_*S_*D_];    // K: plain fp16
__device__ __half g_vth[(size_t)BH_*D_*S_];   // V^T: plain fp16 [bh][d][s]
__device__ __half g_oh[(size_t)M_*E_];        // attn out: plain fp16

// ---------------- helpers ----------------------------------------------------
__device__ __forceinline__ uint32_t smem_u32(const void* p) {
    uint32_t a;
    asm("{ .reg .u64 t; cvta.to.shared.u64 t, %1; cvt.u32.u64 %0, t; }" : "=r"(a) : "l"(p));
    return a;
}
__device__ __forceinline__ void cp16(uint32_t s, const void* g) {
    asm volatile("cp.async.cg.shared.global [%0], [%1], 16;" :: "r"(s), "l"(g));
}
#define CP_COMMIT() asm volatile("cp.async.commit_group;" ::: "memory")
#define CP_WAIT2()  asm volatile("cp.async.wait_group 2;" ::: "memory")

__device__ __forceinline__ void ldsm4(uint32_t addr, uint32_t r[4]) {
    asm volatile("ldmatrix.sync.aligned.m8n8.x4.shared.b16 {%0,%1,%2,%3}, [%4];"
        : "=r"(r[0]), "=r"(r[1]), "=r"(r[2]), "=r"(r[3]) : "r"(addr));
}
__device__ __forceinline__ void mma_fp16(float* c, const uint32_t* a, uint32_t b0, uint32_t b1) {
    asm volatile(
        "mma.sync.aligned.m16n8k16.row.col.f32.f16.f16.f32 "
        "{%0,%1,%2,%3}, {%4,%5,%6,%7}, {%8,%9}, {%0,%1,%2,%3};"
        : "+f"(c[0]), "+f"(c[1]), "+f"(c[2]), "+f"(c[3])
        : "r"(a[0]), "r"(a[1]), "r"(a[2]), "r"(a[3]), "r"(b0), "r"(b1));
}
__device__ __forceinline__ float fexp2(float x) {
    float r;
    asm("ex2.approx.f32 %0, %1;" : "=f"(r) : "f"(x));
    return r;
}
__device__ __forceinline__ uint32_t pack2(float x, float y) {
    __half2 h = __floats2half2_rn(x, y);
    return *(uint32_t*)&h;
}
__device__ __forceinline__ void split16(float v, __half& h, __half& l) {
    h = __float2half_rn(v);
    l = __float2half_rn(v - __half2float(h));
}

// ---------------- fp32 -> fp16 hi/lo conversion ------------------------------
__global__ __launch_bounds__(256) void convert_kernel(
    const float* __restrict__ x,  const float* __restrict__ Wq,
    const float* __restrict__ Wk, const float* __restrict__ Wv,
    const float* __restrict__ Wc)
{
    const int seg = blockIdx.y;
    const float* src; __half* hi; __half* lo; int n4;
    if (seg == 0) { src = x;  hi = g_xh; lo = g_xl; n4 = M_*E_/4; }
    else {
        src = (seg==1)?Wq:(seg==2)?Wk:(seg==3)?Wv:Wc;
        hi = g_wh + (size_t)(seg-1)*E_*E_;
        lo = g_wl + (size_t)(seg-1)*E_*E_;
        n4 = E_*E_/4;
    }
    int i = blockIdx.x * 256 + threadIdx.x;
    if (i >= n4) return;
    float4 v = ((const float4*)src)[i];
    __half h0,h1,h2,h3,l0,l1,l2,l3;
    split16(v.x,h0,l0); split16(v.y,h1,l1); split16(v.z,h2,l2); split16(v.w,h3,l3);
    ((__half2*)hi)[2*i]   = __halves2half2(h0, h1);
    ((__half2*)hi)[2*i+1] = __halves2half2(h2, h3);
    ((__half2*)lo)[2*i]   = __halves2half2(l0, l1);
    ((__half2*)lo)[2*i+1] = __halves2half2(l2, l3);
}

// ---------------- HMMA GEMM ---------------------------------------------------
// 128x128 tile, 8 warps (2x4), k-chunk 32, 4 stages (3 in flight), single
// barrier per chunk. Both modes: 3 tiles/stage, 2 MMA products per fragment.
// MODE 0 (QKV): theta = xh.Wh + xl.Wh  (weight-lo term dropped; ~2e-4 theta).
//               Epilogue: cumprod(cos) -> q (fp16 *log2e/8), k, v^T (fp16).
// MODE 1 (out): out = oh.Wh + oh.Wl + bias.
#define GT_BYTES (128*64)         // 8192 (64B rows, XOR swizzle)
#define GSTAGE   (3*GT_BYTES)     // 24576
#define GSMEM    (4*GSTAGE)       // 98304 -> 2 CTAs/SM

__device__ __forceinline__ uint32_t goff(int r, int ch) {
    return (uint32_t)(r * 64 + ((ch ^ ((r >> 1) & 3)) << 4));
}

template<int MODE>
__global__ __launch_bounds__(256, 2) void gemm_kernel(float* __restrict__ out,
                                                      const float* __restrict__ bc)
{
    extern __shared__ char sm[];
    const uint32_t s0 = smem_u32(sm);
    const int tid = threadIdx.x;
    const int lane = tid & 31, warp = tid >> 5;
    const int wm = warp >> 2, wn = warp & 3;
    const int m0 = blockIdx.y * 128, n0 = blockIdx.x * 128;

    // tile roles per stage:
    //   MODE0: t0 = xh(m0), t1 = xl(m0), t2 = Wh(n0)
    //   MODE1: t0 = oh(m0), t1 = Wh(n0), t2 = Wl(n0)
    const __half *T0, *T1, *T2;
    if (MODE == 0) {
        T0 = g_xh; T1 = g_xl;
        T2 = g_wh + (size_t)blockIdx.z * E_ * E_;
    } else {
        T0 = g_oh;
        T1 = g_wh + (size_t)3 * E_ * E_;
        T2 = g_wl + (size_t)3 * E_ * E_;
    }

    float acc[4][4][4];
#pragma unroll
    for (int a = 0; a < 4; a++)
#pragma unroll
        for (int b = 0; b < 4; b++)
#pragma unroll
            for (int c = 0; c < 4; c++) acc[a][b][c] = 0.f;

    auto load = [&](int c) {
        const uint32_t base = s0 + (c & 3) * GSTAGE;
        const int k0 = c * 32;
#pragma unroll
        for (int i = 0; i < 6; i++) {
            int g = i * 256 + tid;           // 0..1535
            int t = g >> 9;                  // 0..2 tile index
            int r = (g >> 2) & 127;
            int ch = g & 3;
            const __half* src = (t == 0) ? T0 : (t == 1) ? T1 : T2;
            int row;
            if (MODE == 0) row = ((t < 2) ? m0 : n0) + r;
            else           row = ((t == 0) ? m0 : n0) + r;
            cp16(base + t * GT_BYTES + goff(r, ch),
                 src + (size_t)row * E_ + k0 + ch * 8);
        }
    };

    load(0); CP_COMMIT();
    load(1); CP_COMMIT();
    load(2); CP_COMMIT();

    const int rowoff = (lane & 7) + ((lane >> 3) & 1) * 8;
    constexpr uint32_t BOFF = (MODE == 0) ? 2u * GT_BYTES : 1u * GT_BYTES;

    for (int c = 0; c < 32; c++) {
        CP_WAIT2();              // group c complete (2 younger may pend)
        __syncthreads();         // visible to all + stage (c-1)&3 free
        if (c + 3 < 32) load(c + 3);   // -> stage (c+3)&3 == (c-1)&3 : safe
        CP_COMMIT();
        const uint32_t base = s0 + (c & 3) * GSTAGE;
#pragma unroll
        for (int ks = 0; ks < 2; ks++) {
            const int chunk = ks * 2 + (lane >> 4);
            uint32_t ah[4][4], a2[4][4];
#pragma unroll
            for (int mi = 0; mi < 4; mi++) {
                uint32_t ra = base + goff(wm*64 + mi*16 + rowoff, chunk);
                ldsm4(ra, ah[mi]);
                if (MODE == 0) ldsm4(ra + GT_BYTES, a2[mi]);
            }
#pragma unroll
            for (int p = 0; p < 2; p++) {
                uint32_t bh[4], bl[4];
                uint32_t rb = base + BOFF + goff(wn*32 + p*16 + rowoff, chunk);
                ldsm4(rb, bh);
                if (MODE == 1) ldsm4(rb + GT_BYTES, bl);
                // pass 1: main product
#pragma unroll
                for (int mi = 0; mi < 4; mi++) mma_fp16(acc[mi][2*p],   ah[mi], bh[0], bh[2]);
#pragma unroll
                for (int mi = 0; mi < 4; mi++) mma_fp16(acc[mi][2*p+1], ah[mi], bh[1], bh[3]);
                // pass 2: correction product
                if (MODE == 0) {
#pragma unroll
                    for (int mi = 0; mi < 4; mi++) mma_fp16(acc[mi][2*p],   a2[mi], bh[0], bh[2]);
#pragma unroll
                    for (int mi = 0; mi < 4; mi++) mma_fp16(acc[mi][2*p+1], a2[mi], bh[1], bh[3]);
                } else {
#pragma unroll
                    for (int mi = 0; mi < 4; mi++) mma_fp16(acc[mi][2*p],   ah[mi], bl[0], bl[2]);
#pragma unroll
                    for (int mi = 0; mi < 4; mi++) mma_fp16(acc[mi][2*p+1], ah[mi], bl[1], bl[3]);
                }
            }
        }
    }

    const int g = lane >> 2, tg2 = (lane & 3) * 2;
    if (MODE == 1) {
#pragma unroll
        for (int mi = 0; mi < 4; mi++) {
            int m = m0 + wm*64 + mi*16 + g;
#pragma unroll
            for (int ni = 0; ni < 4; ni++) {
                int n = n0 + wn*32 + ni*8 + tg2;
                float b0 = bc[n], b1 = bc[n+1];
                *(float2*)(out + (size_t)m * E_ + n) =
                    make_float2(acc[mi][ni][0] + b0, acc[mi][ni][1] + b1);
                *(float2*)(out + (size_t)(m+8) * E_ + n) =
                    make_float2(acc[mi][ni][2] + b0, acc[mi][ni][3] + b1);
            }
        }
        return;
    }

    // ---- MODE 0: transpose via smem, then per-row cumprod(cos) ----
    __syncthreads();
    float* st = (float*)sm;      // [128][132] fp32 = 67.6KB <= 96KB
#pragma unroll
    for (int mi = 0; mi < 4; mi++) {
        int r = wm*64 + mi*16 + g;
#pragma unroll
        for (int ni = 0; ni < 4; ni++) {
            int n = wn*32 + ni*8 + tg2;
            st[(size_t)r * 132 + n]     = acc[mi][ni][0];
            st[(size_t)r * 132 + n + 1] = acc[mi][ni][1];
            st[(size_t)(r+8) * 132 + n]     = acc[mi][ni][2];
            st[(size_t)(r+8) * 132 + n + 1] = acc[mi][ni][3];
        }
    }
    __syncthreads();

    {
        const int head = tid >> 7;          // 0..1 (two heads per 128-col tile)
        const int r = tid & 127;
        const int m = m0 + r;
        const int b = m >> 11, sI = m & (S_ - 1);
        const int hglob = blockIdx.x * 2 + head;
        const int bh = b * H_ + hglob;
        const int z = blockIdx.z;
        const float* src = st + (size_t)r * 132 + head * 64;

        float run = 1.f;
        float val[64];
#pragma unroll
        for (int d = 0; d < 64; d++) { run *= __cosf(src[d]); val[d] = run; }

        if (z < 2) {
            // Q pre-scale folds softmax 1/sqrt(D) AND log2(e) for ex2-softmax
            const float sc = (z == 0) ? 0.18033688f : 1.0f;   // log2e/8
            __half hb[64];
#pragma unroll
            for (int d = 0; d < 64; d++) hb[d] = __float2half_rn(val[d] * sc);
            __half* dh = (z == 0 ? g_qh : g_kh) + ((size_t)bh * S_ + sI) * 64;
#pragma unroll
            for (int j = 0; j < 8; j++) ((uint4*)dh)[j] = ((uint4*)hb)[j];
        } else {
#pragma unroll
            for (int d = 0; d < 64; d++)
                g_vth[((size_t)bh * 64 + d) * S_ + sI] = __float2half_rn(val[d]);
        }
    }
}

// ---------------- HMMA flash attention ---------------------------------------
// grid (S/128, BH), 256 threads, 2 CTAs/SM. Plain fp16 Q/K/V (fp32 accum).
// NO online max: scores provably bounded (|q.k| <= 64) -> ex2 arg <= 11.6,
// p <= 3020 (fp16-safe), l <= 6.2e6 (fp32-safe). l reduced in epilogue.
// 4 KV stages, 3 in flight (wait_group 2), single barrier per tile.
#define FROWB 144
#define FKT  (64*FROWB)      // 9216
#define FSTAGE (2*FKT)       // 18432 : Kh, Vh
#define FSMEM (4*FSTAGE)     // 73728 -> 2 CTAs/SM

__global__ __launch_bounds__(256, 2) void flash_kernel()
{
    extern __shared__ char sm[];
    const uint32_t s0 = smem_u32(sm);
    const uint32_t sQ = s0 + 3 * FSTAGE;   // Q lives in stage 3 until t==0 ldsm
    const int tid = threadIdx.x, lane = tid & 31, warp = tid >> 5;
    const int bh = blockIdx.y;
    const int q0 = blockIdx.x * 128;

    const __half* Qh = g_qh + (size_t)bh * S_ * 64;
    const __half* Kh = g_kh + (size_t)bh * S_ * 64;
    const __half* Vh = g_vth + (size_t)bh * 64 * S_;

    auto loadKV = [&](int t) {
        const uint32_t base = s0 + (t & 3) * FSTAGE;
        const int kv0 = t * 64;
#pragma unroll
        for (int i = 0; i < 4; i++) {
            int gi = i * 256 + tid;         // 0..1023
            int tl = gi >> 9;               // 0..1 : Kh, Vh
            int r = (gi >> 3) & 63;
            int ch = gi & 7;
            const __half* src = (tl == 0)
                ? Kh + (size_t)(kv0 + r) * 64 + ch * 8
                : Vh + (size_t)r * S_ + kv0 + ch * 8;
            cp16(base + tl * FKT + r * FROWB + ch * 16, src);
        }
    };

    {
        // group 0: Q (into stage 3) + KV0; group 1: KV1; group 2: KV2
#pragma unroll
        for (int i = 0; i < 4; i++) {
            int gi = i * 256 + tid;         // 0..1023
            int r = gi >> 3;                // 0..127
            int ch = gi & 7;
            cp16(sQ + r * FROWB + ch * 16, Qh + (size_t)(q0 + r) * 64 + ch * 8);
        }
        loadKV(0); CP_COMMIT();
        loadKV(1); CP_COMMIT();
        loadKV(2); CP_COMMIT();
    }

    float o[8][4];
#pragma unroll
    for (int i = 0; i < 8; i++)
#pragma unroll
        for (int j = 0; j < 4; j++) o[i][j] = 0.f;
    float l0r = 0.f, l1r = 0.f;

    uint32_t qhf[4][4];
    const int rowoff = (lane & 7) + ((lane >> 3) & 1) * 8;

    for (int t = 0; t < 32; t++) {
        CP_WAIT2();              // groups <= t done (2 younger may pend)
        __syncthreads();
        if (t == 0) {
            // one-time Q fragment load from stage 3; must finish CTA-wide
            // before loadKV(3) overwrites it
#pragma unroll
            for (int ks = 0; ks < 4; ks++) {
                uint32_t ra = sQ + (warp*16 + rowoff) * FROWB + (ks*2 + (lane>>4)) * 16;
                ldsm4(ra, qhf[ks]);
            }
            __syncthreads();
        }
        if (t + 3 < 32) loadKV(t + 3);   // -> stage (t+3)&3 == (t-1)&3 : safe
        CP_COMMIT();

        const uint32_t kb = s0 + (t & 3) * FSTAGE;

        float s[8][4];
#pragma unroll
        for (int i = 0; i < 8; i++)
#pragma unroll
            for (int j = 0; j < 4; j++) s[i][j] = 0.f;

        // S = Q K^T (Q pre-scaled by log2e/8), interleaved over panel pairs
#pragma unroll
        for (int ks = 0; ks < 4; ks++) {
            const int chunk = ks * 2 + (lane >> 4);
#pragma unroll
            for (int pp = 0; pp < 2; pp++) {
                uint32_t kh[2][4];
#pragma unroll
                for (int q = 0; q < 2; q++)
                    ldsm4(kb + ((pp*2+q)*16 + rowoff) * FROWB + chunk * 16, kh[q]);
#pragma unroll
                for (int q = 0; q < 2; q++) mma_fp16(s[2*(pp*2+q)],   qhf[ks], kh[q][0], kh[q][2]);
#pragma unroll
                for (int q = 0; q < 2; q++) mma_fp16(s[2*(pp*2+q)+1], qhf[ks], kh[q][1], kh[q][3]);
            }
        }

        // softmax numerator: p = 2^s (bounded, no max tracking), local l accum
        uint32_t pf[8][2];
#pragma unroll
        for (int ni = 0; ni < 8; ni++) {
            float p0 = fexp2(s[ni][0]);
            float p1 = fexp2(s[ni][1]);
            float p2 = fexp2(s[ni][2]);
            float p3 = fexp2(s[ni][3]);
            l0r += p0 + p1; l1r += p2 + p3;
            pf[ni][0] = pack2(p0, p1);
            pf[ni][1] = pack2(p2, p3);
        }

        // O += P V (plain fp16 V), interleaved over panel pairs
        const uint32_t vb = kb + FKT;
#pragma unroll
        for (int ks = 0; ks < 4; ks++) {
            uint32_t a[4] = { pf[2*ks][0], pf[2*ks][1], pf[2*ks+1][0], pf[2*ks+1][1] };
            const int chunk = ks * 2 + (lane >> 4);
#pragma unroll
            for (int pp = 0; pp < 2; pp++) {
                uint32_t vh[2][4];
#pragma unroll
                for (int q = 0; q < 2; q++)
                    ldsm4(vb + ((pp*2+q)*16 + rowoff) * FROWB + chunk * 16, vh[q]);
#pragma unroll
                for (int q = 0; q < 2; q++) mma_fp16(o[2*(pp*2+q)],   a, vh[q][0], vh[q][2]);
#pragma unroll
                for (int q = 0; q < 2; q++) mma_fp16(o[2*(pp*2+q)+1], a, vh[q][1], vh[q][3]);
            }
        }
    }

    // epilogue: reduce l across the quad, normalize, write fp16 [B,S,H,D]
    l0r += __shfl_xor_sync(0xffffffffu, l0r, 1);
    l0r += __shfl_xor_sync(0xffffffffu, l0r, 2);
    l1r += __shfl_xor_sync(0xffffffffu, l1r, 1);
    l1r += __shfl_xor_sync(0xffffffffu, l1r, 2);
    const float inv0 = 1.f / l0r, inv1 = 1.f / l1r;
    const int g = lane >> 2, tg2 = (lane & 3) * 2;
    const int b = bh >> 4, h = bh & 15;
    const int sA = q0 + warp * 16 + g;
#pragma unroll
    for (int ni = 0; ni < 8; ni++) {
        int d = ni * 8 + tg2;
        size_t i0 = (((size_t)(b * S_ + sA)     * H_ + h) * D_ + d);
        size_t i1 = (((size_t)(b * S_ + sA + 8) * H_ + h) * D_ + d);
        *(__half2*)(g_oh + i0) = __floats2half2_rn(o[ni][0] * inv0, o[ni][1] * inv0);
        *(__half2*)(g_oh + i1) = __floats2half2_rn(o[ni][2] * inv1, o[ni][3] * inv1);
    }
}

// ---------------------------------------------------------------------------
extern "C" void kernel_launch(void* const* d_in, const int* in_sizes, int n_in,
                              void* d_out, int out_size)
{
    const float* x  = (const float*)d_in[0];
    const float* Wq = (const float*)d_in[1];
    const float* Wk = (const float*)d_in[2];
    const float* Wv = (const float*)d_in[3];
    const float* Wc = (const float*)d_in[4];
    const float* bc = (const float*)d_in[5];
    float* out = (float*)d_out;

    cudaFuncSetAttribute(gemm_kernel<0>, cudaFuncAttributeMaxDynamicSharedMemorySize, GSMEM);
    cudaFuncSetAttribute(gemm_kernel<1>, cudaFuncAttributeMaxDynamicSharedMemorySize, GSMEM);
    cudaFuncSetAttribute(flash_kernel,   cudaFuncAttributeMaxDynamicSharedMemorySize, FSMEM);

    // 1) fp32 -> fp16 hi/lo for x and all weights
    convert_kernel<<<dim3(4096, 5), 256>>>(x, Wq, Wk, Wv, Wc);

    // 2) QKV projections (2-product HMMA: xh.Wh + xl.Wh) + quantum epilogue
    gemm_kernel<0><<<dim3(E_/128, M_/128, 3), 256, GSMEM>>>(nullptr, nullptr);

    // 3) flash attention (fp16 Q/K/V, ex2 softmax without max-tracking)
    flash_kernel<<<dim3(S_/128, BH_), 256, FSMEM>>>();

    // 4) output projection (2-product HMMA: oh.Wh + oh.Wl) + bias
    gemm_kernel<1><<<dim3(E_/128, M_/128, 1), 256, GSMEM>>>(out, bc);
}

// round 11
// speedup vs baseline: 2.9360x; 1.3770x over previous
#include <cuda_runtime.h>
#include <cuda_fp16.h>
#include <stdint.h>
#include <math.h>

#define B_ 2
#define S_ 2048
#define E_ 1024
#define H_ 16
#define D_ 64
#define M_ (B_*S_)    // 4096
#define BH_ (B_*H_)   // 32

// ---------------- scratch (device globals; no allocation allowed) -------------
__device__ __half g_xh[(size_t)M_*E_];
__device__ __half g_wh[(size_t)4*E_*E_];
__device__ __half g_qh[(size_t)BH_*S_*D_];    // Q: fp16, pre-scaled by log2e/8
__device__ __half g_kh[(size_t)BH_*S_*D_];    // K: plain fp16
__device__ __half g_vth[(size_t)BH_*D_*S_];   // V^T: plain fp16 [bh][d][s]
__device__ __half g_oh[(size_t)M_*E_];        // attn out: plain fp16

// ---------------- helpers ----------------------------------------------------
__device__ __forceinline__ uint32_t smem_u32(const void* p) {
    uint32_t a;
    asm("{ .reg .u64 t; cvta.to.shared.u64 t, %1; cvt.u32.u64 %0, t; }" : "=r"(a) : "l"(p));
    return a;
}
__device__ __forceinline__ void cp16(uint32_t s, const void* g) {
    asm volatile("cp.async.cg.shared.global [%0], [%1], 16;" :: "r"(s), "l"(g));
}
#define CP_COMMIT() asm volatile("cp.async.commit_group;" ::: "memory")
#define CP_WAIT2()  asm volatile("cp.async.wait_group 2;" ::: "memory")

__device__ __forceinline__ void ldsm4(uint32_t addr, uint32_t r[4]) {
    asm volatile("ldmatrix.sync.aligned.m8n8.x4.shared.b16 {%0,%1,%2,%3}, [%4];"
        : "=r"(r[0]), "=r"(r[1]), "=r"(r[2]), "=r"(r[3]) : "r"(addr));
}
__device__ __forceinline__ void mma_fp16(float* c, const uint32_t* a, uint32_t b0, uint32_t b1) {
    asm volatile(
        "mma.sync.aligned.m16n8k16.row.col.f32.f16.f16.f32 "
        "{%0,%1,%2,%3}, {%4,%5,%6,%7}, {%8,%9}, {%0,%1,%2,%3};"
        : "+f"(c[0]), "+f"(c[1]), "+f"(c[2]), "+f"(c[3])
        : "r"(a[0]), "r"(a[1]), "r"(a[2]), "r"(a[3]), "r"(b0), "r"(b1));
}
__device__ __forceinline__ float fexp2(float x) {
    float r;
    asm("ex2.approx.f32 %0, %1;" : "=f"(r) : "f"(x));
    return r;
}
__device__ __forceinline__ uint32_t pack2(float x, float y) {
    __half2 h = __floats2half2_rn(x, y);
    return *(uint32_t*)&h;
}

// ---------------- fp32 -> fp16 conversion (hi only) ---------------------------
__global__ __launch_bounds__(256) void convert_kernel(
    const float* __restrict__ x,  const float* __restrict__ Wq,
    const float* __restrict__ Wk, const float* __restrict__ Wv,
    const float* __restrict__ Wc)
{
    const int seg = blockIdx.y;
    const float* src; __half* hi; int n4;
    if (seg == 0) { src = x;  hi = g_xh; n4 = M_*E_/4; }
    else {
        src = (seg==1)?Wq:(seg==2)?Wk:(seg==3)?Wv:Wc;
        hi = g_wh + (size_t)(seg-1)*E_*E_;
        n4 = E_*E_/4;
    }
    int i = blockIdx.x * 256 + threadIdx.x;
    if (i >= n4) return;
    float4 v = ((const float4*)src)[i];
    ((__half2*)hi)[2*i]   = __floats2half2_rn(v.x, v.y);
    ((__half2*)hi)[2*i+1] = __floats2half2_rn(v.z, v.w);
}

// ---------------- HMMA GEMM (pure fp16, single product) -----------------------
// 128x128 tile, 8 warps (2x4), k-chunk 32, 4 stages (3 in flight), single
// barrier per chunk. 2 tiles/stage: A(m0), B(n0).
// MODE 0 (QKV): theta = xh.Wh; epilogue cumprod(cos) -> q/k/v^T fp16.
// MODE 1 (out): out = oh.Wh + bias.
#define GT_BYTES (128*64)         // 8192 (64B rows, XOR swizzle)
#define GSTAGE   (2*GT_BYTES)     // 16384
#define GSMEM0   69632            // max(4*GSTAGE, 128*132*4 transpose buf)
#define GSMEM1   (4*GSTAGE)       // 65536

__device__ __forceinline__ uint32_t goff(int r, int ch) {
    return (uint32_t)(r * 64 + ((ch ^ ((r >> 1) & 3)) << 4));
}

template<int MODE>
__global__ __launch_bounds__(256, 2) void gemm_kernel(float* __restrict__ out,
                                                      const float* __restrict__ bc)
{
    extern __shared__ char sm[];
    const uint32_t s0 = smem_u32(sm);
    const int tid = threadIdx.x;
    const int lane = tid & 31, warp = tid >> 5;
    const int wm = warp >> 2, wn = warp & 3;
    const int m0 = blockIdx.y * 128, n0 = blockIdx.x * 128;

    const __half* TA = (MODE == 0) ? g_xh : g_oh;
    const __half* TB = g_wh + (size_t)((MODE == 0) ? blockIdx.z : 3) * E_ * E_;

    float acc[4][4][4];
#pragma unroll
    for (int a = 0; a < 4; a++)
#pragma unroll
        for (int b = 0; b < 4; b++)
#pragma unroll
            for (int c = 0; c < 4; c++) acc[a][b][c] = 0.f;

    auto load = [&](int c) {
        const uint32_t base = s0 + (c & 3) * GSTAGE;
        const int k0 = c * 32;
#pragma unroll
        for (int i = 0; i < 4; i++) {
            int g = i * 256 + tid;           // 0..1023
            int t = g >> 9;                  // 0..1 : A, B
            int r = (g >> 2) & 127;
            int ch = g & 3;
            const __half* src = t ? TB : TA;
            int row = (t ? n0 : m0) + r;
            cp16(base + t * GT_BYTES + goff(r, ch),
                 src + (size_t)row * E_ + k0 + ch * 8);
        }
    };

    load(0); CP_COMMIT();
    load(1); CP_COMMIT();
    load(2); CP_COMMIT();

    const int rowoff = (lane & 7) + ((lane >> 3) & 1) * 8;

    for (int c = 0; c < 32; c++) {
        CP_WAIT2();              // group c complete (2 younger may pend)
        __syncthreads();         // visible to all + stage (c-1)&3 free
        if (c + 3 < 32) load(c + 3);   // -> stage (c+3)&3 == (c-1)&3 : safe
        CP_COMMIT();
        const uint32_t base = s0 + (c & 3) * GSTAGE;
#pragma unroll
        for (int ks = 0; ks < 2; ks++) {
            const int chunk = ks * 2 + (lane >> 4);
            uint32_t ah[4][4];
#pragma unroll
            for (int mi = 0; mi < 4; mi++)
                ldsm4(base + goff(wm*64 + mi*16 + rowoff, chunk), ah[mi]);
#pragma unroll
            for (int p = 0; p < 2; p++) {
                uint32_t bh[4];
                ldsm4(base + GT_BYTES + goff(wn*32 + p*16 + rowoff, chunk), bh);
#pragma unroll
                for (int mi = 0; mi < 4; mi++) mma_fp16(acc[mi][2*p],   ah[mi], bh[0], bh[2]);
#pragma unroll
                for (int mi = 0; mi < 4; mi++) mma_fp16(acc[mi][2*p+1], ah[mi], bh[1], bh[3]);
            }
        }
    }

    const int g = lane >> 2, tg2 = (lane & 3) * 2;
    if (MODE == 1) {
#pragma unroll
        for (int mi = 0; mi < 4; mi++) {
            int m = m0 + wm*64 + mi*16 + g;
#pragma unroll
            for (int ni = 0; ni < 4; ni++) {
                int n = n0 + wn*32 + ni*8 + tg2;
                float b0 = bc[n], b1 = bc[n+1];
                *(float2*)(out + (size_t)m * E_ + n) =
                    make_float2(acc[mi][ni][0] + b0, acc[mi][ni][1] + b1);
                *(float2*)(out + (size_t)(m+8) * E_ + n) =
                    make_float2(acc[mi][ni][2] + b0, acc[mi][ni][3] + b1);
            }
        }
        return;
    }

    // ---- MODE 0: transpose via smem, then per-row cumprod(cos) ----
    __syncthreads();
    float* st = (float*)sm;      // [128][132] fp32 = 67.6KB <= GSMEM0
#pragma unroll
    for (int mi = 0; mi < 4; mi++) {
        int r = wm*64 + mi*16 + g;
#pragma unroll
        for (int ni = 0; ni < 4; ni++) {
            int n = wn*32 + ni*8 + tg2;
            st[(size_t)r * 132 + n]     = acc[mi][ni][0];
            st[(size_t)r * 132 + n + 1] = acc[mi][ni][1];
            st[(size_t)(r+8) * 132 + n]     = acc[mi][ni][2];
            st[(size_t)(r+8) * 132 + n + 1] = acc[mi][ni][3];
        }
    }
    __syncthreads();

    {
        const int head = tid >> 7;          // 0..1 (two heads per 128-col tile)
        const int r = tid & 127;
        const int m = m0 + r;
        const int b = m >> 11, sI = m & (S_ - 1);
        const int hglob = blockIdx.x * 2 + head;
        const int bh = b * H_ + hglob;
        const int z = blockIdx.z;
        const float* src = st + (size_t)r * 132 + head * 64;

        float run = 1.f;
        float val[64];
#pragma unroll
        for (int d = 0; d < 64; d++) { run *= __cosf(src[d]); val[d] = run; }

        if (z < 2) {
            // Q pre-scale folds softmax 1/sqrt(D) AND log2(e) for ex2-softmax
            const float sc = (z == 0) ? 0.18033688f : 1.0f;   // log2e/8
            __half hb[64];
#pragma unroll
            for (int d = 0; d < 64; d++) hb[d] = __float2half_rn(val[d] * sc);
            __half* dh = (z == 0 ? g_qh : g_kh) + ((size_t)bh * S_ + sI) * 64;
#pragma unroll
            for (int j = 0; j < 8; j++) ((uint4*)dh)[j] = ((uint4*)hb)[j];
        } else {
#pragma unroll
            for (int d = 0; d < 64; d++)
                g_vth[((size_t)bh * 64 + d) * S_ + sI] = __float2half_rn(val[d]);
        }
    }
}

// ---------------- HMMA flash attention ---------------------------------------
// grid (S/128, BH), 256 threads, 2 CTAs/SM. Plain fp16 Q/K/V (fp32 accum).
// NO online max: scores provably bounded (|q.k| <= 64) -> ex2 arg <= 11.6,
// p <= 3020 (fp16-safe), l <= 6.2e6 (fp32-safe). l reduced in epilogue.
// 4 KV stages, 3 in flight (wait_group 2), single barrier per tile.
#define FROWB 144
#define FKT  (64*FROWB)      // 9216
#define FSTAGE (2*FKT)       // 18432 : Kh, Vh
#define FSMEM (4*FSTAGE)     // 73728 -> 2 CTAs/SM

__global__ __launch_bounds__(256, 2) void flash_kernel()
{
    extern __shared__ char sm[];
    const uint32_t s0 = smem_u32(sm);
    const uint32_t sQ = s0 + 3 * FSTAGE;   // Q lives in stage 3 until t==0 ldsm
    const int tid = threadIdx.x, lane = tid & 31, warp = tid >> 5;
    const int bh = blockIdx.y;
    const int q0 = blockIdx.x * 128;

    const __half* Qh = g_qh + (size_t)bh * S_ * 64;
    const __half* Kh = g_kh + (size_t)bh * S_ * 64;
    const __half* Vh = g_vth + (size_t)bh * 64 * S_;

    auto loadKV = [&](int t) {
        const uint32_t base = s0 + (t & 3) * FSTAGE;
        const int kv0 = t * 64;
#pragma unroll
        for (int i = 0; i < 4; i++) {
            int gi = i * 256 + tid;         // 0..1023
            int tl = gi >> 9;               // 0..1 : Kh, Vh
            int r = (gi >> 3) & 63;
            int ch = gi & 7;
            const __half* src = (tl == 0)
                ? Kh + (size_t)(kv0 + r) * 64 + ch * 8
                : Vh + (size_t)r * S_ + kv0 + ch * 8;
            cp16(base + tl * FKT + r * FROWB + ch * 16, src);
        }
    };

    {
        // group 0: Q (into stage 3) + KV0; group 1: KV1; group 2: KV2
#pragma unroll
        for (int i = 0; i < 4; i++) {
            int gi = i * 256 + tid;         // 0..1023
            int r = gi >> 3;                // 0..127
            int ch = gi & 7;
            cp16(sQ + r * FROWB + ch * 16, Qh + (size_t)(q0 + r) * 64 + ch * 8);
        }
        loadKV(0); CP_COMMIT();
        loadKV(1); CP_COMMIT();
        loadKV(2); CP_COMMIT();
    }

    float o[8][4];
#pragma unroll
    for (int i = 0; i < 8; i++)
#pragma unroll
        for (int j = 0; j < 4; j++) o[i][j] = 0.f;
    float l0r = 0.f, l1r = 0.f;

    uint32_t qhf[4][4];
    const int rowoff = (lane & 7) + ((lane >> 3) & 1) * 8;

    for (int t = 0; t < 32; t++) {
        CP_WAIT2();              // groups <= t done (2 younger may pend)
        __syncthreads();
        if (t == 0) {
            // one-time Q fragment load from stage 3; must finish CTA-wide
            // before loadKV(3) overwrites it
#pragma unroll
            for (int ks = 0; ks < 4; ks++) {
                uint32_t ra = sQ + (warp*16 + rowoff) * FROWB + (ks*2 + (lane>>4)) * 16;
                ldsm4(ra, qhf[ks]);
            }
            __syncthreads();
        }
        if (t + 3 < 32) loadKV(t + 3);   // -> stage (t+3)&3 == (t-1)&3 : safe
        CP_COMMIT();

        const uint32_t kb = s0 + (t & 3) * FSTAGE;

        float s[8][4];
#pragma unroll
        for (int i = 0; i < 8; i++)
#pragma unroll
            for (int j = 0; j < 4; j++) s[i][j] = 0.f;

        // S = Q K^T (Q pre-scaled by log2e/8), interleaved over panel pairs
#pragma unroll
        for (int ks = 0; ks < 4; ks++) {
            const int chunk = ks * 2 + (lane >> 4);
#pragma unroll
            for (int pp = 0; pp < 2; pp++) {
                uint32_t kh[2][4];
#pragma unroll
                for (int q = 0; q < 2; q++)
                    ldsm4(kb + ((pp*2+q)*16 + rowoff) * FROWB + chunk * 16, kh[q]);
#pragma unroll
                for (int q = 0; q < 2; q++) mma_fp16(s[2*(pp*2+q)],   qhf[ks], kh[q][0], kh[q][2]);
#pragma unroll
                for (int q = 0; q < 2; q++) mma_fp16(s[2*(pp*2+q)+1], qhf[ks], kh[q][1], kh[q][3]);
            }
        }

        // softmax numerator: p = 2^s (bounded, no max tracking), local l accum
        uint32_t pf[8][2];
#pragma unroll
        for (int ni = 0; ni < 8; ni++) {
            float p0 = fexp2(s[ni][0]);
            float p1 = fexp2(s[ni][1]);
            float p2 = fexp2(s[ni][2]);
            float p3 = fexp2(s[ni][3]);
            l0r += p0 + p1; l1r += p2 + p3;
            pf[ni][0] = pack2(p0, p1);
            pf[ni][1] = pack2(p2, p3);
        }

        // O += P V (plain fp16 V), interleaved over panel pairs
        const uint32_t vb = kb + FKT;
#pragma unroll
        for (int ks = 0; ks < 4; ks++) {
            uint32_t a[4] = { pf[2*ks][0], pf[2*ks][1], pf[2*ks+1][0], pf[2*ks+1][1] };
            const int chunk = ks * 2 + (lane >> 4);
#pragma unroll
            for (int pp = 0; pp < 2; pp++) {
                uint32_t vh[2][4];
#pragma unroll
                for (int q = 0; q < 2; q++)
                    ldsm4(vb + ((pp*2+q)*16 + rowoff) * FROWB + chunk * 16, vh[q]);
#pragma unroll
                for (int q = 0; q < 2; q++) mma_fp16(o[2*(pp*2+q)],   a, vh[q][0], vh[q][2]);
#pragma unroll
                for (int q = 0; q < 2; q++) mma_fp16(o[2*(pp*2+q)+1], a, vh[q][1], vh[q][3]);
            }
        }
    }

    // epilogue: reduce l across the quad, normalize, write fp16 [B,S,H,D]
    l0r += __shfl_xor_sync(0xffffffffu, l0r, 1);
    l0r += __shfl_xor_sync(0xffffffffu, l0r, 2);
    l1r += __shfl_xor_sync(0xffffffffu, l1r, 1);
    l1r += __shfl_xor_sync(0xffffffffu, l1r, 2);
    const float inv0 = 1.f / l0r, inv1 = 1.f / l1r;
    const int g = lane >> 2, tg2 = (lane & 3) * 2;
    const int b = bh >> 4, h = bh & 15;
    const int sA = q0 + warp * 16 + g;
#pragma unroll
    for (int ni = 0; ni < 8; ni++) {
        int d = ni * 8 + tg2;
        size_t i0 = (((size_t)(b * S_ + sA)     * H_ + h) * D_ + d);
        size_t i1 = (((size_t)(b * S_ + sA + 8) * H_ + h) * D_ + d);
        *(__half2*)(g_oh + i0) = __floats2half2_rn(o[ni][0] * inv0, o[ni][1] * inv0);
        *(__half2*)(g_oh + i1) = __floats2half2_rn(o[ni][2] * inv1, o[ni][3] * inv1);
    }
}

// ---------------------------------------------------------------------------
extern "C" void kernel_launch(void* const* d_in, const int* in_sizes, int n_in,
                              void* d_out, int out_size)
{
    const float* x  = (const float*)d_in[0];
    const float* Wq = (const float*)d_in[1];
    const float* Wk = (const float*)d_in[2];
    const float* Wv = (const float*)d_in[3];
    const float* Wc = (const float*)d_in[4];
    const float* bc = (const float*)d_in[5];
    float* out = (float*)d_out;

    cudaFuncSetAttribute(gemm_kernel<0>, cudaFuncAttributeMaxDynamicSharedMemorySize, GSMEM0);
    cudaFuncSetAttribute(gemm_kernel<1>, cudaFuncAttributeMaxDynamicSharedMemorySize, GSMEM1);
    cudaFuncSetAttribute(flash_kernel,   cudaFuncAttributeMaxDynamicSharedMemorySize, FSMEM);

    // 1) fp32 -> fp16 for x and all weights
    convert_kernel<<<dim3(4096, 5), 256>>>(x, Wq, Wk, Wv, Wc);

    // 2) QKV projections (pure fp16 HMMA) + quantum cumprod(cos) epilogue
    gemm_kernel<0><<<dim3(E_/128, M_/128, 3), 256, GSMEM0>>>(nullptr, nullptr);

    // 3) flash attention (fp16 Q/K/V, ex2 softmax without max-tracking)
    flash_kernel<<<dim3(S_/128, BH_), 256, FSMEM>>>();

    // 4) output projection (pure fp16 HMMA) + bias
    gemm_kernel<1><<<dim3(E_/128, M_/128, 1), 256, GSMEM1>>>(out, bc);
}

// round 12
// speedup vs baseline: 3.0677x; 1.0449x over previous
#include <cuda_runtime.h>
#include <cuda_fp16.h>
#include <stdint.h>
#include <math.h>

#define B_ 2
#define S_ 2048
#define E_ 1024
#define H_ 16
#define D_ 64
#define M_ (B_*S_)    // 4096
#define BH_ (B_*H_)   // 32

// ---------------- scratch (device globals; no allocation allowed) -------------
__device__ __half g_xh[(size_t)M_*E_];
__device__ __half g_wh[(size_t)4*E_*E_];
__device__ __half g_qh[(size_t)BH_*S_*D_];    // Q: fp16, pre-scaled by log2e/8
__device__ __half g_kh[(size_t)BH_*S_*D_];    // K: plain fp16
__device__ __half g_vth[(size_t)BH_*D_*S_];   // V^T: plain fp16 [bh][d][s]
__device__ __half g_oh[(size_t)M_*E_];        // attn out: plain fp16

// ---------------- helpers ----------------------------------------------------
__device__ __forceinline__ uint32_t smem_u32(const void* p) {
    uint32_t a;
    asm("{ .reg .u64 t; cvta.to.shared.u64 t, %1; cvt.u32.u64 %0, t; }" : "=r"(a) : "l"(p));
    return a;
}
__device__ __forceinline__ void cp16(uint32_t s, const void* g) {
    asm volatile("cp.async.cg.shared.global [%0], [%1], 16;" :: "r"(s), "l"(g));
}
#define CP_COMMIT() asm volatile("cp.async.commit_group;" ::: "memory")
#define CP_WAIT1()  asm volatile("cp.async.wait_group 1;" ::: "memory")

__device__ __forceinline__ void ldsm4(uint32_t addr, uint32_t r[4]) {
    asm volatile("ldmatrix.sync.aligned.m8n8.x4.shared.b16 {%0,%1,%2,%3}, [%4];"
        : "=r"(r[0]), "=r"(r[1]), "=r"(r[2]), "=r"(r[3]) : "r"(addr));
}
__device__ __forceinline__ void mma_fp16(float* c, const uint32_t* a, uint32_t b0, uint32_t b1) {
    asm volatile(
        "mma.sync.aligned.m16n8k16.row.col.f32.f16.f16.f32 "
        "{%0,%1,%2,%3}, {%4,%5,%6,%7}, {%8,%9}, {%0,%1,%2,%3};"
        : "+f"(c[0]), "+f"(c[1]), "+f"(c[2]), "+f"(c[3])
        : "r"(a[0]), "r"(a[1]), "r"(a[2]), "r"(a[3]), "r"(b0), "r"(b1));
}
__device__ __forceinline__ float fexp2(float x) {
    float r;
    asm("ex2.approx.f32 %0, %1;" : "=f"(r) : "f"(x));
    return r;
}
__device__ __forceinline__ uint32_t pack2(float x, float y) {
    __half2 h = __floats2half2_rn(x, y);
    return *(uint32_t*)&h;
}

// ---------------- fp32 -> fp16 conversion ------------------------------------
__global__ __launch_bounds__(256) void convert_kernel(
    const float* __restrict__ x,  const float* __restrict__ Wq,
    const float* __restrict__ Wk, const float* __restrict__ Wv,
    const float* __restrict__ Wc)
{
    const int seg = blockIdx.y;
    const float* src; __half* hi; int n4;
    if (seg == 0) { src = x;  hi = g_xh; n4 = M_*E_/4; }
    else {
        src = (seg==1)?Wq:(seg==2)?Wk:(seg==3)?Wv:Wc;
        hi = g_wh + (size_t)(seg-1)*E_*E_;
        n4 = E_*E_/4;
    }
    int i = blockIdx.x * 256 + threadIdx.x;
    if (i >= n4) return;
    float4 v = ((const float4*)src)[i];
    ((__half2*)hi)[2*i]   = __floats2half2_rn(v.x, v.y);
    ((__half2*)hi)[2*i+1] = __floats2half2_rn(v.z, v.w);
}

// ---------------- HMMA GEMM (pure fp16, k-chunk 64) ---------------------------
// 128x128 tile, 8 warps (2x4), k-chunk 64, 3 stages (2 in flight), single
// barrier per chunk (16 barriers). Warps walk the 4 k16 steps in rotated
// order (ks = (i+warp)&3) so ldsm and mma phases of different warps overlap.
// MODE 0 (QKV): theta = xh.Wh; epilogue cumprod(cos) -> q/k/v^T fp16.
// MODE 1 (out): out = oh.Wh + bias.
#define GT_BYTES (128*128)        // 16384 (128B rows, XOR swizzle)
#define GSTAGE   (2*GT_BYTES)     // 32768
#define GSMEM    (3*GSTAGE)       // 98304 -> 2 CTAs/SM

__device__ __forceinline__ uint32_t goff64(int r, int ch) {
    return (uint32_t)(r * 128 + ((ch ^ (r & 7)) << 4));
}

template<int MODE>
__global__ __launch_bounds__(256, 2) void gemm_kernel(float* __restrict__ out,
                                                      const float* __restrict__ bc)
{
    extern __shared__ char sm[];
    const uint32_t s0 = smem_u32(sm);
    const int tid = threadIdx.x;
    const int lane = tid & 31, warp = tid >> 5;
    const int wm = warp >> 2, wn = warp & 3;
    const int m0 = blockIdx.y * 128, n0 = blockIdx.x * 128;

    const __half* TA = (MODE == 0) ? g_xh : g_oh;
    const __half* TB = g_wh + (size_t)((MODE == 0) ? blockIdx.z : 3) * E_ * E_;

    float acc[4][4][4];
#pragma unroll
    for (int a = 0; a < 4; a++)
#pragma unroll
        for (int b = 0; b < 4; b++)
#pragma unroll
            for (int c = 0; c < 4; c++) acc[a][b][c] = 0.f;

    auto load = [&](int c) {
        const uint32_t base = s0 + (c % 3) * GSTAGE;
        const int k0 = c * 64;
#pragma unroll
        for (int i = 0; i < 8; i++) {
            int g = i * 256 + tid;           // 0..2047
            int t = g >> 10;                 // 0..1 : A, B
            int r = (g >> 3) & 127;
            int ch = g & 7;
            const __half* src = t ? TB : TA;
            int row = (t ? n0 : m0) + r;
            cp16(base + t * GT_BYTES + goff64(r, ch),
                 src + (size_t)row * E_ + k0 + ch * 8);
        }
    };

    load(0); CP_COMMIT();
    load(1); CP_COMMIT();

    const int rowoff = (lane & 7) + ((lane >> 3) & 1) * 8;

    for (int c = 0; c < 16; c++) {
        CP_WAIT1();              // group c complete (c+1 may pend)
        __syncthreads();         // copies visible + stage (c-1)%3 free
        if (c + 2 < 16) load(c + 2);   // -> stage (c+2)%3 == (c-1)%3 : safe
        CP_COMMIT();
        const uint32_t base = s0 + (c % 3) * GSTAGE;
#pragma unroll
        for (int i = 0; i < 4; i++) {
            const int ks = (i + warp) & 3;          // per-warp rotation
            const int chunk = ks * 2 + (lane >> 4);
            uint32_t ah[4][4];
#pragma unroll
            for (int mi = 0; mi < 4; mi++)
                ldsm4(base + goff64(wm*64 + mi*16 + rowoff, chunk), ah[mi]);
#pragma unroll
            for (int p = 0; p < 2; p++) {
                uint32_t bh[4];
                ldsm4(base + GT_BYTES + goff64(wn*32 + p*16 + rowoff, chunk), bh);
#pragma unroll
                for (int mi = 0; mi < 4; mi++) mma_fp16(acc[mi][2*p],   ah[mi], bh[0], bh[2]);
#pragma unroll
                for (int mi = 0; mi < 4; mi++) mma_fp16(acc[mi][2*p+1], ah[mi], bh[1], bh[3]);
            }
        }
    }

    const int g = lane >> 2, tg2 = (lane & 3) * 2;
    if (MODE == 1) {
#pragma unroll
        for (int mi = 0; mi < 4; mi++) {
            int m = m0 + wm*64 + mi*16 + g;
#pragma unroll
            for (int ni = 0; ni < 4; ni++) {
                int n = n0 + wn*32 + ni*8 + tg2;
                float b0 = bc[n], b1 = bc[n+1];
                *(float2*)(out + (size_t)m * E_ + n) =
                    make_float2(acc[mi][ni][0] + b0, acc[mi][ni][1] + b1);
                *(float2*)(out + (size_t)(m+8) * E_ + n) =
                    make_float2(acc[mi][ni][2] + b0, acc[mi][ni][3] + b1);
            }
        }
        return;
    }

    // ---- MODE 0: transpose via smem, then per-row cumprod(cos) ----
    __syncthreads();
    float* st = (float*)sm;      // [128][132] fp32 = 67.6KB <= 96KB
#pragma unroll
    for (int mi = 0; mi < 4; mi++) {
        int r = wm*64 + mi*16 + g;
#pragma unroll
        for (int ni = 0; ni < 4; ni++) {
            int n = wn*32 + ni*8 + tg2;
            st[(size_t)r * 132 + n]     = acc[mi][ni][0];
            st[(size_t)r * 132 + n + 1] = acc[mi][ni][1];
            st[(size_t)(r+8) * 132 + n]     = acc[mi][ni][2];
            st[(size_t)(r+8) * 132 + n + 1] = acc[mi][ni][3];
        }
    }
    __syncthreads();

    {
        const int head = tid >> 7;          // 0..1 (two heads per 128-col tile)
        const int r = tid & 127;
        const int m = m0 + r;
        const int b = m >> 11, sI = m & (S_ - 1);
        const int hglob = blockIdx.x * 2 + head;
        const int bh = b * H_ + hglob;
        const int z = blockIdx.z;
        const float* src = st + (size_t)r * 132 + head * 64;

        float run = 1.f;
        float val[64];
#pragma unroll
        for (int d = 0; d < 64; d++) { run *= __cosf(src[d]); val[d] = run; }

        if (z < 2) {
            // Q pre-scale folds softmax 1/sqrt(D) AND log2(e) for ex2-softmax
            const float sc = (z == 0) ? 0.18033688f : 1.0f;   // log2e/8
            __half hb[64];
#pragma unroll
            for (int d = 0; d < 64; d++) hb[d] = __float2half_rn(val[d] * sc);
            __half* dh = (z == 0 ? g_qh : g_kh) + ((size_t)bh * S_ + sI) * 64;
#pragma unroll
            for (int j = 0; j < 8; j++) ((uint4*)dh)[j] = ((uint4*)hb)[j];
        } else {
#pragma unroll
            for (int d = 0; d < 64; d++)
                g_vth[((size_t)bh * 64 + d) * S_ + sI] = __float2half_rn(val[d]);
        }
    }
}

// ---------------- HMMA flash attention ---------------------------------------
// grid (S/128, BH), 256 threads, 2 CTAs/SM. Plain fp16 Q/K/V (fp32 accum).
// NO online max (scores provably bounded: |q.k| <= 64 -> ex2 arg <= 11.6).
// Super-tiles of 128 keys = two 64-key sub-tiles per barrier; 3-super ring
// (110.6KB), 2 supers in flight. 16 barriers total.
#define FROWB 144
#define FKT  (64*FROWB)      // 9216
#define FSTAGE (2*FKT)       // 18432 : Kh, Vh (one 64-key sub-tile)
#define FSUPER (2*FSTAGE)    // 36864 (128-key super-tile)
#define FSMEM  (3*FSUPER)    // 110592 -> 2 CTAs/SM

__global__ __launch_bounds__(256, 2) void flash_kernel()
{
    extern __shared__ char sm[];
    const uint32_t s0 = smem_u32(sm);
    const uint32_t sQ = s0 + 2 * FSUPER;   // Q parked in super 2 until t==0 ldsm
    const int tid = threadIdx.x, lane = tid & 31, warp = tid >> 5;
    const int bh = blockIdx.y;
    const int q0 = blockIdx.x * 128;

    const __half* Qh = g_qh + (size_t)bh * S_ * 64;
    const __half* Kh = g_kh + (size_t)bh * S_ * 64;
    const __half* Vh = g_vth + (size_t)bh * 64 * S_;

    auto loadKV = [&](int t) {   // t = 64-key tile index (0..31)
        const uint32_t base = s0 + ((t >> 1) % 3) * FSUPER + (t & 1) * FSTAGE;
        const int kv0 = t * 64;
#pragma unroll
        for (int i = 0; i < 4; i++) {
            int gi = i * 256 + tid;         // 0..1023
            int tl = gi >> 9;               // 0..1 : Kh, Vh
            int r = (gi >> 3) & 63;
            int ch = gi & 7;
            const __half* src = (tl == 0)
                ? Kh + (size_t)(kv0 + r) * 64 + ch * 8
                : Vh + (size_t)r * S_ + kv0 + ch * 8;
            cp16(base + tl * FKT + r * FROWB + ch * 16, src);
        }
    };

    {
        // group 0: Q (into super 2) + super 0; group 1: super 1
#pragma unroll
        for (int i = 0; i < 4; i++) {
            int gi = i * 256 + tid;         // 0..1023
            int r = gi >> 3;                // 0..127
            int ch = gi & 7;
            cp16(sQ + r * FROWB + ch * 16, Qh + (size_t)(q0 + r) * 64 + ch * 8);
        }
        loadKV(0); loadKV(1); CP_COMMIT();
        loadKV(2); loadKV(3); CP_COMMIT();
    }

    float o[8][4];
#pragma unroll
    for (int i = 0; i < 8; i++)
#pragma unroll
        for (int j = 0; j < 4; j++) o[i][j] = 0.f;
    float l0r = 0.f, l1r = 0.f;

    uint32_t qhf[4][4];
    const int rowoff = (lane & 7) + ((lane >> 3) & 1) * 8;

    for (int u = 0; u < 16; u++) {           // super-tile loop (128 keys each)
        CP_WAIT1();              // super u complete (u+1 may pend)
        __syncthreads();
        if (u == 0) {
            // one-time Q fragment load from super 2; must finish CTA-wide
            // before the super-2 prefetch below overwrites it
#pragma unroll
            for (int ks = 0; ks < 4; ks++) {
                uint32_t ra = sQ + (warp*16 + rowoff) * FROWB + (ks*2 + (lane>>4)) * 16;
                ldsm4(ra, qhf[ks]);
            }
            __syncthreads();
        }
        if (u + 2 < 16) { loadKV(2*u + 4); loadKV(2*u + 5); }  // super (u+2)%3
        CP_COMMIT();

#pragma unroll
        for (int tt = 0; tt < 2; tt++) {     // two 64-key sub-tiles
            const uint32_t kb = s0 + (u % 3) * FSUPER + tt * FSTAGE;

            float s[8][4];
#pragma unroll
            for (int i = 0; i < 8; i++)
#pragma unroll
                for (int j = 0; j < 4; j++) s[i][j] = 0.f;

            // S = Q K^T (Q pre-scaled by log2e/8)
#pragma unroll
            for (int ks = 0; ks < 4; ks++) {
                const int chunk = ks * 2 + (lane >> 4);
#pragma unroll
                for (int pp = 0; pp < 2; pp++) {
                    uint32_t kh[2][4];
#pragma unroll
                    for (int q = 0; q < 2; q++)
                        ldsm4(kb + ((pp*2+q)*16 + rowoff) * FROWB + chunk * 16, kh[q]);
#pragma unroll
                    for (int q = 0; q < 2; q++) mma_fp16(s[2*(pp*2+q)],   qhf[ks], kh[q][0], kh[q][2]);
#pragma unroll
                    for (int q = 0; q < 2; q++) mma_fp16(s[2*(pp*2+q)+1], qhf[ks], kh[q][1], kh[q][3]);
                }
            }

            // softmax numerator: p = 2^s (bounded), local l accumulate
            uint32_t pf[8][2];
#pragma unroll
            for (int ni = 0; ni < 8; ni++) {
                float p0 = fexp2(s[ni][0]);
                float p1 = fexp2(s[ni][1]);
                float p2 = fexp2(s[ni][2]);
                float p3 = fexp2(s[ni][3]);
                l0r += p0 + p1; l1r += p2 + p3;
                pf[ni][0] = pack2(p0, p1);
                pf[ni][1] = pack2(p2, p3);
            }

            // O += P V
            const uint32_t vb = kb + FKT;
#pragma unroll
            for (int ks = 0; ks < 4; ks++) {
                uint32_t a[4] = { pf[2*ks][0], pf[2*ks][1], pf[2*ks+1][0], pf[2*ks+1][1] };
                const int chunk = ks * 2 + (lane >> 4);
#pragma unroll
                for (int pp = 0; pp < 2; pp++) {
                    uint32_t vh[2][4];
#pragma unroll
                    for (int q = 0; q < 2; q++)
                        ldsm4(vb + ((pp*2+q)*16 + rowoff) * FROWB + chunk * 16, vh[q]);
#pragma unroll
                    for (int q = 0; q < 2; q++) mma_fp16(o[2*(pp*2+q)],   a, vh[q][0], vh[q][2]);
#pragma unroll
                    for (int q = 0; q < 2; q++) mma_fp16(o[2*(pp*2+q)+1], a, vh[q][1], vh[q][3]);
                }
            }
        }
    }

    // epilogue: reduce l across the quad, normalize, write fp16 [B,S,H,D]
    l0r += __shfl_xor_sync(0xffffffffu, l0r, 1);
    l0r += __shfl_xor_sync(0xffffffffu, l0r, 2);
    l1r += __shfl_xor_sync(0xffffffffu, l1r, 1);
    l1r += __shfl_xor_sync(0xffffffffu, l1r, 2);
    const float inv0 = 1.f / l0r, inv1 = 1.f / l1r;
    const int g = lane >> 2, tg2 = (lane & 3) * 2;
    const int b = bh >> 4, h = bh & 15;
    const int sA = q0 + warp * 16 + g;
#pragma unroll
    for (int ni = 0; ni < 8; ni++) {
        int d = ni * 8 + tg2;
        size_t i0 = (((size_t)(b * S_ + sA)     * H_ + h) * D_ + d);
        size_t i1 = (((size_t)(b * S_ + sA + 8) * H_ + h) * D_ + d);
        *(__half2*)(g_oh + i0) = __floats2half2_rn(o[ni][0] * inv0, o[ni][1] * inv0);
        *(__half2*)(g_oh + i1) = __floats2half2_rn(o[ni][2] * inv1, o[ni][3] * inv1);
    }
}

// ---------------------------------------------------------------------------
extern "C" void kernel_launch(void* const* d_in, const int* in_sizes, int n_in,
                              void* d_out, int out_size)
{
    const float* x  = (const float*)d_in[0];
    const float* Wq = (const float*)d_in[1];
    const float* Wk = (const float*)d_in[2];
    const float* Wv = (const float*)d_in[3];
    const float* Wc = (const float*)d_in[4];
    const float* bc = (const float*)d_in[5];
    float* out = (float*)d_out;

    cudaFuncSetAttribute(gemm_kernel<0>, cudaFuncAttributeMaxDynamicSharedMemorySize, GSMEM);
    cudaFuncSetAttribute(gemm_kernel<1>, cudaFuncAttributeMaxDynamicSharedMemorySize, GSMEM);
    cudaFuncSetAttribute(flash_kernel,   cudaFuncAttributeMaxDynamicSharedMemorySize, FSMEM);

    // 1) fp32 -> fp16 for x and all weights
    convert_kernel<<<dim3(4096, 5), 256>>>(x, Wq, Wk, Wv, Wc);

    // 2) QKV projections (pure fp16 HMMA) + quantum cumprod(cos) epilogue
    gemm_kernel<0><<<dim3(E_/128, M_/128, 3), 256, GSMEM>>>(nullptr, nullptr);

    // 3) flash attention (fp16 Q/K/V, ex2 softmax, 128-key super-tiles)
    flash_kernel<<<dim3(S_/128, BH_), 256, FSMEM>>>();

    // 4) output projection (pure fp16 HMMA) + bias
    gemm_kernel<1><<<dim3(E_/128, M_/128, 1), 256, GSMEM>>>(out, bc);
}